// round 2
// baseline (speedup 1.0000x reference)
#include <cuda_runtime.h>
#include <cuda_bf16.h>
#include <math.h>

#define BATCH  4
#define NQ     1024
#define NKV    2048
#define DMODEL 1024
#define HEADS  16
#define DH     64
#define INNER  1024

// ---------------- scratch (no allocation allowed) ----------------
__device__ float g_xn [BATCH * NQ  * DMODEL];
__device__ float g_q  [BATCH * NQ  * INNER];
__device__ float g_k  [BATCH * NKV * INNER];
__device__ float g_v  [BATCH * NKV * INNER];
__device__ float g_ctx[BATCH * NQ  * INNER];

// ---------------- LayerNorm: one block per row ----------------
__global__ void ln_kernel(const float* __restrict__ x,
                          const float* __restrict__ gamma,
                          const float* __restrict__ beta,
                          float* __restrict__ y) {
    __shared__ float red[16];
    int row = blockIdx.x;
    int tid = threadIdx.x;  // 256 threads, 1024 cols -> 1 float4 each
    const float4* xr = (const float4*)(x + (size_t)row * DMODEL);
    float4 a = xr[tid];
    float s = a.x + a.y + a.z + a.w;
    float q = a.x * a.x + a.y * a.y + a.z * a.z + a.w * a.w;
#pragma unroll
    for (int off = 16; off; off >>= 1) {
        s += __shfl_xor_sync(0xffffffffu, s, off);
        q += __shfl_xor_sync(0xffffffffu, q, off);
    }
    if ((tid & 31) == 0) { red[tid >> 5] = s; red[8 + (tid >> 5)] = q; }
    __syncthreads();
    if (tid < 32) {
        float ss = (tid < 8) ? red[tid] : 0.f;
        float qq = (tid < 8) ? red[8 + tid] : 0.f;
#pragma unroll
        for (int off = 4; off; off >>= 1) {
            ss += __shfl_xor_sync(0xffffffffu, ss, off);
            qq += __shfl_xor_sync(0xffffffffu, qq, off);
        }
        if (tid == 0) { red[0] = ss; red[1] = qq; }
    }
    __syncthreads();
    float mu  = red[0] * (1.f / DMODEL);
    float var = red[1] * (1.f / DMODEL) - mu * mu;
    float inv = rsqrtf(var + 1e-5f);
    float4 g = ((const float4*)gamma)[tid];
    float4 b = ((const float4*)beta)[tid];
    float4 o;
    o.x = (a.x - mu) * inv * g.x + b.x;
    o.y = (a.y - mu) * inv * g.y + b.y;
    o.z = (a.z - mu) * inv * g.z + b.z;
    o.w = (a.w - mu) * inv * g.w + b.w;
    ((float4*)(y + (size_t)row * DMODEL))[tid] = o;
}

// ---------------- SGEMM: C[M,N] = A[M,K] * W[K,N], 64x64x16 tiles ----------------
__global__ void sgemm_kernel(const float* __restrict__ A,
                             const float* __restrict__ W,
                             float* __restrict__ C,
                             int M, int N, int K) {
    __shared__ float As[16][68];   // As[k][m], pad 68 (272B rows, 16B aligned)
    __shared__ float Ws[16][64];   // Ws[k][n]
    int tid = threadIdx.x;         // 256
    int tx = tid & 15, ty = tid >> 4;

    int arow = tid >> 2, akc = (tid & 3) * 4;       // A tile: 64 rows x 16 k (float4 along k)
    int wrow = tid >> 4, wc  = (tid & 15) * 4;      // W tile: 16 rows x 64 n
    const float* Ap = A + (size_t)(blockIdx.y * 64 + arow) * K + akc;
    const float* Wp = W + (size_t)wrow * N + blockIdx.x * 64 + wc;

    float acc[4][4] = {};

    for (int k0 = 0; k0 < K; k0 += 16) {
        float4 av = *(const float4*)(Ap + k0);
        float4 wv = *(const float4*)(Wp + (size_t)k0 * N);
        As[akc + 0][arow] = av.x;
        As[akc + 1][arow] = av.y;
        As[akc + 2][arow] = av.z;
        As[akc + 3][arow] = av.w;
        *(float4*)&Ws[wrow][wc] = wv;
        __syncthreads();
#pragma unroll
        for (int kk = 0; kk < 16; kk++) {
            float4 a = *(const float4*)&As[kk][ty * 4];
            float4 b = *(const float4*)&Ws[kk][tx * 4];
            acc[0][0] += a.x * b.x; acc[0][1] += a.x * b.y; acc[0][2] += a.x * b.z; acc[0][3] += a.x * b.w;
            acc[1][0] += a.y * b.x; acc[1][1] += a.y * b.y; acc[1][2] += a.y * b.z; acc[1][3] += a.y * b.w;
            acc[2][0] += a.z * b.x; acc[2][1] += a.z * b.y; acc[2][2] += a.z * b.z; acc[2][3] += a.z * b.w;
            acc[3][0] += a.w * b.x; acc[3][1] += a.w * b.y; acc[3][2] += a.w * b.z; acc[3][3] += a.w * b.w;
        }
        __syncthreads();
    }

    int crow = blockIdx.y * 64 + ty * 4;
    int ccol = blockIdx.x * 64 + tx * 4;
#pragma unroll
    for (int i = 0; i < 4; i++) {
        float4 o = make_float4(acc[i][0], acc[i][1], acc[i][2], acc[i][3]);
        *(float4*)(C + (size_t)(crow + i) * N + ccol) = o;
    }
}

// ---------------- Flash attention: 64x64 tiles per (qtile, h, b) ----------------
#define PADA 68
__global__ void attn_kernel(const float* __restrict__ Q,
                            const float* __restrict__ K,
                            const float* __restrict__ V,
                            const int* __restrict__ mask,   // int32: nonzero => masked out
                            float* __restrict__ ctx) {
    extern __shared__ float sm[];
    float* Qt = sm;                          // [64 d][PADA] Qt[d][m]
    float* Kt = Qt + 64 * PADA;              // [64 d][PADA] Kt[d][n]
    float* Pt = Kt + 64 * PADA;              // [64 kv][PADA] Pt[kv][m]
    float* Vs = Pt + 64 * PADA;              // [64 kv][64 d]
    unsigned char* Ms = (unsigned char*)(Vs + 64 * 64);  // [64 q][64 kv]

    int tid = threadIdx.x;                   // 256
    int tx = tid & 15, ty = tid >> 4;
    int b = blockIdx.z, h = blockIdx.y, qt = blockIdx.x;

    const float* Qb = Q + ((size_t)b * NQ + qt * 64) * INNER + h * DH;
    const float* Kb = K + (size_t)b * NKV * INNER + h * DH;
    const float* Vb = V + (size_t)b * NKV * INNER + h * DH;
    const int* Mb = mask + ((size_t)b * NQ + qt * 64) * NKV;

    // load Q tile transposed (once)
    {
        int r = tid >> 2, cb = tid & 3;
        const float* src = Qb + (size_t)r * INNER;
#pragma unroll
        for (int it = 0; it < 4; it++) {
            int c = (cb + it * 4) * 4;
            float4 v = *(const float4*)(src + c);
            Qt[(c + 0) * PADA + r] = v.x;
            Qt[(c + 1) * PADA + r] = v.y;
            Qt[(c + 2) * PADA + r] = v.z;
            Qt[(c + 3) * PADA + r] = v.w;
        }
    }

    float o[4][4] = {};
    float m[4], l[4];
#pragma unroll
    for (int i = 0; i < 4; i++) { m[i] = -3.402823466e38f; l[i] = 0.f; }

    const float scl = 0.125f;  // 1/sqrt(64)

    for (int t = 0; t < NKV / 64; t++) {
        __syncthreads();  // prior O-phase done before overwriting Kt/Vs
        {
            int r = tid >> 2, cb = tid & 3;
            const float* ksrc = Kb + (size_t)(t * 64 + r) * INNER;
            const float* vsrc = Vb + (size_t)(t * 64 + r) * INNER;
            const int* msrc = Mb + (size_t)r * NKV + t * 64;
#pragma unroll
            for (int it = 0; it < 4; it++) {
                int c = (cb + it * 4) * 4;
                float4 kv = *(const float4*)(ksrc + c);
                Kt[(c + 0) * PADA + r] = kv.x;
                Kt[(c + 1) * PADA + r] = kv.y;
                Kt[(c + 2) * PADA + r] = kv.z;
                Kt[(c + 3) * PADA + r] = kv.w;
                *(float4*)&Vs[r * 64 + c] = *(const float4*)(vsrc + c);
                int4 mi = *(const int4*)(msrc + c);
                Ms[r * 64 + c + 0] = (unsigned char)(mi.x != 0);
                Ms[r * 64 + c + 1] = (unsigned char)(mi.y != 0);
                Ms[r * 64 + c + 2] = (unsigned char)(mi.z != 0);
                Ms[r * 64 + c + 3] = (unsigned char)(mi.w != 0);
            }
        }
        __syncthreads();

        // S = Q K^T (64-deep dot, 4x4 register tile)
        float s[4][4] = {};
#pragma unroll 16
        for (int kk = 0; kk < 64; kk++) {
            float4 a = *(const float4*)&Qt[kk * PADA + ty * 4];
            float4 bb = *(const float4*)&Kt[kk * PADA + tx * 4];
            s[0][0] += a.x * bb.x; s[0][1] += a.x * bb.y; s[0][2] += a.x * bb.z; s[0][3] += a.x * bb.w;
            s[1][0] += a.y * bb.x; s[1][1] += a.y * bb.y; s[1][2] += a.y * bb.z; s[1][3] += a.y * bb.w;
            s[2][0] += a.z * bb.x; s[2][1] += a.z * bb.y; s[2][2] += a.z * bb.z; s[2][3] += a.z * bb.w;
            s[3][0] += a.w * bb.x; s[3][1] += a.w * bb.y; s[3][2] += a.w * bb.z; s[3][3] += a.w * bb.w;
        }

        // scale + mask + online softmax update
#pragma unroll
        for (int i = 0; i < 4; i++) {
#pragma unroll
            for (int j = 0; j < 4; j++) {
                float sv = s[i][j] * scl;
                if (Ms[(ty * 4 + i) * 64 + tx * 4 + j]) sv = -3.402823466e38f;
                s[i][j] = sv;
            }
            float r0 = fmaxf(fmaxf(s[i][0], s[i][1]), fmaxf(s[i][2], s[i][3]));
#pragma unroll
            for (int off = 8; off; off >>= 1)
                r0 = fmaxf(r0, __shfl_xor_sync(0xffffffffu, r0, off));
            float mn = fmaxf(m[i], r0);
            float corr = __expf(m[i] - mn);
            m[i] = mn;
            float ls = 0.f;
#pragma unroll
            for (int j = 0; j < 4; j++) {
                float p = __expf(s[i][j] - mn);
                s[i][j] = p;
                ls += p;
            }
#pragma unroll
            for (int off = 8; off; off >>= 1)
                ls += __shfl_xor_sync(0xffffffffu, ls, off);
            l[i] = l[i] * corr + ls;
            o[i][0] *= corr; o[i][1] *= corr; o[i][2] *= corr; o[i][3] *= corr;
        }

        // store P transposed: Pt[kv][qrow]
#pragma unroll
        for (int i = 0; i < 4; i++)
#pragma unroll
            for (int j = 0; j < 4; j++)
                Pt[(tx * 4 + j) * PADA + ty * 4 + i] = s[i][j];
        __syncthreads();

        // O += P V
#pragma unroll 16
        for (int kk = 0; kk < 64; kk++) {
            float4 p4 = *(const float4*)&Pt[kk * PADA + ty * 4];
            float4 v4 = *(const float4*)&Vs[kk * 64 + tx * 4];
            o[0][0] += p4.x * v4.x; o[0][1] += p4.x * v4.y; o[0][2] += p4.x * v4.z; o[0][3] += p4.x * v4.w;
            o[1][0] += p4.y * v4.x; o[1][1] += p4.y * v4.y; o[1][2] += p4.y * v4.z; o[1][3] += p4.y * v4.w;
            o[2][0] += p4.z * v4.x; o[2][1] += p4.z * v4.y; o[2][2] += p4.z * v4.z; o[2][3] += p4.z * v4.w;
            o[3][0] += p4.w * v4.x; o[3][1] += p4.w * v4.y; o[3][2] += p4.w * v4.z; o[3][3] += p4.w * v4.w;
        }
    }

    // epilogue: normalize and write ctx[b, q, h*64 + d]
#pragma unroll
    for (int i = 0; i < 4; i++) {
        float inv = __fdividef(1.f, l[i]);
        float4 w = make_float4(o[i][0] * inv, o[i][1] * inv, o[i][2] * inv, o[i][3] * inv);
        size_t row = (size_t)b * NQ + qt * 64 + ty * 4 + i;
        *(float4*)(ctx + row * INNER + h * DH + tx * 4) = w;
    }
}

// ---------------- launcher ----------------
extern "C" void kernel_launch(void* const* d_in, const int* in_sizes, int n_in,
                              void* d_out, int out_size) {
    const float* x     = (const float*)d_in[0];
    const float* key_t = (const float*)d_in[1];
    const float* value = (const float*)d_in[2];
    const int*   mask  = (const int*)d_in[3];
    const float* Wq    = (const float*)d_in[4];
    const float* Wk    = (const float*)d_in[5];
    const float* Wv    = (const float*)d_in[6];
    const float* Wo    = (const float*)d_in[7];
    const float* gamma = (const float*)d_in[8];
    const float* beta  = (const float*)d_in[9];
    float* out = (float*)d_out;

    float *xn, *q, *k, *v, *ctx;
    cudaGetSymbolAddress((void**)&xn,  g_xn);
    cudaGetSymbolAddress((void**)&q,   g_q);
    cudaGetSymbolAddress((void**)&k,   g_k);
    cudaGetSymbolAddress((void**)&v,   g_v);
    cudaGetSymbolAddress((void**)&ctx, g_ctx);

    const int ATTN_SMEM = (3 * 64 * PADA + 64 * 64) * 4 + 64 * 64;  // 72704 B
    cudaFuncSetAttribute(attn_kernel, cudaFuncAttributeMaxDynamicSharedMemorySize, ATTN_SMEM);

    ln_kernel<<<BATCH * NQ, 256>>>(x, gamma, beta, xn);

    dim3 gq(INNER / 64, BATCH * NQ / 64);
    dim3 gkv(INNER / 64, BATCH * NKV / 64);
    sgemm_kernel<<<gq, 256>>>(xn, Wq, q, BATCH * NQ, INNER, DMODEL);
    sgemm_kernel<<<gkv, 256>>>(key_t, Wk, k, BATCH * NKV, INNER, DMODEL);
    sgemm_kernel<<<gkv, 256>>>(value, Wv, v, BATCH * NKV, INNER, DMODEL);

    attn_kernel<<<dim3(NQ / 64, HEADS, BATCH), 256, ATTN_SMEM>>>(q, k, v, mask, ctx);

    sgemm_kernel<<<gq, 256>>>(ctx, Wo, out, BATCH * NQ, DMODEL, INNER);
}

// round 4
// speedup vs baseline: 1.6103x; 1.6103x over previous
#include <cuda_runtime.h>
#include <cuda_bf16.h>
#include <math.h>
#include <cstdint>

#define BATCH  4
#define NQ     1024
#define NKV    2048
#define DMODEL 1024
#define HEADS  16
#define DH     64
#define INNER  1024
#define KDIM   1024

// ---------------- scratch (no allocation allowed) ----------------
__device__ float g_xn [BATCH * NQ  * DMODEL];
__device__ float g_q  [BATCH * NQ  * INNER];
__device__ float g_k  [BATCH * NKV * INNER];
__device__ float g_v  [BATCH * NKV * INNER];
__device__ float g_ctx[BATCH * NQ  * INNER];
__device__ float g_wqt[KDIM * INNER];
__device__ float g_wkt[KDIM * INNER];
__device__ float g_wvt[KDIM * INNER];
__device__ float g_wot[KDIM * INNER];

__device__ __forceinline__ uint32_t f2tf(float f) {
    uint32_t r;
    asm("cvt.rna.tf32.f32 %0, %1;" : "=r"(r) : "f"(f));
    return r;
}

// ---------------- weight transpose: dst[n][k] = src[k][n] ----------------
__global__ void transpose_kernel(const float* __restrict__ src, float* __restrict__ dst) {
    __shared__ float t[32][33];
    int bx = blockIdx.x * 32, by = blockIdx.y * 32;
    int x = threadIdx.x, y = threadIdx.y;   // 32 x 8
#pragma unroll
    for (int i = 0; i < 32; i += 8)
        t[y + i][x] = src[(size_t)(by + y + i) * KDIM + bx + x];
    __syncthreads();
#pragma unroll
    for (int i = 0; i < 32; i += 8)
        dst[(size_t)(bx + y + i) * KDIM + by + x] = t[x][y + i];
}

// ---------------- LayerNorm: one block per row ----------------
__global__ void ln_kernel(const float* __restrict__ x,
                          const float* __restrict__ gamma,
                          const float* __restrict__ beta,
                          float* __restrict__ y) {
    __shared__ float red[16];
    int row = blockIdx.x;
    int tid = threadIdx.x;
    const float4* xr = (const float4*)(x + (size_t)row * DMODEL);
    float4 a = xr[tid];
    float s = a.x + a.y + a.z + a.w;
    float q = a.x * a.x + a.y * a.y + a.z * a.z + a.w * a.w;
#pragma unroll
    for (int off = 16; off; off >>= 1) {
        s += __shfl_xor_sync(0xffffffffu, s, off);
        q += __shfl_xor_sync(0xffffffffu, q, off);
    }
    if ((tid & 31) == 0) { red[tid >> 5] = s; red[8 + (tid >> 5)] = q; }
    __syncthreads();
    if (tid < 32) {
        float ss = (tid < 8) ? red[tid] : 0.f;
        float qq = (tid < 8) ? red[8 + tid] : 0.f;
#pragma unroll
        for (int off = 4; off; off >>= 1) {
            ss += __shfl_xor_sync(0xffffffffu, ss, off);
            qq += __shfl_xor_sync(0xffffffffu, qq, off);
        }
        if (tid == 0) { red[0] = ss; red[1] = qq; }
    }
    __syncthreads();
    float mu  = red[0] * (1.f / DMODEL);
    float var = red[1] * (1.f / DMODEL) - mu * mu;
    float inv = rsqrtf(var + 1e-5f);
    float4 g = ((const float4*)gamma)[tid];
    float4 b = ((const float4*)beta)[tid];
    float4 o;
    o.x = (a.x - mu) * inv * g.x + b.x;
    o.y = (a.y - mu) * inv * g.y + b.y;
    o.z = (a.z - mu) * inv * g.z + b.z;
    o.w = (a.w - mu) * inv * g.w + b.w;
    ((float4*)(y + (size_t)row * DMODEL))[tid] = o;
}

// ---------------- tf32 mma.sync GEMM: C[M,1024] = A[M,1024] * Bt[1024,1024]^T --
// Tile 128x128, BK=32, 8 warps (4m x 2n), warp tile 32x64, m16n8k8 tf32.
#define GPAD 36
#define GBUF (128 * GPAD)
#define GT_SMEM (4 * GBUF * 4)   // 2 bufs x (A+B) x 128*36 words * 4B = 73728

__global__ void __launch_bounds__(256, 1)
gemm_mma(const float* __restrict__ A, const float* __restrict__ Bt, float* __restrict__ C) {
    extern __shared__ uint32_t smw[];
    uint32_t* As = smw;              // [2][128][GPAD]
    uint32_t* Bs = smw + 2 * GBUF;   // [2][128][GPAD]

    int tid = threadIdx.x, lane = tid & 31, wid = tid >> 5;
    int wm = (wid & 3) * 32, wn = (wid >> 2) * 64;

    const float* Ab = A  + (size_t)(blockIdx.y * 128) * KDIM;
    const float* Bb = Bt + (size_t)(blockIdx.x * 128) * KDIM;

    float acc[2][8][4] = {};
    float4 stA[4], stB[4];

#define LDG_TILE(it) do { \
    _Pragma("unroll") \
    for (int i = 0; i < 4; i++) { \
        int idx = tid + i * 256; int rr = idx >> 3, qq = idx & 7; \
        stA[i] = *(const float4*)(Ab + (size_t)rr * KDIM + (it) * 32 + qq * 4); \
        stB[i] = *(const float4*)(Bb + (size_t)rr * KDIM + (it) * 32 + qq * 4); \
    } } while (0)

#define STS_TILE(buf) do { \
    _Pragma("unroll") \
    for (int i = 0; i < 4; i++) { \
        int idx = tid + i * 256; int rr = idx >> 3, qq = idx & 7; \
        uint4 ta = make_uint4(f2tf(stA[i].x), f2tf(stA[i].y), f2tf(stA[i].z), f2tf(stA[i].w)); \
        uint4 tb = make_uint4(f2tf(stB[i].x), f2tf(stB[i].y), f2tf(stB[i].z), f2tf(stB[i].w)); \
        *(uint4*)&As[(buf) * GBUF + rr * GPAD + qq * 4] = ta; \
        *(uint4*)&Bs[(buf) * GBUF + rr * GPAD + qq * 4] = tb; \
    } } while (0)

    LDG_TILE(0);
    STS_TILE(0);
    __syncthreads();

    for (int it = 0; it < 32; it++) {
        int buf = it & 1;
        if (it < 31) LDG_TILE(it + 1);

        const uint32_t* Abuf = &As[buf * GBUF];
        const uint32_t* Bbuf = &Bs[buf * GBUF];
#pragma unroll
        for (int ks = 0; ks < 4; ks++) {
            int kb = ks * 8 + (lane & 3);
            uint32_t a[2][4];
#pragma unroll
            for (int mf = 0; mf < 2; mf++) {
                int row = wm + mf * 16 + (lane >> 2);
                a[mf][0] = Abuf[row * GPAD + kb];
                a[mf][1] = Abuf[(row + 8) * GPAD + kb];
                a[mf][2] = Abuf[row * GPAD + kb + 4];
                a[mf][3] = Abuf[(row + 8) * GPAD + kb + 4];
            }
#pragma unroll
            for (int nf = 0; nf < 8; nf++) {
                int n = wn + nf * 8 + (lane >> 2);
                uint32_t b0 = Bbuf[n * GPAD + kb];
                uint32_t b1 = Bbuf[n * GPAD + kb + 4];
#pragma unroll
                for (int mf = 0; mf < 2; mf++) {
                    asm volatile(
                        "mma.sync.aligned.m16n8k8.row.col.f32.tf32.tf32.f32 "
                        "{%0,%1,%2,%3}, {%4,%5,%6,%7}, {%8,%9}, {%0,%1,%2,%3};"
                        : "+f"(acc[mf][nf][0]), "+f"(acc[mf][nf][1]),
                          "+f"(acc[mf][nf][2]), "+f"(acc[mf][nf][3])
                        : "r"(a[mf][0]), "r"(a[mf][1]), "r"(a[mf][2]), "r"(a[mf][3]),
                          "r"(b0), "r"(b1));
                }
            }
        }
        __syncthreads();
        if (it < 31) {
            STS_TILE(buf ^ 1);
            __syncthreads();
        }
    }

    float* Cb = C + (size_t)(blockIdx.y * 128) * 1024 + blockIdx.x * 128;
#pragma unroll
    for (int mf = 0; mf < 2; mf++) {
        int row = wm + mf * 16 + (lane >> 2);
#pragma unroll
        for (int nf = 0; nf < 8; nf++) {
            int col = wn + nf * 8 + (lane & 3) * 2;
            *(float2*)(Cb + (size_t)row * 1024 + col) = make_float2(acc[mf][nf][0], acc[mf][nf][1]);
            *(float2*)(Cb + (size_t)(row + 8) * 1024 + col) = make_float2(acc[mf][nf][2], acc[mf][nf][3]);
        }
    }
#undef LDG_TILE
#undef STS_TILE
}

// ---------------- Flash attention: 64x64 tiles per (qtile, h, b) ----------------
#define PADA 68
__global__ void attn_kernel(const float* __restrict__ Q,
                            const float* __restrict__ K,
                            const float* __restrict__ V,
                            const int* __restrict__ mask,   // int32: nonzero => masked out
                            float* __restrict__ ctx) {
    extern __shared__ float sm[];
    float* Qt = sm;
    float* Kt = Qt + 64 * PADA;
    float* Pt = Kt + 64 * PADA;
    float* Vs = Pt + 64 * PADA;
    unsigned char* Ms = (unsigned char*)(Vs + 64 * 64);

    int tid = threadIdx.x;
    int tx = tid & 15, ty = tid >> 4;
    int b = blockIdx.z, h = blockIdx.y, qt = blockIdx.x;

    const float* Qb = Q + ((size_t)b * NQ + qt * 64) * INNER + h * DH;
    const float* Kb = K + (size_t)b * NKV * INNER + h * DH;
    const float* Vb = V + (size_t)b * NKV * INNER + h * DH;
    const int* Mb = mask + ((size_t)b * NQ + qt * 64) * NKV;

    {
        int r = tid >> 2, cb = tid & 3;
        const float* src = Qb + (size_t)r * INNER;
#pragma unroll
        for (int it = 0; it < 4; it++) {
            int c = (cb + it * 4) * 4;
            float4 v = *(const float4*)(src + c);
            Qt[(c + 0) * PADA + r] = v.x;
            Qt[(c + 1) * PADA + r] = v.y;
            Qt[(c + 2) * PADA + r] = v.z;
            Qt[(c + 3) * PADA + r] = v.w;
        }
    }

    float o[4][4] = {};
    float m[4], l[4];
#pragma unroll
    for (int i = 0; i < 4; i++) { m[i] = -3.402823466e38f; l[i] = 0.f; }

    const float scl = 0.125f;

    for (int t = 0; t < NKV / 64; t++) {
        __syncthreads();
        {
            int r = tid >> 2, cb = tid & 3;
            const float* ksrc = Kb + (size_t)(t * 64 + r) * INNER;
            const float* vsrc = Vb + (size_t)(t * 64 + r) * INNER;
            const int* msrc = Mb + (size_t)r * NKV + t * 64;
#pragma unroll
            for (int it = 0; it < 4; it++) {
                int c = (cb + it * 4) * 4;
                float4 kv = *(const float4*)(ksrc + c);
                Kt[(c + 0) * PADA + r] = kv.x;
                Kt[(c + 1) * PADA + r] = kv.y;
                Kt[(c + 2) * PADA + r] = kv.z;
                Kt[(c + 3) * PADA + r] = kv.w;
                *(float4*)&Vs[r * 64 + c] = *(const float4*)(vsrc + c);
                int4 mi = *(const int4*)(msrc + c);
                Ms[r * 64 + c + 0] = (unsigned char)(mi.x != 0);
                Ms[r * 64 + c + 1] = (unsigned char)(mi.y != 0);
                Ms[r * 64 + c + 2] = (unsigned char)(mi.z != 0);
                Ms[r * 64 + c + 3] = (unsigned char)(mi.w != 0);
            }
        }
        __syncthreads();

        float s[4][4] = {};
#pragma unroll 16
        for (int kk = 0; kk < 64; kk++) {
            float4 a = *(const float4*)&Qt[kk * PADA + ty * 4];
            float4 bb = *(const float4*)&Kt[kk * PADA + tx * 4];
            s[0][0] += a.x * bb.x; s[0][1] += a.x * bb.y; s[0][2] += a.x * bb.z; s[0][3] += a.x * bb.w;
            s[1][0] += a.y * bb.x; s[1][1] += a.y * bb.y; s[1][2] += a.y * bb.z; s[1][3] += a.y * bb.w;
            s[2][0] += a.z * bb.x; s[2][1] += a.z * bb.y; s[2][2] += a.z * bb.z; s[2][3] += a.z * bb.w;
            s[3][0] += a.w * bb.x; s[3][1] += a.w * bb.y; s[3][2] += a.w * bb.z; s[3][3] += a.w * bb.w;
        }

#pragma unroll
        for (int i = 0; i < 4; i++) {
#pragma unroll
            for (int j = 0; j < 4; j++) {
                float sv = s[i][j] * scl;
                if (Ms[(ty * 4 + i) * 64 + tx * 4 + j]) sv = -3.402823466e38f;
                s[i][j] = sv;
            }
            float r0 = fmaxf(fmaxf(s[i][0], s[i][1]), fmaxf(s[i][2], s[i][3]));
#pragma unroll
            for (int off = 8; off; off >>= 1)
                r0 = fmaxf(r0, __shfl_xor_sync(0xffffffffu, r0, off));
            float mn = fmaxf(m[i], r0);
            float corr = __expf(m[i] - mn);
            m[i] = mn;
            float ls = 0.f;
#pragma unroll
            for (int j = 0; j < 4; j++) {
                float p = __expf(s[i][j] - mn);
                s[i][j] = p;
                ls += p;
            }
#pragma unroll
            for (int off = 8; off; off >>= 1)
                ls += __shfl_xor_sync(0xffffffffu, ls, off);
            l[i] = l[i] * corr + ls;
            o[i][0] *= corr; o[i][1] *= corr; o[i][2] *= corr; o[i][3] *= corr;
        }

#pragma unroll
        for (int i = 0; i < 4; i++)
#pragma unroll
            for (int j = 0; j < 4; j++)
                Pt[(tx * 4 + j) * PADA + ty * 4 + i] = s[i][j];
        __syncthreads();

#pragma unroll 16
        for (int kk = 0; kk < 64; kk++) {
            float4 p4 = *(const float4*)&Pt[kk * PADA + ty * 4];
            float4 v4 = *(const float4*)&Vs[kk * 64 + tx * 4];
            o[0][0] += p4.x * v4.x; o[0][1] += p4.x * v4.y; o[0][2] += p4.x * v4.z; o[0][3] += p4.x * v4.w;
            o[1][0] += p4.y * v4.x; o[1][1] += p4.y * v4.y; o[1][2] += p4.y * v4.z; o[1][3] += p4.y * v4.w;
            o[2][0] += p4.z * v4.x; o[2][1] += p4.z * v4.y; o[2][2] += p4.z * v4.z; o[2][3] += p4.z * v4.w;
            o[3][0] += p4.w * v4.x; o[3][1] += p4.w * v4.y; o[3][2] += p4.w * v4.z; o[3][3] += p4.w * v4.w;
        }
    }

#pragma unroll
    for (int i = 0; i < 4; i++) {
        float inv = __fdividef(1.f, l[i]);
        float4 w = make_float4(o[i][0] * inv, o[i][1] * inv, o[i][2] * inv, o[i][3] * inv);
        size_t row = (size_t)b * NQ + qt * 64 + ty * 4 + i;
        *(float4*)(ctx + row * INNER + h * DH + tx * 4) = w;
    }
}

// ---------------- launcher ----------------
extern "C" void kernel_launch(void* const* d_in, const int* in_sizes, int n_in,
                              void* d_out, int out_size) {
    const float* x     = (const float*)d_in[0];
    const float* key_t = (const float*)d_in[1];
    const float* value = (const float*)d_in[2];
    const int*   mask  = (const int*)d_in[3];
    const float* Wq    = (const float*)d_in[4];
    const float* Wk    = (const float*)d_in[5];
    const float* Wv    = (const float*)d_in[6];
    const float* Wo    = (const float*)d_in[7];
    const float* gamma = (const float*)d_in[8];
    const float* beta  = (const float*)d_in[9];
    float* out = (float*)d_out;

    float *xn, *q, *k, *v, *ctx, *wqt, *wkt, *wvt, *wot;
    cudaGetSymbolAddress((void**)&xn,  g_xn);
    cudaGetSymbolAddress((void**)&q,   g_q);
    cudaGetSymbolAddress((void**)&k,   g_k);
    cudaGetSymbolAddress((void**)&v,   g_v);
    cudaGetSymbolAddress((void**)&ctx, g_ctx);
    cudaGetSymbolAddress((void**)&wqt, g_wqt);
    cudaGetSymbolAddress((void**)&wkt, g_wkt);
    cudaGetSymbolAddress((void**)&wvt, g_wvt);
    cudaGetSymbolAddress((void**)&wot, g_wot);

    const int ATTN_SMEM = (3 * 64 * PADA + 64 * 64) * 4 + 64 * 64;
    cudaFuncSetAttribute(attn_kernel, cudaFuncAttributeMaxDynamicSharedMemorySize, ATTN_SMEM);
    cudaFuncSetAttribute(gemm_mma, cudaFuncAttributeMaxDynamicSharedMemorySize, GT_SMEM);

    dim3 tb(32, 8), tg(32, 32);
    transpose_kernel<<<tg, tb>>>(Wq, wqt);
    transpose_kernel<<<tg, tb>>>(Wk, wkt);
    transpose_kernel<<<tg, tb>>>(Wv, wvt);
    transpose_kernel<<<tg, tb>>>(Wo, wot);

    ln_kernel<<<BATCH * NQ, 256>>>(x, gamma, beta, xn);

    gemm_mma<<<dim3(8, 32), 256, GT_SMEM>>>(xn,    wqt, q);
    gemm_mma<<<dim3(8, 64), 256, GT_SMEM>>>(key_t, wkt, k);
    gemm_mma<<<dim3(8, 64), 256, GT_SMEM>>>(value, wvt, v);

    attn_kernel<<<dim3(NQ / 64, HEADS, BATCH), 256, ATTN_SMEM>>>(q, k, v, mask, ctx);

    gemm_mma<<<dim3(8, 32), 256, GT_SMEM>>>(ctx, wot, out);
}

// round 5
// speedup vs baseline: 2.4084x; 1.4956x over previous
#include <cuda_runtime.h>
#include <cuda_bf16.h>
#include <math.h>
#include <cstdint>

#define BATCH  4
#define NQ     1024
#define NKV    2048
#define DMODEL 1024
#define HEADS  16
#define DH     64
#define INNER  1024
#define KDIM   1024

// ---------------- scratch (no allocation allowed) ----------------
__device__ float g_xn [BATCH * NQ  * DMODEL];
__device__ float g_q  [BATCH * NQ  * INNER];
__device__ float g_k  [BATCH * NKV * INNER];
__device__ float g_v  [BATCH * NKV * INNER];
__device__ float g_ctx[BATCH * NQ  * INNER];
__device__ float g_wqt[KDIM * INNER];
__device__ float g_wkt[KDIM * INNER];
__device__ float g_wvt[KDIM * INNER];
__device__ float g_wot[KDIM * INNER];

__device__ __forceinline__ uint32_t f2tf(float f) {
    uint32_t r;
    asm("cvt.rna.tf32.f32 %0, %1;" : "=r"(r) : "f"(f));
    return r;
}

#define MMA_TF32(acc, a0, a1, a2, a3, b0, b1) \
    asm volatile( \
        "mma.sync.aligned.m16n8k8.row.col.f32.tf32.tf32.f32 " \
        "{%0,%1,%2,%3}, {%4,%5,%6,%7}, {%8,%9}, {%0,%1,%2,%3};" \
        : "+f"((acc)[0]), "+f"((acc)[1]), "+f"((acc)[2]), "+f"((acc)[3]) \
        : "r"(a0), "r"(a1), "r"(a2), "r"(a3), "r"(b0), "r"(b1))

// ---------------- weight transpose: dst[n][k] = src[k][n] ----------------
__global__ void transpose_kernel(const float* __restrict__ src, float* __restrict__ dst) {
    __shared__ float t[32][33];
    int bx = blockIdx.x * 32, by = blockIdx.y * 32;
    int x = threadIdx.x, y = threadIdx.y;   // 32 x 8
#pragma unroll
    for (int i = 0; i < 32; i += 8)
        t[y + i][x] = src[(size_t)(by + y + i) * KDIM + bx + x];
    __syncthreads();
#pragma unroll
    for (int i = 0; i < 32; i += 8)
        dst[(size_t)(bx + y + i) * KDIM + by + x] = t[x][y + i];
}

// ---------------- LayerNorm: one block per row ----------------
__global__ void ln_kernel(const float* __restrict__ x,
                          const float* __restrict__ gamma,
                          const float* __restrict__ beta,
                          float* __restrict__ y) {
    __shared__ float red[16];
    int row = blockIdx.x;
    int tid = threadIdx.x;
    const float4* xr = (const float4*)(x + (size_t)row * DMODEL);
    float4 a = xr[tid];
    float s = a.x + a.y + a.z + a.w;
    float q = a.x * a.x + a.y * a.y + a.z * a.z + a.w * a.w;
#pragma unroll
    for (int off = 16; off; off >>= 1) {
        s += __shfl_xor_sync(0xffffffffu, s, off);
        q += __shfl_xor_sync(0xffffffffu, q, off);
    }
    if ((tid & 31) == 0) { red[tid >> 5] = s; red[8 + (tid >> 5)] = q; }
    __syncthreads();
    if (tid < 32) {
        float ss = (tid < 8) ? red[tid] : 0.f;
        float qq = (tid < 8) ? red[8 + tid] : 0.f;
#pragma unroll
        for (int off = 4; off; off >>= 1) {
            ss += __shfl_xor_sync(0xffffffffu, ss, off);
            qq += __shfl_xor_sync(0xffffffffu, qq, off);
        }
        if (tid == 0) { red[0] = ss; red[1] = qq; }
    }
    __syncthreads();
    float mu  = red[0] * (1.f / DMODEL);
    float var = red[1] * (1.f / DMODEL) - mu * mu;
    float inv = rsqrtf(var + 1e-5f);
    float4 g = ((const float4*)gamma)[tid];
    float4 b = ((const float4*)beta)[tid];
    float4 o;
    o.x = (a.x - mu) * inv * g.x + b.x;
    o.y = (a.y - mu) * inv * g.y + b.y;
    o.z = (a.z - mu) * inv * g.z + b.z;
    o.w = (a.w - mu) * inv * g.w + b.w;
    ((float4*)(y + (size_t)row * DMODEL))[tid] = o;
}

// ---------------- tf32 mma.sync GEMM: C[M,1024] = A[M,1024] * Bt[1024,1024]^T --
#define GPAD 36
#define GBUF (128 * GPAD)
#define GT_SMEM (4 * GBUF * 4)

__global__ void __launch_bounds__(256, 1)
gemm_mma(const float* __restrict__ A, const float* __restrict__ Bt, float* __restrict__ C) {
    extern __shared__ uint32_t smw[];
    uint32_t* As = smw;
    uint32_t* Bs = smw + 2 * GBUF;

    int tid = threadIdx.x, lane = tid & 31, wid = tid >> 5;
    int wm = (wid & 3) * 32, wn = (wid >> 2) * 64;

    const float* Ab = A  + (size_t)(blockIdx.y * 128) * KDIM;
    const float* Bb = Bt + (size_t)(blockIdx.x * 128) * KDIM;

    float acc[2][8][4] = {};
    float4 stA[4], stB[4];

#define LDG_TILE(it) do { \
    _Pragma("unroll") \
    for (int i = 0; i < 4; i++) { \
        int idx = tid + i * 256; int rr = idx >> 3, qq = idx & 7; \
        stA[i] = *(const float4*)(Ab + (size_t)rr * KDIM + (it) * 32 + qq * 4); \
        stB[i] = *(const float4*)(Bb + (size_t)rr * KDIM + (it) * 32 + qq * 4); \
    } } while (0)

#define STS_TILE(buf) do { \
    _Pragma("unroll") \
    for (int i = 0; i < 4; i++) { \
        int idx = tid + i * 256; int rr = idx >> 3, qq = idx & 7; \
        uint4 ta = make_uint4(f2tf(stA[i].x), f2tf(stA[i].y), f2tf(stA[i].z), f2tf(stA[i].w)); \
        uint4 tb = make_uint4(f2tf(stB[i].x), f2tf(stB[i].y), f2tf(stB[i].z), f2tf(stB[i].w)); \
        *(uint4*)&As[(buf) * GBUF + rr * GPAD + qq * 4] = ta; \
        *(uint4*)&Bs[(buf) * GBUF + rr * GPAD + qq * 4] = tb; \
    } } while (0)

    LDG_TILE(0);
    STS_TILE(0);
    __syncthreads();

    for (int it = 0; it < 32; it++) {
        int buf = it & 1;
        if (it < 31) LDG_TILE(it + 1);

        const uint32_t* Abuf = &As[buf * GBUF];
        const uint32_t* Bbuf = &Bs[buf * GBUF];
#pragma unroll
        for (int ks = 0; ks < 4; ks++) {
            int kb = ks * 8 + (lane & 3);
            uint32_t a[2][4];
#pragma unroll
            for (int mf = 0; mf < 2; mf++) {
                int row = wm + mf * 16 + (lane >> 2);
                a[mf][0] = Abuf[row * GPAD + kb];
                a[mf][1] = Abuf[(row + 8) * GPAD + kb];
                a[mf][2] = Abuf[row * GPAD + kb + 4];
                a[mf][3] = Abuf[(row + 8) * GPAD + kb + 4];
            }
#pragma unroll
            for (int nf = 0; nf < 8; nf++) {
                int n = wn + nf * 8 + (lane >> 2);
                uint32_t b0 = Bbuf[n * GPAD + kb];
                uint32_t b1 = Bbuf[n * GPAD + kb + 4];
#pragma unroll
                for (int mf = 0; mf < 2; mf++)
                    MMA_TF32(acc[mf][nf], a[mf][0], a[mf][1], a[mf][2], a[mf][3], b0, b1);
            }
        }
        __syncthreads();
        if (it < 31) {
            STS_TILE(buf ^ 1);
            __syncthreads();
        }
    }

    float* Cb = C + (size_t)(blockIdx.y * 128) * 1024 + blockIdx.x * 128;
#pragma unroll
    for (int mf = 0; mf < 2; mf++) {
        int row = wm + mf * 16 + (lane >> 2);
#pragma unroll
        for (int nf = 0; nf < 8; nf++) {
            int col = wn + nf * 8 + (lane & 3) * 2;
            *(float2*)(Cb + (size_t)row * 1024 + col) = make_float2(acc[mf][nf][0], acc[mf][nf][1]);
            *(float2*)(Cb + (size_t)(row + 8) * 1024 + col) = make_float2(acc[mf][nf][2], acc[mf][nf][3]);
        }
    }
#undef LDG_TILE
#undef STS_TILE
}

// ---------------- tf32 mma flash attention: 128 q x 64 kv tiles ----------------
// 8 warps; warp w owns q rows [w*16, w*16+16) (one m16 fragment) x 64 kv.
#define APAD 68
#define ATTN_SMEM ((128 * APAD + 64 * APAD + 64 * APAD + 128 * APAD) * 4 + 128 * 64)

__global__ void __launch_bounds__(256, 1)
attn_mma(const float* __restrict__ Q,
         const float* __restrict__ K,
         const float* __restrict__ V,
         const int* __restrict__ mask,
         float* __restrict__ ctx) {
    extern __shared__ uint32_t sw[];
    uint32_t* Qs = sw;                       // [128][APAD]  Q[m][d] tf32
    uint32_t* Ks = Qs + 128 * APAD;          // [64][APAD]   K[kv][d] tf32
    uint32_t* Vs = Ks + 64 * APAD;           // [64][APAD]   V[kv][d] tf32
    uint32_t* Ps = Vs + 64 * APAD;           // [128][APAD]  P[m][kv] tf32 (per-warp slices)
    unsigned char* Ms = (unsigned char*)(Ps + 128 * APAD);   // [128][64]

    int tid = threadIdx.x, lane = tid & 31, wid = tid >> 5;
    int b = blockIdx.z, h = blockIdx.y, qt = blockIdx.x;

    const float* Qb = Q + ((size_t)b * NQ + qt * 128) * INNER + h * DH;
    const float* Kb = K + (size_t)b * NKV * INNER + h * DH;
    const float* Vb = V + (size_t)b * NKV * INNER + h * DH;
    const int* Mb = mask + ((size_t)b * NQ + qt * 128) * NKV;

    // load Q tile (natural layout, tf32)
#pragma unroll
    for (int i = 0; i < 8; i++) {
        int idx = tid + i * 256;            // 0..2047
        int r = idx >> 4, c4 = (idx & 15) * 4;
        float4 v = *(const float4*)(Qb + (size_t)r * INNER + c4);
        *(uint4*)&Qs[r * APAD + c4] = make_uint4(f2tf(v.x), f2tf(v.y), f2tf(v.z), f2tf(v.w));
    }

    const int r1 = wid * 16 + (lane >> 2);  // local q row (and r1+8)
    const int c0 = (lane & 3) * 2;

    float oacc[8][4] = {};
    float m1 = -3.402823466e38f, m2 = -3.402823466e38f;
    float l1 = 0.f, l2 = 0.f;
    const float scl = 0.125f;

    for (int t = 0; t < NKV / 64; t++) {
        __syncthreads();
        // K/V tiles (natural layout) + mask tile
#pragma unroll
        for (int i = 0; i < 4; i++) {
            int idx = tid + i * 256;        // 0..1023
            int r = idx >> 4, c4 = (idx & 15) * 4;
            float4 kv = *(const float4*)(Kb + (size_t)(t * 64 + r) * INNER + c4);
            *(uint4*)&Ks[r * APAD + c4] = make_uint4(f2tf(kv.x), f2tf(kv.y), f2tf(kv.z), f2tf(kv.w));
            float4 vv = *(const float4*)(Vb + (size_t)(t * 64 + r) * INNER + c4);
            *(uint4*)&Vs[r * APAD + c4] = make_uint4(f2tf(vv.x), f2tf(vv.y), f2tf(vv.z), f2tf(vv.w));
        }
#pragma unroll
        for (int i = 0; i < 8; i++) {
            int idx = tid + i * 256;        // 0..2047
            int r = idx >> 4, c4 = (idx & 15) * 4;
            int4 mi = *(const int4*)(Mb + (size_t)r * NKV + t * 64 + c4);
            Ms[r * 64 + c4 + 0] = (unsigned char)(mi.x != 0);
            Ms[r * 64 + c4 + 1] = (unsigned char)(mi.y != 0);
            Ms[r * 64 + c4 + 2] = (unsigned char)(mi.z != 0);
            Ms[r * 64 + c4 + 3] = (unsigned char)(mi.w != 0);
        }
        __syncthreads();

        // ---- S = Q K^T (warp: 16 x 64) ----
        float sacc[8][4] = {};
#pragma unroll
        for (int ks = 0; ks < 8; ks++) {
            int kb = ks * 8 + (lane & 3);
            uint32_t a0 = Qs[r1 * APAD + kb];
            uint32_t a1 = Qs[(r1 + 8) * APAD + kb];
            uint32_t a2 = Qs[r1 * APAD + kb + 4];
            uint32_t a3 = Qs[(r1 + 8) * APAD + kb + 4];
#pragma unroll
            for (int nf = 0; nf < 8; nf++) {
                int n = nf * 8 + (lane >> 2);
                uint32_t b0 = Ks[n * APAD + kb];
                uint32_t b1 = Ks[n * APAD + kb + 4];
                MMA_TF32(sacc[nf], a0, a1, a2, a3, b0, b1);
            }
        }

        // ---- scale + mask + online softmax ----
        float tm1 = -3.402823466e38f, tm2 = -3.402823466e38f;
#pragma unroll
        for (int nf = 0; nf < 8; nf++) {
            int c = nf * 8 + c0;
            float s0 = sacc[nf][0] * scl, s1 = sacc[nf][1] * scl;
            float s2 = sacc[nf][2] * scl, s3 = sacc[nf][3] * scl;
            if (Ms[r1 * 64 + c])           s0 = -3.402823466e38f;
            if (Ms[r1 * 64 + c + 1])       s1 = -3.402823466e38f;
            if (Ms[(r1 + 8) * 64 + c])     s2 = -3.402823466e38f;
            if (Ms[(r1 + 8) * 64 + c + 1]) s3 = -3.402823466e38f;
            sacc[nf][0] = s0; sacc[nf][1] = s1; sacc[nf][2] = s2; sacc[nf][3] = s3;
            tm1 = fmaxf(tm1, fmaxf(s0, s1));
            tm2 = fmaxf(tm2, fmaxf(s2, s3));
        }
        tm1 = fmaxf(tm1, __shfl_xor_sync(0xffffffffu, tm1, 1));
        tm1 = fmaxf(tm1, __shfl_xor_sync(0xffffffffu, tm1, 2));
        tm2 = fmaxf(tm2, __shfl_xor_sync(0xffffffffu, tm2, 1));
        tm2 = fmaxf(tm2, __shfl_xor_sync(0xffffffffu, tm2, 2));

        float mn1 = fmaxf(m1, tm1), mn2 = fmaxf(m2, tm2);
        float corr1 = __expf(m1 - mn1), corr2 = __expf(m2 - mn2);
        m1 = mn1; m2 = mn2;

        float ls1 = 0.f, ls2 = 0.f;
#pragma unroll
        for (int nf = 0; nf < 8; nf++) {
            int c = nf * 8 + c0;
            float p0 = __expf(sacc[nf][0] - mn1);
            float p1 = __expf(sacc[nf][1] - mn1);
            float p2 = __expf(sacc[nf][2] - mn2);
            float p3 = __expf(sacc[nf][3] - mn2);
            ls1 += p0 + p1; ls2 += p2 + p3;
            *(uint2*)&Ps[r1 * APAD + c]       = make_uint2(f2tf(p0), f2tf(p1));
            *(uint2*)&Ps[(r1 + 8) * APAD + c] = make_uint2(f2tf(p2), f2tf(p3));
        }
        ls1 += __shfl_xor_sync(0xffffffffu, ls1, 1);
        ls1 += __shfl_xor_sync(0xffffffffu, ls1, 2);
        ls2 += __shfl_xor_sync(0xffffffffu, ls2, 1);
        ls2 += __shfl_xor_sync(0xffffffffu, ls2, 2);
        l1 = l1 * corr1 + ls1;
        l2 = l2 * corr2 + ls2;
#pragma unroll
        for (int nf = 0; nf < 8; nf++) {
            oacc[nf][0] *= corr1; oacc[nf][1] *= corr1;
            oacc[nf][2] *= corr2; oacc[nf][3] *= corr2;
        }
        __syncwarp();

        // ---- O += P V  (A = Ps warp slice, B = Vs[kv][d]) ----
#pragma unroll
        for (int ks = 0; ks < 8; ks++) {
            int kb = ks * 8 + (lane & 3);
            uint32_t a0 = Ps[r1 * APAD + kb];
            uint32_t a1 = Ps[(r1 + 8) * APAD + kb];
            uint32_t a2 = Ps[r1 * APAD + kb + 4];
            uint32_t a3 = Ps[(r1 + 8) * APAD + kb + 4];
#pragma unroll
            for (int nf = 0; nf < 8; nf++) {
                int n = nf * 8 + (lane >> 2);
                uint32_t b0 = Vs[kb * APAD + n];
                uint32_t b1 = Vs[(kb + 4) * APAD + n];
                MMA_TF32(oacc[nf], a0, a1, a2, a3, b0, b1);
            }
        }
    }

    // epilogue
    float inv1 = __fdividef(1.f, l1), inv2 = __fdividef(1.f, l2);
    float* o1 = ctx + ((size_t)b * NQ + qt * 128 + r1) * INNER + h * DH;
    float* o2 = o1 + (size_t)8 * INNER;
#pragma unroll
    for (int nf = 0; nf < 8; nf++) {
        int c = nf * 8 + c0;
        *(float2*)(o1 + c) = make_float2(oacc[nf][0] * inv1, oacc[nf][1] * inv1);
        *(float2*)(o2 + c) = make_float2(oacc[nf][2] * inv2, oacc[nf][3] * inv2);
    }
}

// ---------------- launcher ----------------
extern "C" void kernel_launch(void* const* d_in, const int* in_sizes, int n_in,
                              void* d_out, int out_size) {
    const float* x     = (const float*)d_in[0];
    const float* key_t = (const float*)d_in[1];
    const float* value = (const float*)d_in[2];
    const int*   mask  = (const int*)d_in[3];
    const float* Wq    = (const float*)d_in[4];
    const float* Wk    = (const float*)d_in[5];
    const float* Wv    = (const float*)d_in[6];
    const float* Wo    = (const float*)d_in[7];
    const float* gamma = (const float*)d_in[8];
    const float* beta  = (const float*)d_in[9];
    float* out = (float*)d_out;

    float *xn, *q, *k, *v, *ctx, *wqt, *wkt, *wvt, *wot;
    cudaGetSymbolAddress((void**)&xn,  g_xn);
    cudaGetSymbolAddress((void**)&q,   g_q);
    cudaGetSymbolAddress((void**)&k,   g_k);
    cudaGetSymbolAddress((void**)&v,   g_v);
    cudaGetSymbolAddress((void**)&ctx, g_ctx);
    cudaGetSymbolAddress((void**)&wqt, g_wqt);
    cudaGetSymbolAddress((void**)&wkt, g_wkt);
    cudaGetSymbolAddress((void**)&wvt, g_wvt);
    cudaGetSymbolAddress((void**)&wot, g_wot);

    cudaFuncSetAttribute(attn_mma, cudaFuncAttributeMaxDynamicSharedMemorySize, ATTN_SMEM);
    cudaFuncSetAttribute(gemm_mma, cudaFuncAttributeMaxDynamicSharedMemorySize, GT_SMEM);

    dim3 tb(32, 8), tg(32, 32);
    transpose_kernel<<<tg, tb>>>(Wq, wqt);
    transpose_kernel<<<tg, tb>>>(Wk, wkt);
    transpose_kernel<<<tg, tb>>>(Wv, wvt);
    transpose_kernel<<<tg, tb>>>(Wo, wot);

    ln_kernel<<<BATCH * NQ, 256>>>(x, gamma, beta, xn);

    gemm_mma<<<dim3(8, 32), 256, GT_SMEM>>>(xn,    wqt, q);
    gemm_mma<<<dim3(8, 64), 256, GT_SMEM>>>(key_t, wkt, k);
    gemm_mma<<<dim3(8, 64), 256, GT_SMEM>>>(value, wvt, v);

    attn_mma<<<dim3(NQ / 128, HEADS, BATCH), 256, ATTN_SMEM>>>(q, k, v, mask, ctx);

    gemm_mma<<<dim3(8, 32), 256, GT_SMEM>>>(ctx, wot, out);
}

// round 6
// speedup vs baseline: 2.8206x; 1.1712x over previous
#include <cuda_runtime.h>
#include <cuda_bf16.h>
#include <math.h>
#include <cstdint>

#define BATCH  4
#define NQ     1024
#define NKV    2048
#define DMODEL 1024
#define HEADS  16
#define DH     64
#define INNER  1024
#define KDIM   1024

// ---------------- scratch (no allocation allowed) ----------------
__device__ float g_xn [BATCH * NQ  * DMODEL];
__device__ float g_q  [BATCH * NQ  * INNER];
__device__ float g_k  [BATCH * NKV * INNER];
__device__ float g_v  [BATCH * NKV * INNER];
__device__ float g_ctx[BATCH * NQ  * INNER];
__device__ float g_wqt[KDIM * INNER];
__device__ float g_wkt[KDIM * INNER];
__device__ float g_wvt[KDIM * INNER];
__device__ float g_wot[KDIM * INNER];
__device__ float g_kin[BATCH * NKV * KDIM];
__device__ float g_vin[BATCH * NKV * KDIM];
__device__ unsigned char g_m8[BATCH * NQ * NKV];

__device__ __forceinline__ uint32_t f2tf(float f) {
    uint32_t r;
    asm("cvt.rna.tf32.f32 %0, %1;" : "=r"(r) : "f"(f));
    return r;
}
__device__ __forceinline__ float f2tf_f(float f) { return __uint_as_float(f2tf(f)); }

__device__ __forceinline__ uint32_t smem_to_u32(const void* p) {
    uint32_t a;
    asm("{ .reg .u64 t; cvta.to.shared.u64 t, %1; cvt.u32.u64 %0, t; }" : "=r"(a) : "l"(p));
    return a;
}
__device__ __forceinline__ void cp_async16(uint32_t saddr, const void* g) {
    asm volatile("cp.async.cg.shared.global [%0], [%1], 16;" :: "r"(saddr), "l"(g));
}
#define CP_COMMIT() asm volatile("cp.async.commit_group;")
#define CP_WAIT(n)  asm volatile("cp.async.wait_group %0;" :: "n"(n) : "memory")

#define MMA_TF32(acc, a0, a1, a2, a3, b0, b1) \
    asm volatile( \
        "mma.sync.aligned.m16n8k8.row.col.f32.tf32.tf32.f32 " \
        "{%0,%1,%2,%3}, {%4,%5,%6,%7}, {%8,%9}, {%0,%1,%2,%3};" \
        : "+f"((acc)[0]), "+f"((acc)[1]), "+f"((acc)[2]), "+f"((acc)[3]) \
        : "r"(a0), "r"(a1), "r"(a2), "r"(a3), "r"(b0), "r"(b1))

// ---------------- elementwise round to tf32 ----------------
__global__ void round_kernel(const float* __restrict__ src, float* __restrict__ dst) {
    int i = blockIdx.x * 256 + threadIdx.x;
    float4 v = ((const float4*)src)[i];
    ((float4*)dst)[i] = make_float4(f2tf_f(v.x), f2tf_f(v.y), f2tf_f(v.z), f2tf_f(v.w));
}

// ---------------- mask int32 -> byte ----------------
__global__ void mask8_kernel(const int* __restrict__ src, unsigned char* __restrict__ dst) {
    size_t base = ((size_t)blockIdx.x * 256 + threadIdx.x) * 16;
    uint32_t w[4];
#pragma unroll
    for (int j = 0; j < 4; j++) {
        int4 v = *(const int4*)(src + base + j * 4);
        w[j] = (v.x ? 1u : 0u) | (v.y ? 0x100u : 0u) | (v.z ? 0x10000u : 0u) | (v.w ? 0x1000000u : 0u);
    }
    *(uint4*)(dst + base) = make_uint4(w[0], w[1], w[2], w[3]);
}

// ---------------- weight transpose (rounded): dst[n][k] = tf32(src[k][n]) ------
__global__ void transpose_kernel(const float* __restrict__ src, float* __restrict__ dst) {
    __shared__ float t[32][33];
    int bx = blockIdx.x * 32, by = blockIdx.y * 32;
    int x = threadIdx.x, y = threadIdx.y;   // 32 x 8
#pragma unroll
    for (int i = 0; i < 32; i += 8)
        t[y + i][x] = src[(size_t)(by + y + i) * KDIM + bx + x];
    __syncthreads();
#pragma unroll
    for (int i = 0; i < 32; i += 8)
        dst[(size_t)(bx + y + i) * KDIM + by + x] = f2tf_f(t[x][y + i]);
}

// ---------------- LayerNorm (tf32-rounded output) ----------------
__global__ void ln_kernel(const float* __restrict__ x,
                          const float* __restrict__ gamma,
                          const float* __restrict__ beta,
                          float* __restrict__ y) {
    __shared__ float red[16];
    int row = blockIdx.x;
    int tid = threadIdx.x;
    const float4* xr = (const float4*)(x + (size_t)row * DMODEL);
    float4 a = xr[tid];
    float s = a.x + a.y + a.z + a.w;
    float q = a.x * a.x + a.y * a.y + a.z * a.z + a.w * a.w;
#pragma unroll
    for (int off = 16; off; off >>= 1) {
        s += __shfl_xor_sync(0xffffffffu, s, off);
        q += __shfl_xor_sync(0xffffffffu, q, off);
    }
    if ((tid & 31) == 0) { red[tid >> 5] = s; red[8 + (tid >> 5)] = q; }
    __syncthreads();
    if (tid < 32) {
        float ss = (tid < 8) ? red[tid] : 0.f;
        float qq = (tid < 8) ? red[8 + tid] : 0.f;
#pragma unroll
        for (int off = 4; off; off >>= 1) {
            ss += __shfl_xor_sync(0xffffffffu, ss, off);
            qq += __shfl_xor_sync(0xffffffffu, qq, off);
        }
        if (tid == 0) { red[0] = ss; red[1] = qq; }
    }
    __syncthreads();
    float mu  = red[0] * (1.f / DMODEL);
    float var = red[1] * (1.f / DMODEL) - mu * mu;
    float inv = rsqrtf(var + 1e-5f);
    float4 g = ((const float4*)gamma)[tid];
    float4 b = ((const float4*)beta)[tid];
    float4 o;
    o.x = f2tf_f((a.x - mu) * inv * g.x + b.x);
    o.y = f2tf_f((a.y - mu) * inv * g.y + b.y);
    o.z = f2tf_f((a.z - mu) * inv * g.z + b.z);
    o.w = f2tf_f((a.w - mu) * inv * g.w + b.w);
    ((float4*)(y + (size_t)row * DMODEL))[tid] = o;
}

// ---------------- tf32 mma GEMM (cp.async double-buffered) --------------------
// C[M,1024] = A[M,1024] * Bt[1024,1024]^T. Inputs are tf32-exact fp32.
#define GPAD 36
#define GBUF (128 * GPAD)
#define GT_SMEM (4 * GBUF * 4)

__global__ void __launch_bounds__(256, 2)
gemm_mma(const float* __restrict__ A, const float* __restrict__ Bt,
         float* __restrict__ C, int round_out) {
    extern __shared__ uint32_t smw[];
    uint32_t sb = smem_to_u32(smw);
    int tid = threadIdx.x, lane = tid & 31, wid = tid >> 5;
    int wm = (wid & 3) * 32, wn = (wid >> 2) * 64;

    const float* Ab = A  + (size_t)(blockIdx.y * 128) * KDIM;
    const float* Bb = Bt + (size_t)(blockIdx.x * 128) * KDIM;

    float acc[2][8][4] = {};

#define G_ISSUE(it, bf) do { \
    uint32_t abase = sb + (bf) * (GBUF * 4); \
    uint32_t bbase = sb + (2 + (bf)) * (GBUF * 4); \
    _Pragma("unroll") \
    for (int i = 0; i < 4; i++) { \
        int idx = tid + i * 256; int rr = idx >> 3, qq = idx & 7; \
        cp_async16(abase + (rr * GPAD + qq * 4) * 4, Ab + (size_t)rr * KDIM + (it) * 32 + qq * 4); \
        cp_async16(bbase + (rr * GPAD + qq * 4) * 4, Bb + (size_t)rr * KDIM + (it) * 32 + qq * 4); \
    } \
    CP_COMMIT(); \
} while (0)

    G_ISSUE(0, 0);

    for (int it = 0; it < 32; it++) {
        int buf = it & 1;
        if (it < 31) { G_ISSUE(it + 1, buf ^ 1); CP_WAIT(1); }
        else         { CP_WAIT(0); }
        __syncthreads();

        const uint32_t* Abuf = smw + buf * GBUF;
        const uint32_t* Bbuf = smw + (2 + buf) * GBUF;
#pragma unroll
        for (int ks = 0; ks < 4; ks++) {
            int kb = ks * 8 + (lane & 3);
            uint32_t a[2][4];
#pragma unroll
            for (int mf = 0; mf < 2; mf++) {
                int row = wm + mf * 16 + (lane >> 2);
                a[mf][0] = Abuf[row * GPAD + kb];
                a[mf][1] = Abuf[(row + 8) * GPAD + kb];
                a[mf][2] = Abuf[row * GPAD + kb + 4];
                a[mf][3] = Abuf[(row + 8) * GPAD + kb + 4];
            }
#pragma unroll
            for (int nf = 0; nf < 8; nf++) {
                int n = wn + nf * 8 + (lane >> 2);
                uint32_t b0 = Bbuf[n * GPAD + kb];
                uint32_t b1 = Bbuf[n * GPAD + kb + 4];
#pragma unroll
                for (int mf = 0; mf < 2; mf++)
                    MMA_TF32(acc[mf][nf], a[mf][0], a[mf][1], a[mf][2], a[mf][3], b0, b1);
            }
        }
        __syncthreads();
    }
#undef G_ISSUE

    float* Cb = C + (size_t)(blockIdx.y * 128) * 1024 + blockIdx.x * 128;
#pragma unroll
    for (int mf = 0; mf < 2; mf++) {
        int row = wm + mf * 16 + (lane >> 2);
#pragma unroll
        for (int nf = 0; nf < 8; nf++) {
            int col = wn + nf * 8 + (lane & 3) * 2;
            float2 w0 = make_float2(acc[mf][nf][0], acc[mf][nf][1]);
            float2 w1 = make_float2(acc[mf][nf][2], acc[mf][nf][3]);
            if (round_out) {
                w0.x = f2tf_f(w0.x); w0.y = f2tf_f(w0.y);
                w1.x = f2tf_f(w1.x); w1.y = f2tf_f(w1.y);
            }
            *(float2*)(Cb + (size_t)row * 1024 + col) = w0;
            *(float2*)(Cb + (size_t)(row + 8) * 1024 + col) = w1;
        }
    }
}

// ---------------- tf32 mma flash attention (cp.async double-buffered) ---------
#define APAD 68
#define QW (128 * APAD)
#define KW (64 * APAD)
#define PS_OFF (QW + 4 * KW)
#define MS_BYTEOFF ((2 * QW + 4 * KW) * 4)
#define ATTN_SMEM (MS_BYTEOFF + 2 * 8192)   // 155648

__global__ void __launch_bounds__(256, 1)
attn_mma(const float* __restrict__ Q,
         const float* __restrict__ K,
         const float* __restrict__ V,
         const unsigned char* __restrict__ mask8,
         float* __restrict__ ctx) {
    extern __shared__ uint32_t sw[];
    uint32_t sb = smem_to_u32(sw);

    int tid = threadIdx.x, lane = tid & 31, wid = tid >> 5;
    int b = blockIdx.z, h = blockIdx.y, qt = blockIdx.x;

    const float* Qb = Q + ((size_t)b * NQ + qt * 128) * INNER + h * DH;
    const float* Kb = K + (size_t)b * NKV * INNER + h * DH;
    const float* Vb = V + (size_t)b * NKV * INNER + h * DH;
    const unsigned char* M8b = mask8 + ((size_t)b * NQ + qt * 128) * NKV;

    // issue Q tile (group 0)
#pragma unroll
    for (int i = 0; i < 8; i++) {
        int idx = tid + i * 256;
        int r = idx >> 4, c4 = (idx & 15) * 4;
        cp_async16(sb + (r * APAD + c4) * 4, Qb + (size_t)r * INNER + c4);
    }
    CP_COMMIT();

#define A_ISSUE(t, bf) do { \
    uint32_t kb_ = sb + (QW + (bf) * KW) * 4; \
    uint32_t vb_ = sb + (QW + 2 * KW + (bf) * KW) * 4; \
    uint32_t mb_ = sb + MS_BYTEOFF + (bf) * 8192; \
    _Pragma("unroll") \
    for (int i = 0; i < 4; i++) { \
        int idx = tid + i * 256; int r = idx >> 4, c4 = (idx & 15) * 4; \
        cp_async16(kb_ + (r * APAD + c4) * 4, Kb + (size_t)((t) * 64 + r) * INNER + c4); \
        cp_async16(vb_ + (r * APAD + c4) * 4, Vb + (size_t)((t) * 64 + r) * INNER + c4); \
    } \
    _Pragma("unroll") \
    for (int i = 0; i < 2; i++) { \
        int idx = tid + i * 256; int row = idx >> 2, off = (idx & 3) * 16; \
        cp_async16(mb_ + row * 64 + off, M8b + (size_t)row * NKV + (t) * 64 + off); \
    } \
    CP_COMMIT(); \
} while (0)

    A_ISSUE(0, 0);

    const int r1 = wid * 16 + (lane >> 2);
    const int c0 = (lane & 3) * 2;

    float oacc[8][4] = {};
    float m1 = -3.402823466e38f, m2 = -3.402823466e38f;
    float l1 = 0.f, l2 = 0.f;
    const float scl = 0.125f;

    const uint32_t* Qs = sw;
    uint32_t* Ps = sw + PS_OFF;

    for (int t = 0; t < NKV / 64; t++) {
        int buf = t & 1;
        if (t < 31) { A_ISSUE(t + 1, buf ^ 1); CP_WAIT(1); }
        else        { CP_WAIT(0); }
        __syncthreads();

        const uint32_t* Ks = sw + QW + buf * KW;
        const uint32_t* Vs = sw + QW + 2 * KW + buf * KW;
        const unsigned char* Msb = (const unsigned char*)sw + MS_BYTEOFF + buf * 8192;

        // ---- S = Q K^T ----
        float sacc[8][4] = {};
#pragma unroll
        for (int ks = 0; ks < 8; ks++) {
            int kb = ks * 8 + (lane & 3);
            uint32_t a0 = Qs[r1 * APAD + kb];
            uint32_t a1 = Qs[(r1 + 8) * APAD + kb];
            uint32_t a2 = Qs[r1 * APAD + kb + 4];
            uint32_t a3 = Qs[(r1 + 8) * APAD + kb + 4];
#pragma unroll
            for (int nf = 0; nf < 8; nf++) {
                int n = nf * 8 + (lane >> 2);
                uint32_t b0 = Ks[n * APAD + kb];
                uint32_t b1 = Ks[n * APAD + kb + 4];
                MMA_TF32(sacc[nf], a0, a1, a2, a3, b0, b1);
            }
        }

        // ---- scale + mask + online softmax ----
        float tm1 = -3.402823466e38f, tm2 = -3.402823466e38f;
#pragma unroll
        for (int nf = 0; nf < 8; nf++) {
            int c = nf * 8 + c0;
            unsigned short mm1 = *(const unsigned short*)(Msb + r1 * 64 + c);
            unsigned short mm2 = *(const unsigned short*)(Msb + (r1 + 8) * 64 + c);
            float s0 = sacc[nf][0] * scl, s1 = sacc[nf][1] * scl;
            float s2 = sacc[nf][2] * scl, s3 = sacc[nf][3] * scl;
            if (mm1 & 0xFF) s0 = -3.402823466e38f;
            if (mm1 >> 8)   s1 = -3.402823466e38f;
            if (mm2 & 0xFF) s2 = -3.402823466e38f;
            if (mm2 >> 8)   s3 = -3.402823466e38f;
            sacc[nf][0] = s0; sacc[nf][1] = s1; sacc[nf][2] = s2; sacc[nf][3] = s3;
            tm1 = fmaxf(tm1, fmaxf(s0, s1));
            tm2 = fmaxf(tm2, fmaxf(s2, s3));
        }
        tm1 = fmaxf(tm1, __shfl_xor_sync(0xffffffffu, tm1, 1));
        tm1 = fmaxf(tm1, __shfl_xor_sync(0xffffffffu, tm1, 2));
        tm2 = fmaxf(tm2, __shfl_xor_sync(0xffffffffu, tm2, 1));
        tm2 = fmaxf(tm2, __shfl_xor_sync(0xffffffffu, tm2, 2));

        float mn1 = fmaxf(m1, tm1), mn2 = fmaxf(m2, tm2);
        float corr1 = __expf(m1 - mn1), corr2 = __expf(m2 - mn2);
        m1 = mn1; m2 = mn2;

        float ls1 = 0.f, ls2 = 0.f;
#pragma unroll
        for (int nf = 0; nf < 8; nf++) {
            int c = nf * 8 + c0;
            float p0 = __expf(sacc[nf][0] - mn1);
            float p1 = __expf(sacc[nf][1] - mn1);
            float p2 = __expf(sacc[nf][2] - mn2);
            float p3 = __expf(sacc[nf][3] - mn2);
            ls1 += p0 + p1; ls2 += p2 + p3;
            *(uint2*)&Ps[r1 * APAD + c]       = make_uint2(f2tf(p0), f2tf(p1));
            *(uint2*)&Ps[(r1 + 8) * APAD + c] = make_uint2(f2tf(p2), f2tf(p3));
        }
        ls1 += __shfl_xor_sync(0xffffffffu, ls1, 1);
        ls1 += __shfl_xor_sync(0xffffffffu, ls1, 2);
        ls2 += __shfl_xor_sync(0xffffffffu, ls2, 1);
        ls2 += __shfl_xor_sync(0xffffffffu, ls2, 2);
        l1 = l1 * corr1 + ls1;
        l2 = l2 * corr2 + ls2;
#pragma unroll
        for (int nf = 0; nf < 8; nf++) {
            oacc[nf][0] *= corr1; oacc[nf][1] *= corr1;
            oacc[nf][2] *= corr2; oacc[nf][3] *= corr2;
        }
        __syncwarp();

        // ---- O += P V ----
#pragma unroll
        for (int ks = 0; ks < 8; ks++) {
            int kb = ks * 8 + (lane & 3);
            uint32_t a0 = Ps[r1 * APAD + kb];
            uint32_t a1 = Ps[(r1 + 8) * APAD + kb];
            uint32_t a2 = Ps[r1 * APAD + kb + 4];
            uint32_t a3 = Ps[(r1 + 8) * APAD + kb + 4];
#pragma unroll
            for (int nf = 0; nf < 8; nf++) {
                int n = nf * 8 + (lane >> 2);
                uint32_t b0 = Vs[kb * APAD + n];
                uint32_t b1 = Vs[(kb + 4) * APAD + n];
                MMA_TF32(oacc[nf], a0, a1, a2, a3, b0, b1);
            }
        }
        __syncthreads();
    }
#undef A_ISSUE

    // epilogue: write ctx tf32-rounded (feeds final GEMM)
    float inv1 = __fdividef(1.f, l1), inv2 = __fdividef(1.f, l2);
    float* o1 = ctx + ((size_t)b * NQ + qt * 128 + r1) * INNER + h * DH;
    float* o2 = o1 + (size_t)8 * INNER;
#pragma unroll
    for (int nf = 0; nf < 8; nf++) {
        int c = nf * 8 + c0;
        *(float2*)(o1 + c) = make_float2(f2tf_f(oacc[nf][0] * inv1), f2tf_f(oacc[nf][1] * inv1));
        *(float2*)(o2 + c) = make_float2(f2tf_f(oacc[nf][2] * inv2), f2tf_f(oacc[nf][3] * inv2));
    }
}

// ---------------- launcher ----------------
extern "C" void kernel_launch(void* const* d_in, const int* in_sizes, int n_in,
                              void* d_out, int out_size) {
    const float* x     = (const float*)d_in[0];
    const float* key_t = (const float*)d_in[1];
    const float* value = (const float*)d_in[2];
    const int*   mask  = (const int*)d_in[3];
    const float* Wq    = (const float*)d_in[4];
    const float* Wk    = (const float*)d_in[5];
    const float* Wv    = (const float*)d_in[6];
    const float* Wo    = (const float*)d_in[7];
    const float* gamma = (const float*)d_in[8];
    const float* beta  = (const float*)d_in[9];
    float* out = (float*)d_out;

    float *xn, *q, *k, *v, *ctx, *wqt, *wkt, *wvt, *wot, *kin, *vin;
    unsigned char* m8;
    cudaGetSymbolAddress((void**)&xn,  g_xn);
    cudaGetSymbolAddress((void**)&q,   g_q);
    cudaGetSymbolAddress((void**)&k,   g_k);
    cudaGetSymbolAddress((void**)&v,   g_v);
    cudaGetSymbolAddress((void**)&ctx, g_ctx);
    cudaGetSymbolAddress((void**)&wqt, g_wqt);
    cudaGetSymbolAddress((void**)&wkt, g_wkt);
    cudaGetSymbolAddress((void**)&wvt, g_wvt);
    cudaGetSymbolAddress((void**)&wot, g_wot);
    cudaGetSymbolAddress((void**)&kin, g_kin);
    cudaGetSymbolAddress((void**)&vin, g_vin);
    cudaGetSymbolAddress((void**)&m8,  g_m8);

    cudaFuncSetAttribute(attn_mma, cudaFuncAttributeMaxDynamicSharedMemorySize, ATTN_SMEM);
    cudaFuncSetAttribute(gemm_mma, cudaFuncAttributeMaxDynamicSharedMemorySize, GT_SMEM);

    dim3 tb(32, 8), tg(32, 32);
    transpose_kernel<<<tg, tb>>>(Wq, wqt);
    transpose_kernel<<<tg, tb>>>(Wk, wkt);
    transpose_kernel<<<tg, tb>>>(Wv, wvt);
    transpose_kernel<<<tg, tb>>>(Wo, wot);

    round_kernel<<<BATCH * NKV * KDIM / 4 / 256, 256>>>(key_t, kin);
    round_kernel<<<BATCH * NKV * KDIM / 4 / 256, 256>>>(value, vin);
    mask8_kernel<<<BATCH * NQ * NKV / 16 / 256, 256>>>(mask, m8);

    ln_kernel<<<BATCH * NQ, 256>>>(x, gamma, beta, xn);

    gemm_mma<<<dim3(8, 32), 256, GT_SMEM>>>(xn,  wqt, q, 1);
    gemm_mma<<<dim3(8, 64), 256, GT_SMEM>>>(kin, wkt, k, 1);
    gemm_mma<<<dim3(8, 64), 256, GT_SMEM>>>(vin, wvt, v, 1);

    attn_mma<<<dim3(NQ / 128, HEADS, BATCH), 256, ATTN_SMEM>>>(q, k, v, m8, ctx);

    gemm_mma<<<dim3(8, 32), 256, GT_SMEM>>>(ctx, wot, out, 0);
}

// round 9
// speedup vs baseline: 3.3894x; 1.2016x over previous
#include <cuda_runtime.h>
#include <cuda_bf16.h>
#include <math.h>
#include <cstdint>

#define BATCH  4
#define NQ     1024
#define NKV    2048
#define DMODEL 1024
#define HEADS  16
#define DH     64
#define INNER  1024
#define KDIM   1024

// ---------------- scratch (no allocation allowed) ----------------
__device__ float g_xn [BATCH * NQ  * DMODEL];
__device__ float g_q  [BATCH * NQ  * INNER];
__device__ float g_k  [BATCH * NKV * INNER];
__device__ float g_v  [BATCH * NKV * INNER];
__device__ float g_ctx[BATCH * NQ  * INNER];
__device__ float g_wqt[KDIM * INNER];
__device__ float g_wkt[KDIM * INNER];
__device__ float g_wvt[KDIM * INNER];
__device__ float g_wot[KDIM * INNER];
__device__ float g_kin[BATCH * NKV * KDIM];
__device__ float g_vin[BATCH * NKV * KDIM];
__device__ unsigned long long g_mb[BATCH * 32 * NQ];   // [b][kvblock][q] bitmask

__device__ __forceinline__ uint32_t f2tf(float f) {
    uint32_t r;
    asm("cvt.rna.tf32.f32 %0, %1;" : "=r"(r) : "f"(f));
    return r;
}
__device__ __forceinline__ float f2tf_f(float f) { return __uint_as_float(f2tf(f)); }

__device__ __forceinline__ uint32_t smem_to_u32(const void* p) {
    uint32_t a;
    asm("{ .reg .u64 t; cvta.to.shared.u64 t, %1; cvt.u32.u64 %0, t; }" : "=r"(a) : "l"(p));
    return a;
}
__device__ __forceinline__ void cp_async16(uint32_t saddr, const void* g) {
    asm volatile("cp.async.cg.shared.global [%0], [%1], 16;" :: "r"(saddr), "l"(g));
}
#define CP_COMMIT() asm volatile("cp.async.commit_group;")
#define CP_WAIT(n)  asm volatile("cp.async.wait_group %0;" :: "n"(n) : "memory")

#define MMA_TF32(acc, a0, a1, a2, a3, b0, b1) \
    asm volatile( \
        "mma.sync.aligned.m16n8k8.row.col.f32.tf32.tf32.f32 " \
        "{%0,%1,%2,%3}, {%4,%5,%6,%7}, {%8,%9}, {%0,%1,%2,%3};" \
        : "+f"((acc)[0]), "+f"((acc)[1]), "+f"((acc)[2]), "+f"((acc)[3]) \
        : "r"(a0), "r"(a1), "r"(a2), "r"(a3), "r"(b0), "r"(b1))

// ---------------- elementwise round to tf32 ----------------
__global__ void round_kernel(const float* __restrict__ src, float* __restrict__ dst) {
    int i = blockIdx.x * 256 + threadIdx.x;
    float4 v = ((const float4*)src)[i];
    ((float4*)dst)[i] = make_float4(f2tf_f(v.x), f2tf_f(v.y), f2tf_f(v.z), f2tf_f(v.w));
}

// ---------------- mask int32 -> 1 bit, layout [b][kvblock t][q] ----------------
__global__ void maskbit_kernel(const int* __restrict__ src, unsigned long long* __restrict__ dst) {
    int idx = blockIdx.x * 256 + threadIdx.x;   // 131072 total
    int b = idx >> 15;
    int t = (idx >> 10) & 31;
    int q = idx & 1023;
    const int4* p = (const int4*)(src + (((size_t)b * NQ + q) * NKV + t * 64));
    unsigned long long bits = 0ull;
#pragma unroll
    for (int j = 0; j < 16; j++) {
        int4 v = p[j];
        bits |= (unsigned long long)(v.x != 0) << (4 * j);
        bits |= (unsigned long long)(v.y != 0) << (4 * j + 1);
        bits |= (unsigned long long)(v.z != 0) << (4 * j + 2);
        bits |= (unsigned long long)(v.w != 0) << (4 * j + 3);
    }
    dst[idx] = bits;
}

// ---------------- weight transpose (rounded): dst[n][k] = tf32(src[k][n]) ------
__global__ void transpose_kernel(const float* __restrict__ src, float* __restrict__ dst) {
    __shared__ float t[32][33];
    int bx = blockIdx.x * 32, by = blockIdx.y * 32;
    int x = threadIdx.x, y = threadIdx.y;   // 32 x 8
#pragma unroll
    for (int i = 0; i < 32; i += 8)
        t[y + i][x] = src[(size_t)(by + y + i) * KDIM + bx + x];
    __syncthreads();
#pragma unroll
    for (int i = 0; i < 32; i += 8)
        dst[(size_t)(bx + y + i) * KDIM + by + x] = f2tf_f(t[x][y + i]);
}

// ---------------- LayerNorm (tf32-rounded output) ----------------
__global__ void ln_kernel(const float* __restrict__ x,
                          const float* __restrict__ gamma,
                          const float* __restrict__ beta,
                          float* __restrict__ y) {
    __shared__ float red[16];
    int row = blockIdx.x;
    int tid = threadIdx.x;
    const float4* xr = (const float4*)(x + (size_t)row * DMODEL);
    float4 a = xr[tid];
    float s = a.x + a.y + a.z + a.w;
    float q = a.x * a.x + a.y * a.y + a.z * a.z + a.w * a.w;
#pragma unroll
    for (int off = 16; off; off >>= 1) {
        s += __shfl_xor_sync(0xffffffffu, s, off);
        q += __shfl_xor_sync(0xffffffffu, q, off);
    }
    if ((tid & 31) == 0) { red[tid >> 5] = s; red[8 + (tid >> 5)] = q; }
    __syncthreads();
    if (tid < 32) {
        float ss = (tid < 8) ? red[tid] : 0.f;
        float qq = (tid < 8) ? red[8 + tid] : 0.f;
#pragma unroll
        for (int off = 4; off; off >>= 1) {
            ss += __shfl_xor_sync(0xffffffffu, ss, off);
            qq += __shfl_xor_sync(0xffffffffu, qq, off);
        }
        if (tid == 0) { red[0] = ss; red[1] = qq; }
    }
    __syncthreads();
    float mu  = red[0] * (1.f / DMODEL);
    float var = red[1] * (1.f / DMODEL) - mu * mu;
    float inv = rsqrtf(var + 1e-5f);
    float4 g = ((const float4*)gamma)[tid];
    float4 b = ((const float4*)beta)[tid];
    float4 o;
    o.x = f2tf_f((a.x - mu) * inv * g.x + b.x);
    o.y = f2tf_f((a.y - mu) * inv * g.y + b.y);
    o.z = f2tf_f((a.z - mu) * inv * g.z + b.z);
    o.w = f2tf_f((a.w - mu) * inv * g.w + b.w);
    ((float4*)(y + (size_t)row * DMODEL))[tid] = o;
}

// ---------------- tf32 mma GEMM (cp.async double-buffered) --------------------
#define GPAD 36
#define GBUF (128 * GPAD)
#define GT_SMEM (4 * GBUF * 4)

__global__ void __launch_bounds__(256, 2)
gemm_mma(const float* __restrict__ A, const float* __restrict__ Bt,
         float* __restrict__ C, int round_out) {
    extern __shared__ uint32_t smw[];
    uint32_t sb = smem_to_u32(smw);
    int tid = threadIdx.x, lane = tid & 31, wid = tid >> 5;
    int wm = (wid & 3) * 32, wn = (wid >> 2) * 64;

    const float* Ab = A  + (size_t)(blockIdx.y * 128) * KDIM;
    const float* Bb = Bt + (size_t)(blockIdx.x * 128) * KDIM;

    float acc[2][8][4] = {};

#define G_ISSUE(it, bf) do { \
    uint32_t abase = sb + (bf) * (GBUF * 4); \
    uint32_t bbase = sb + (2 + (bf)) * (GBUF * 4); \
    _Pragma("unroll") \
    for (int i = 0; i < 4; i++) { \
        int idx = tid + i * 256; int rr = idx >> 3, qq = idx & 7; \
        cp_async16(abase + (rr * GPAD + qq * 4) * 4, Ab + (size_t)rr * KDIM + (it) * 32 + qq * 4); \
        cp_async16(bbase + (rr * GPAD + qq * 4) * 4, Bb + (size_t)rr * KDIM + (it) * 32 + qq * 4); \
    } \
    CP_COMMIT(); \
} while (0)

    G_ISSUE(0, 0);

    for (int it = 0; it < 32; it++) {
        int buf = it & 1;
        if (it < 31) { G_ISSUE(it + 1, buf ^ 1); CP_WAIT(1); }
        else         { CP_WAIT(0); }
        __syncthreads();

        const uint32_t* Abuf = smw + buf * GBUF;
        const uint32_t* Bbuf = smw + (2 + buf) * GBUF;
#pragma unroll
        for (int ks = 0; ks < 4; ks++) {
            int kb = ks * 8 + (lane & 3);
            uint32_t a[2][4];
#pragma unroll
            for (int mf = 0; mf < 2; mf++) {
                int row = wm + mf * 16 + (lane >> 2);
                a[mf][0] = Abuf[row * GPAD + kb];
                a[mf][1] = Abuf[(row + 8) * GPAD + kb];
                a[mf][2] = Abuf[row * GPAD + kb + 4];
                a[mf][3] = Abuf[(row + 8) * GPAD + kb + 4];
            }
#pragma unroll
            for (int nf = 0; nf < 8; nf++) {
                int n = wn + nf * 8 + (lane >> 2);
                uint32_t b0 = Bbuf[n * GPAD + kb];
                uint32_t b1 = Bbuf[n * GPAD + kb + 4];
#pragma unroll
                for (int mf = 0; mf < 2; mf++)
                    MMA_TF32(acc[mf][nf], a[mf][0], a[mf][1], a[mf][2], a[mf][3], b0, b1);
            }
        }
        __syncthreads();
    }
#undef G_ISSUE

    float* Cb = C + (size_t)(blockIdx.y * 128) * 1024 + blockIdx.x * 128;
#pragma unroll
    for (int mf = 0; mf < 2; mf++) {
        int row = wm + mf * 16 + (lane >> 2);
#pragma unroll
        for (int nf = 0; nf < 8; nf++) {
            int col = wn + nf * 8 + (lane & 3) * 2;
            float2 w0 = make_float2(acc[mf][nf][0], acc[mf][nf][1]);
            float2 w1 = make_float2(acc[mf][nf][2], acc[mf][nf][3]);
            if (round_out) {
                w0.x = f2tf_f(w0.x); w0.y = f2tf_f(w0.y);
                w1.x = f2tf_f(w1.x); w1.y = f2tf_f(w1.y);
            }
            *(float2*)(Cb + (size_t)row * 1024 + col) = w0;
            *(float2*)(Cb + (size_t)(row + 8) * 1024 + col) = w1;
        }
    }
}

// ---------------- tf32 mma flash attention: 256 q x 64 kv, 32-row warps -------
#define APAD 68
#define VPAD 72
#define QTILE 256
#define AQ_W  (QTILE * APAD)                 // 17408 words
#define AK_W  (64 * APAD)                    // 4352 words
#define AV_W  (64 * VPAD)                    // 4608 words
#define PS_W  (AQ_W + 2 * AK_W + 2 * AV_W)   // word offset of Ps
#define MB_BYTE ((PS_W + AQ_W) * 4)          // byte offset of mask buffers
#define ATTN_SMEM (MB_BYTE + 2 * 2048)

__global__ void __launch_bounds__(256, 1)
attn_mma(const float* __restrict__ Q,
         const float* __restrict__ K,
         const float* __restrict__ V,
         const unsigned long long* __restrict__ mbits,
         float* __restrict__ ctx) {
    extern __shared__ uint32_t sw[];
    uint32_t sb = smem_to_u32(sw);

    int tid = threadIdx.x, lane = tid & 31, wid = tid >> 5;
    int b = blockIdx.z, h = blockIdx.y, qt = blockIdx.x;
    const int g = lane >> 2, t4 = lane & 3;
    const int wm = wid * 32;

    const float* Qb = Q + ((size_t)b * NQ + qt * QTILE) * INNER + h * DH;
    const float* Kb = K + (size_t)b * NKV * INNER + h * DH;
    const float* Vb = V + (size_t)b * NKV * INNER + h * DH;
    const char* Mb8 = (const char*)(mbits + (size_t)b * 32 * NQ) + (size_t)qt * QTILE * 8;

    // issue Q tile (group 0): 256 rows x 64 cols
#pragma unroll
    for (int i = 0; i < 16; i++) {
        int idx = tid + i * 256;
        int r = idx >> 4, c4 = (idx & 15) * 4;
        cp_async16(sb + (r * APAD + c4) * 4, Qb + (size_t)r * INNER + c4);
    }
    CP_COMMIT();

#define A_ISSUE(t, bf) do { \
    uint32_t kb_ = sb + (AQ_W + (bf) * AK_W) * 4; \
    uint32_t vb_ = sb + (AQ_W + 2 * AK_W + (bf) * AV_W) * 4; \
    uint32_t mb_ = sb + MB_BYTE + (bf) * 2048; \
    _Pragma("unroll") \
    for (int i = 0; i < 4; i++) { \
        int idx = tid + i * 256; int r = idx >> 4, c4 = (idx & 15) * 4; \
        cp_async16(kb_ + (r * APAD + c4) * 4, Kb + (size_t)((t) * 64 + r) * INNER + c4); \
        cp_async16(vb_ + (r * VPAD + c4) * 4, Vb + (size_t)((t) * 64 + r) * INNER + c4); \
    } \
    if (tid < 128) cp_async16(mb_ + tid * 16, Mb8 + (size_t)(t) * NQ * 8 + tid * 16); \
    CP_COMMIT(); \
} while (0)

    A_ISSUE(0, 0);

    float oacc[2][8][4] = {};
    float mrun[4], lrun[4];
#pragma unroll
    for (int i = 0; i < 4; i++) { mrun[i] = -3.402823466e38f; lrun[i] = 0.f; }
    const float scl = 0.125f;

    const uint32_t* Qs = sw;
    uint32_t* Ps = sw + PS_W;

    for (int t = 0; t < NKV / 64; t++) {
        int buf = t & 1;
        if (t < 31) { A_ISSUE(t + 1, buf ^ 1); CP_WAIT(1); }
        else        { CP_WAIT(0); }
        __syncthreads();

        const uint32_t* Ks = sw + AQ_W + buf * AK_W;
        const uint32_t* Vs = sw + AQ_W + 2 * AK_W + buf * AV_W;
        const unsigned long long* Msk =
            (const unsigned long long*)((const char*)sw + MB_BYTE + buf * 2048);

        // ---- S = Q K^T (warp: 32 x 64) ----
        float sacc[2][8][4] = {};
#pragma unroll
        for (int ks = 0; ks < 8; ks++) {
            int kb = ks * 8 + t4;
            uint32_t a[2][4];
#pragma unroll
            for (int mf = 0; mf < 2; mf++) {
                int row = wm + mf * 16 + g;
                a[mf][0] = Qs[row * APAD + kb];
                a[mf][1] = Qs[(row + 8) * APAD + kb];
                a[mf][2] = Qs[row * APAD + kb + 4];
                a[mf][3] = Qs[(row + 8) * APAD + kb + 4];
            }
#pragma unroll
            for (int nf = 0; nf < 8; nf++) {
                int n = nf * 8 + g;
                uint32_t b0 = Ks[n * APAD + kb];
                uint32_t b1 = Ks[n * APAD + kb + 4];
#pragma unroll
                for (int mf = 0; mf < 2; mf++)
                    MMA_TF32(sacc[mf][nf], a[mf][0], a[mf][1], a[mf][2], a[mf][3], b0, b1);
            }
        }

        // ---- mask + scale + online softmax (4 q-rows per thread) ----
        unsigned long long mbm[4];
        mbm[0] = Msk[wm + g];
        mbm[1] = Msk[wm + g + 8];
        mbm[2] = Msk[wm + g + 16];
        mbm[3] = Msk[wm + g + 24];
        int sh0 = t4 * 2;

        float tm[4];
#pragma unroll
        for (int i = 0; i < 4; i++) tm[i] = -3.402823466e38f;
#pragma unroll
        for (int mf = 0; mf < 2; mf++) {
            unsigned long long mlo = mbm[2 * mf], mhi = mbm[2 * mf + 1];
#pragma unroll
            for (int nf = 0; nf < 8; nf++) {
                int shn = nf * 8 + sh0;
                float s0 = sacc[mf][nf][0] * scl, s1 = sacc[mf][nf][1] * scl;
                float s2 = sacc[mf][nf][2] * scl, s3 = sacc[mf][nf][3] * scl;
                if ((mlo >> shn) & 1)       s0 = -3.402823466e38f;
                if ((mlo >> (shn + 1)) & 1) s1 = -3.402823466e38f;
                if ((mhi >> shn) & 1)       s2 = -3.402823466e38f;
                if ((mhi >> (shn + 1)) & 1) s3 = -3.402823466e38f;
                sacc[mf][nf][0] = s0; sacc[mf][nf][1] = s1;
                sacc[mf][nf][2] = s2; sacc[mf][nf][3] = s3;
                tm[2 * mf]     = fmaxf(tm[2 * mf], fmaxf(s0, s1));
                tm[2 * mf + 1] = fmaxf(tm[2 * mf + 1], fmaxf(s2, s3));
            }
        }
        float corr[4], mn[4];
#pragma unroll
        for (int i = 0; i < 4; i++) {
            tm[i] = fmaxf(tm[i], __shfl_xor_sync(0xffffffffu, tm[i], 1));
            tm[i] = fmaxf(tm[i], __shfl_xor_sync(0xffffffffu, tm[i], 2));
            mn[i] = fmaxf(mrun[i], tm[i]);
            corr[i] = __expf(mrun[i] - mn[i]);
            mrun[i] = mn[i];
        }
        float ls[4] = {0.f, 0.f, 0.f, 0.f};
#pragma unroll
        for (int mf = 0; mf < 2; mf++) {
#pragma unroll
            for (int nf = 0; nf < 8; nf++) {
                int c = nf * 8 + sh0;
                float p0 = __expf(sacc[mf][nf][0] - mn[2 * mf]);
                float p1 = __expf(sacc[mf][nf][1] - mn[2 * mf]);
                float p2 = __expf(sacc[mf][nf][2] - mn[2 * mf + 1]);
                float p3 = __expf(sacc[mf][nf][3] - mn[2 * mf + 1]);
                ls[2 * mf]     += p0 + p1;
                ls[2 * mf + 1] += p2 + p3;
                int row = wm + mf * 16 + g;
                *(uint2*)&Ps[row * APAD + c]       = make_uint2(f2tf(p0), f2tf(p1));
                *(uint2*)&Ps[(row + 8) * APAD + c] = make_uint2(f2tf(p2), f2tf(p3));
            }
        }
#pragma unroll
        for (int i = 0; i < 4; i++) {
            ls[i] += __shfl_xor_sync(0xffffffffu, ls[i], 1);
            ls[i] += __shfl_xor_sync(0xffffffffu, ls[i], 2);
            lrun[i] = lrun[i] * corr[i] + ls[i];
        }
#pragma unroll
        for (int mf = 0; mf < 2; mf++)
#pragma unroll
            for (int nf = 0; nf < 8; nf++) {
                oacc[mf][nf][0] *= corr[2 * mf];     oacc[mf][nf][1] *= corr[2 * mf];
                oacc[mf][nf][2] *= corr[2 * mf + 1]; oacc[mf][nf][3] *= corr[2 * mf + 1];
            }
        __syncwarp();

        // ---- O += P V ----
#pragma unroll
        for (int ks = 0; ks < 8; ks++) {
            int kb = ks * 8 + t4;
            uint32_t a[2][4];
#pragma unroll
            for (int mf = 0; mf < 2; mf++) {
                int row = wm + mf * 16 + g;
                a[mf][0] = Ps[row * APAD + kb];
                a[mf][1] = Ps[(row + 8) * APAD + kb];
                a[mf][2] = Ps[row * APAD + kb + 4];
                a[mf][3] = Ps[(row + 8) * APAD + kb + 4];
            }
#pragma unroll
            for (int nf = 0; nf < 8; nf++) {
                int n = nf * 8 + g;
                uint32_t b0 = Vs[kb * VPAD + n];
                uint32_t b1 = Vs[(kb + 4) * VPAD + n];
#pragma unroll
                for (int mf = 0; mf < 2; mf++)
                    MMA_TF32(oacc[mf][nf], a[mf][0], a[mf][1], a[mf][2], a[mf][3], b0, b1);
            }
        }
        __syncthreads();
    }
#undef A_ISSUE

    // epilogue: write ctx tf32-rounded
    float inv[4];
#pragma unroll
    for (int i = 0; i < 4; i++) inv[i] = __fdividef(1.f, lrun[i]);
#pragma unroll
    for (int mf = 0; mf < 2; mf++) {
        size_t row = (size_t)b * NQ + qt * QTILE + wm + mf * 16 + g;
        float* o1 = ctx + row * INNER + h * DH;
        float* o2 = o1 + (size_t)8 * INNER;
#pragma unroll
        for (int nf = 0; nf < 8; nf++) {
            int c = nf * 8 + t4 * 2;
            *(float2*)(o1 + c) = make_float2(f2tf_f(oacc[mf][nf][0] * inv[2 * mf]),
                                             f2tf_f(oacc[mf][nf][1] * inv[2 * mf]));
            *(float2*)(o2 + c) = make_float2(f2tf_f(oacc[mf][nf][2] * inv[2 * mf + 1]),
                                             f2tf_f(oacc[mf][nf][3] * inv[2 * mf + 1]));
        }
    }
}

// ---------------- launcher ----------------
extern "C" void kernel_launch(void* const* d_in, const int* in_sizes, int n_in,
                              void* d_out, int out_size) {
    const float* x     = (const float*)d_in[0];
    const float* key_t = (const float*)d_in[1];
    const float* value = (const float*)d_in[2];
    const int*   mask  = (const int*)d_in[3];
    const float* Wq    = (const float*)d_in[4];
    const float* Wk    = (const float*)d_in[5];
    const float* Wv    = (const float*)d_in[6];
    const float* Wo    = (const float*)d_in[7];
    const float* gamma = (const float*)d_in[8];
    const float* beta  = (const float*)d_in[9];
    float* out = (float*)d_out;

    float *xn, *q, *k, *v, *ctx, *wqt, *wkt, *wvt, *wot, *kin, *vin;
    unsigned long long* mb;
    cudaGetSymbolAddress((void**)&xn,  g_xn);
    cudaGetSymbolAddress((void**)&q,   g_q);
    cudaGetSymbolAddress((void**)&k,   g_k);
    cudaGetSymbolAddress((void**)&v,   g_v);
    cudaGetSymbolAddress((void**)&ctx, g_ctx);
    cudaGetSymbolAddress((void**)&wqt, g_wqt);
    cudaGetSymbolAddress((void**)&wkt, g_wkt);
    cudaGetSymbolAddress((void**)&wvt, g_wvt);
    cudaGetSymbolAddress((void**)&wot, g_wot);
    cudaGetSymbolAddress((void**)&kin, g_kin);
    cudaGetSymbolAddress((void**)&vin, g_vin);
    cudaGetSymbolAddress((void**)&mb,  g_mb);

    cudaFuncSetAttribute(attn_mma, cudaFuncAttributeMaxDynamicSharedMemorySize, ATTN_SMEM);
    cudaFuncSetAttribute(gemm_mma, cudaFuncAttributeMaxDynamicSharedMemorySize, GT_SMEM);

    dim3 tb(32, 8), tg(32, 32);
    transpose_kernel<<<tg, tb>>>(Wq, wqt);
    transpose_kernel<<<tg, tb>>>(Wk, wkt);
    transpose_kernel<<<tg, tb>>>(Wv, wvt);
    transpose_kernel<<<tg, tb>>>(Wo, wot);

    round_kernel<<<BATCH * NKV * KDIM / 4 / 256, 256>>>(key_t, kin);
    round_kernel<<<BATCH * NKV * KDIM / 4 / 256, 256>>>(value, vin);
    maskbit_kernel<<<BATCH * 32 * NQ / 256, 256>>>(mask, mb);

    ln_kernel<<<BATCH * NQ, 256>>>(x, gamma, beta, xn);

    gemm_mma<<<dim3(8, 32), 256, GT_SMEM>>>(xn,  wqt, q, 1);
    gemm_mma<<<dim3(8, 64), 256, GT_SMEM>>>(kin, wkt, k, 1);
    gemm_mma<<<dim3(8, 64), 256, GT_SMEM>>>(vin, wvt, v, 1);

    attn_mma<<<dim3(NQ / QTILE, HEADS, BATCH), 256, ATTN_SMEM>>>(q, k, v, mb, ctx);

    gemm_mma<<<dim3(8, 32), 256, GT_SMEM>>>(ctx, wot, out, 0);
}

// round 10
// speedup vs baseline: 3.5361x; 1.0433x over previous
#include <cuda_runtime.h>
#include <cuda_bf16.h>
#include <math.h>
#include <cstdint>

#define BATCH  4
#define NQ     1024
#define NKV    2048
#define DMODEL 1024
#define HEADS  16
#define DH     64
#define INNER  1024
#define KDIM   1024

// ---------------- scratch (no allocation allowed) ----------------
__device__ float g_xn [BATCH * NQ  * DMODEL];
__device__ float g_q  [BATCH * NQ  * INNER];
__device__ float g_k  [BATCH * NKV * INNER];
__device__ float g_v  [BATCH * NKV * INNER];
__device__ float g_ctx[BATCH * NQ  * INNER];
__device__ float g_wqt[KDIM * INNER];
__device__ float g_wkt[KDIM * INNER];
__device__ float g_wvt[KDIM * INNER];
__device__ float g_wot[KDIM * INNER];
__device__ float g_kin[BATCH * NKV * KDIM];
__device__ float g_vin[BATCH * NKV * KDIM];
__device__ unsigned long long g_mb[BATCH * 32 * NQ];   // [b][kvblock][q] bitmask

__device__ __forceinline__ uint32_t f2tf(float f) {
    uint32_t r;
    asm("cvt.rna.tf32.f32 %0, %1;" : "=r"(r) : "f"(f));
    return r;
}
__device__ __forceinline__ float f2tf_f(float f) { return __uint_as_float(f2tf(f)); }

__device__ __forceinline__ uint32_t smem_to_u32(const void* p) {
    uint32_t a;
    asm("{ .reg .u64 t; cvta.to.shared.u64 t, %1; cvt.u32.u64 %0, t; }" : "=r"(a) : "l"(p));
    return a;
}
__device__ __forceinline__ void cp_async16(uint32_t saddr, const void* g) {
    asm volatile("cp.async.cg.shared.global [%0], [%1], 16;" :: "r"(saddr), "l"(g));
}
#define CP_COMMIT() asm volatile("cp.async.commit_group;")
#define CP_WAIT(n)  asm volatile("cp.async.wait_group %0;" :: "n"(n) : "memory")

#define MMA_TF32(acc, a0, a1, a2, a3, b0, b1) \
    asm volatile( \
        "mma.sync.aligned.m16n8k8.row.col.f32.tf32.tf32.f32 " \
        "{%0,%1,%2,%3}, {%4,%5,%6,%7}, {%8,%9}, {%0,%1,%2,%3};" \
        : "+f"((acc)[0]), "+f"((acc)[1]), "+f"((acc)[2]), "+f"((acc)[3]) \
        : "r"(a0), "r"(a1), "r"(a2), "r"(a3), "r"(b0), "r"(b1))

// ldmatrix x4: 4 8x8 b16 matrices == one 16x8 tf32 A-frag or two 8x8-pair B-frags
#define LDSM_X4(r, addr) \
    asm volatile("ldmatrix.sync.aligned.m8n8.x4.shared.b16 {%0,%1,%2,%3}, [%4];" \
        : "=r"((r)[0]), "=r"((r)[1]), "=r"((r)[2]), "=r"((r)[3]) : "r"(addr))

// ---------------- elementwise round to tf32 ----------------
__global__ void round_kernel(const float* __restrict__ src, float* __restrict__ dst) {
    int i = blockIdx.x * 256 + threadIdx.x;
    float4 v = ((const float4*)src)[i];
    ((float4*)dst)[i] = make_float4(f2tf_f(v.x), f2tf_f(v.y), f2tf_f(v.z), f2tf_f(v.w));
}

// ---------------- mask int32 -> 1 bit, layout [b][kvblock t][q] ----------------
__global__ void maskbit_kernel(const int* __restrict__ src, unsigned long long* __restrict__ dst) {
    int idx = blockIdx.x * 256 + threadIdx.x;   // 131072 total
    int b = idx >> 15;
    int t = (idx >> 10) & 31;
    int q = idx & 1023;
    const int4* p = (const int4*)(src + (((size_t)b * NQ + q) * NKV + t * 64));
    unsigned long long bits = 0ull;
#pragma unroll
    for (int j = 0; j < 16; j++) {
        int4 v = p[j];
        bits |= (unsigned long long)(v.x != 0) << (4 * j);
        bits |= (unsigned long long)(v.y != 0) << (4 * j + 1);
        bits |= (unsigned long long)(v.z != 0) << (4 * j + 2);
        bits |= (unsigned long long)(v.w != 0) << (4 * j + 3);
    }
    dst[idx] = bits;
}

// ---------------- weight transpose (rounded): dst[n][k] = tf32(src[k][n]) ------
__global__ void transpose_kernel(const float* __restrict__ src, float* __restrict__ dst) {
    __shared__ float t[32][33];
    int bx = blockIdx.x * 32, by = blockIdx.y * 32;
    int x = threadIdx.x, y = threadIdx.y;   // 32 x 8
#pragma unroll
    for (int i = 0; i < 32; i += 8)
        t[y + i][x] = src[(size_t)(by + y + i) * KDIM + bx + x];
    __syncthreads();
#pragma unroll
    for (int i = 0; i < 32; i += 8)
        dst[(size_t)(bx + y + i) * KDIM + by + x] = f2tf_f(t[x][y + i]);
}

// ---------------- LayerNorm (tf32-rounded output) ----------------
__global__ void ln_kernel(const float* __restrict__ x,
                          const float* __restrict__ gamma,
                          const float* __restrict__ beta,
                          float* __restrict__ y) {
    __shared__ float red[16];
    int row = blockIdx.x;
    int tid = threadIdx.x;
    const float4* xr = (const float4*)(x + (size_t)row * DMODEL);
    float4 a = xr[tid];
    float s = a.x + a.y + a.z + a.w;
    float q = a.x * a.x + a.y * a.y + a.z * a.z + a.w * a.w;
#pragma unroll
    for (int off = 16; off; off >>= 1) {
        s += __shfl_xor_sync(0xffffffffu, s, off);
        q += __shfl_xor_sync(0xffffffffu, q, off);
    }
    if ((tid & 31) == 0) { red[tid >> 5] = s; red[8 + (tid >> 5)] = q; }
    __syncthreads();
    if (tid < 32) {
        float ss = (tid < 8) ? red[tid] : 0.f;
        float qq = (tid < 8) ? red[8 + tid] : 0.f;
#pragma unroll
        for (int off = 4; off; off >>= 1) {
            ss += __shfl_xor_sync(0xffffffffu, ss, off);
            qq += __shfl_xor_sync(0xffffffffu, qq, off);
        }
        if (tid == 0) { red[0] = ss; red[1] = qq; }
    }
    __syncthreads();
    float mu  = red[0] * (1.f / DMODEL);
    float var = red[1] * (1.f / DMODEL) - mu * mu;
    float inv = rsqrtf(var + 1e-5f);
    float4 g = ((const float4*)gamma)[tid];
    float4 b = ((const float4*)beta)[tid];
    float4 o;
    o.x = f2tf_f((a.x - mu) * inv * g.x + b.x);
    o.y = f2tf_f((a.y - mu) * inv * g.y + b.y);
    o.z = f2tf_f((a.z - mu) * inv * g.z + b.z);
    o.w = f2tf_f((a.w - mu) * inv * g.w + b.w);
    ((float4*)(y + (size_t)row * DMODEL))[tid] = o;
}

// ---------------- tf32 mma GEMM (cp.async + ldmatrix) -------------------------
#define GPAD 36
#define GBUF (128 * GPAD)
#define GT_SMEM (4 * GBUF * 4)

__global__ void __launch_bounds__(256, 2)
gemm_mma(const float* __restrict__ A, const float* __restrict__ Bt,
         float* __restrict__ C, int round_out) {
    extern __shared__ uint32_t smw[];
    uint32_t sb = smem_to_u32(smw);
    int tid = threadIdx.x, lane = tid & 31, wid = tid >> 5;
    int wm = (wid & 3) * 32, wn = (wid >> 2) * 64;
    int mrow = lane & 7, msel = lane >> 3;

    // ldmatrix per-thread word offsets (A-pattern / B-pattern)
    uint32_t aoffw = (uint32_t)((wm + (msel & 1) * 8 + mrow) * GPAD + (msel >> 1) * 4);
    uint32_t boffw = (uint32_t)((wn + (msel >> 1) * 8 + mrow) * GPAD + (msel & 1) * 4);

    const float* Ab = A  + (size_t)(blockIdx.y * 128) * KDIM;
    const float* Bb = Bt + (size_t)(blockIdx.x * 128) * KDIM;

    float acc[2][8][4] = {};

#define G_ISSUE(it, bf) do { \
    uint32_t abase = sb + (bf) * (GBUF * 4); \
    uint32_t bbase = sb + (2 + (bf)) * (GBUF * 4); \
    _Pragma("unroll") \
    for (int i = 0; i < 4; i++) { \
        int idx = tid + i * 256; int rr = idx >> 3, qq = idx & 7; \
        cp_async16(abase + (rr * GPAD + qq * 4) * 4, Ab + (size_t)rr * KDIM + (it) * 32 + qq * 4); \
        cp_async16(bbase + (rr * GPAD + qq * 4) * 4, Bb + (size_t)rr * KDIM + (it) * 32 + qq * 4); \
    } \
    CP_COMMIT(); \
} while (0)

    G_ISSUE(0, 0);

    for (int it = 0; it < 32; it++) {
        int buf = it & 1;
        if (it < 31) { G_ISSUE(it + 1, buf ^ 1); CP_WAIT(1); }
        else         { CP_WAIT(0); }
        __syncthreads();

        uint32_t aaddr = sb + buf * (GBUF * 4) + aoffw * 4;
        uint32_t baddr = sb + (2 + buf) * (GBUF * 4) + boffw * 4;
#pragma unroll
        for (int ks = 0; ks < 4; ks++) {
            uint32_t afr[2][4];
            LDSM_X4(afr[0], aaddr + ks * 32);
            LDSM_X4(afr[1], aaddr + 16 * GPAD * 4 + ks * 32);
#pragma unroll
            for (int p = 0; p < 4; p++) {
                uint32_t bfr[4];
                LDSM_X4(bfr, baddr + p * (16 * GPAD * 4) + ks * 32);
#pragma unroll
                for (int sub = 0; sub < 2; sub++) {
                    int nf = 2 * p + sub;
                    uint32_t b0 = bfr[sub * 2], b1 = bfr[sub * 2 + 1];
#pragma unroll
                    for (int mf = 0; mf < 2; mf++)
                        MMA_TF32(acc[mf][nf], afr[mf][0], afr[mf][1], afr[mf][2], afr[mf][3], b0, b1);
                }
            }
        }
        __syncthreads();
    }
#undef G_ISSUE

    float* Cb = C + (size_t)(blockIdx.y * 128) * 1024 + blockIdx.x * 128;
#pragma unroll
    for (int mf = 0; mf < 2; mf++) {
        int row = wm + mf * 16 + (lane >> 2);
#pragma unroll
        for (int nf = 0; nf < 8; nf++) {
            int col = wn + nf * 8 + (lane & 3) * 2;
            float2 w0 = make_float2(acc[mf][nf][0], acc[mf][nf][1]);
            float2 w1 = make_float2(acc[mf][nf][2], acc[mf][nf][3]);
            if (round_out) {
                w0.x = f2tf_f(w0.x); w0.y = f2tf_f(w0.y);
                w1.x = f2tf_f(w1.x); w1.y = f2tf_f(w1.y);
            }
            *(float2*)(Cb + (size_t)row * 1024 + col) = w0;
            *(float2*)(Cb + (size_t)(row + 8) * 1024 + col) = w1;
        }
    }
}

// ---------------- tf32 mma flash attention: 256 q x 64 kv, 32-row warps -------
#define APAD 68
#define VPAD 72
#define QTILE 256
#define AQ_W  (QTILE * APAD)
#define AK_W  (64 * APAD)
#define AV_W  (64 * VPAD)
#define PS_W  (AQ_W + 2 * AK_W + 2 * AV_W)
#define MB_BYTE ((PS_W + AQ_W) * 4)
#define ATTN_SMEM (MB_BYTE + 2 * 2048)

__global__ void __launch_bounds__(256, 1)
attn_mma(const float* __restrict__ Q,
         const float* __restrict__ K,
         const float* __restrict__ V,
         const unsigned long long* __restrict__ mbits,
         float* __restrict__ ctx) {
    extern __shared__ uint32_t sw[];
    uint32_t sb = smem_to_u32(sw);

    int tid = threadIdx.x, lane = tid & 31, wid = tid >> 5;
    int b = blockIdx.z, h = blockIdx.y, qt = blockIdx.x;
    const int g = lane >> 2, t4 = lane & 3;
    const int wm = wid * 32;
    const int mrow = lane & 7, msel = lane >> 3;

    // ldmatrix per-thread byte offsets
    const uint32_t qa0 = sb + (uint32_t)((wm + (msel & 1) * 8 + mrow) * APAD + (msel >> 1) * 4) * 4;
    const uint32_t qa1 = qa0 + 16 * APAD * 4;
    const uint32_t kboffB = (uint32_t)(((msel >> 1) * 8 + mrow) * APAD + (msel & 1) * 4) * 4;
    const uint32_t pa0 = sb + PS_W * 4 +
        (uint32_t)((wm + (msel & 1) * 8 + mrow) * APAD + (msel >> 1) * 4) * 4;
    const uint32_t pa1 = pa0 + 16 * APAD * 4;

    const float* Qb = Q + ((size_t)b * NQ + qt * QTILE) * INNER + h * DH;
    const float* Kb = K + (size_t)b * NKV * INNER + h * DH;
    const float* Vb = V + (size_t)b * NKV * INNER + h * DH;
    const char* Mb8 = (const char*)(mbits + (size_t)b * 32 * NQ) + (size_t)qt * QTILE * 8;

    // issue Q tile (group 0): 256 rows x 64 cols
#pragma unroll
    for (int i = 0; i < 16; i++) {
        int idx = tid + i * 256;
        int r = idx >> 4, c4 = (idx & 15) * 4;
        cp_async16(sb + (r * APAD + c4) * 4, Qb + (size_t)r * INNER + c4);
    }
    CP_COMMIT();

#define A_ISSUE(t, bf) do { \
    uint32_t kb_ = sb + (AQ_W + (bf) * AK_W) * 4; \
    uint32_t vb_ = sb + (AQ_W + 2 * AK_W + (bf) * AV_W) * 4; \
    uint32_t mb_ = sb + MB_BYTE + (bf) * 2048; \
    _Pragma("unroll") \
    for (int i = 0; i < 4; i++) { \
        int idx = tid + i * 256; int r = idx >> 4, c4 = (idx & 15) * 4; \
        cp_async16(kb_ + (r * APAD + c4) * 4, Kb + (size_t)((t) * 64 + r) * INNER + c4); \
        cp_async16(vb_ + (r * VPAD + c4) * 4, Vb + (size_t)((t) * 64 + r) * INNER + c4); \
    } \
    if (tid < 128) cp_async16(mb_ + tid * 16, Mb8 + (size_t)(t) * NQ * 8 + tid * 16); \
    CP_COMMIT(); \
} while (0)

    A_ISSUE(0, 0);

    float oacc[2][8][4] = {};
    float mrun[4], lrun[4];
#pragma unroll
    for (int i = 0; i < 4; i++) { mrun[i] = -3.402823466e38f; lrun[i] = 0.f; }
    const float scl = 0.125f;

    uint32_t* Ps = sw + PS_W;

    for (int t = 0; t < NKV / 64; t++) {
        int buf = t & 1;
        if (t < 31) { A_ISSUE(t + 1, buf ^ 1); CP_WAIT(1); }
        else        { CP_WAIT(0); }
        __syncthreads();

        const uint32_t* Vs = sw + AQ_W + 2 * AK_W + buf * AV_W;
        const uint32_t kbase = sb + (AQ_W + buf * AK_W) * 4 + kboffB;
        const unsigned long long* Msk =
            (const unsigned long long*)((const char*)sw + MB_BYTE + buf * 2048);

        // ---- S = Q K^T (warp: 32 x 64) ----
        float sacc[2][8][4] = {};
#pragma unroll
        for (int ks = 0; ks < 8; ks++) {
            uint32_t afr[2][4];
            LDSM_X4(afr[0], qa0 + ks * 32);
            LDSM_X4(afr[1], qa1 + ks * 32);
#pragma unroll
            for (int p = 0; p < 4; p++) {
                uint32_t bfr[4];
                LDSM_X4(bfr, kbase + p * (16 * APAD * 4) + ks * 32);
#pragma unroll
                for (int sub = 0; sub < 2; sub++) {
                    int nf = 2 * p + sub;
                    uint32_t b0 = bfr[sub * 2], b1 = bfr[sub * 2 + 1];
#pragma unroll
                    for (int mf = 0; mf < 2; mf++)
                        MMA_TF32(sacc[mf][nf], afr[mf][0], afr[mf][1], afr[mf][2], afr[mf][3], b0, b1);
                }
            }
        }

        // ---- mask + scale + online softmax (4 q-rows per thread) ----
        unsigned long long mbm[4];
        mbm[0] = Msk[wm + g];
        mbm[1] = Msk[wm + g + 8];
        mbm[2] = Msk[wm + g + 16];
        mbm[3] = Msk[wm + g + 24];
        int sh0 = t4 * 2;

        float tm[4];
#pragma unroll
        for (int i = 0; i < 4; i++) tm[i] = -3.402823466e38f;
#pragma unroll
        for (int mf = 0; mf < 2; mf++) {
            unsigned long long mlo = mbm[2 * mf], mhi = mbm[2 * mf + 1];
#pragma unroll
            for (int nf = 0; nf < 8; nf++) {
                int shn = nf * 8 + sh0;
                float s0 = sacc[mf][nf][0] * scl, s1 = sacc[mf][nf][1] * scl;
                float s2 = sacc[mf][nf][2] * scl, s3 = sacc[mf][nf][3] * scl;
                if ((mlo >> shn) & 1)       s0 = -3.402823466e38f;
                if ((mlo >> (shn + 1)) & 1) s1 = -3.402823466e38f;
                if ((mhi >> shn) & 1)       s2 = -3.402823466e38f;
                if ((mhi >> (shn + 1)) & 1) s3 = -3.402823466e38f;
                sacc[mf][nf][0] = s0; sacc[mf][nf][1] = s1;
                sacc[mf][nf][2] = s2; sacc[mf][nf][3] = s3;
                tm[2 * mf]     = fmaxf(tm[2 * mf], fmaxf(s0, s1));
                tm[2 * mf + 1] = fmaxf(tm[2 * mf + 1], fmaxf(s2, s3));
            }
        }
        float corr[4], mn[4];
#pragma unroll
        for (int i = 0; i < 4; i++) {
            tm[i] = fmaxf(tm[i], __shfl_xor_sync(0xffffffffu, tm[i], 1));
            tm[i] = fmaxf(tm[i], __shfl_xor_sync(0xffffffffu, tm[i], 2));
            mn[i] = fmaxf(mrun[i], tm[i]);
            corr[i] = __expf(mrun[i] - mn[i]);
            mrun[i] = mn[i];
        }
        float ls[4] = {0.f, 0.f, 0.f, 0.f};
#pragma unroll
        for (int mf = 0; mf < 2; mf++) {
#pragma unroll
            for (int nf = 0; nf < 8; nf++) {
                int c = nf * 8 + sh0;
                float p0 = __expf(sacc[mf][nf][0] - mn[2 * mf]);
                float p1 = __expf(sacc[mf][nf][1] - mn[2 * mf]);
                float p2 = __expf(sacc[mf][nf][2] - mn[2 * mf + 1]);
                float p3 = __expf(sacc[mf][nf][3] - mn[2 * mf + 1]);
                ls[2 * mf]     += p0 + p1;
                ls[2 * mf + 1] += p2 + p3;
                int row = wm + mf * 16 + g;
                *(uint2*)&Ps[row * APAD + c]       = make_uint2(f2tf(p0), f2tf(p1));
                *(uint2*)&Ps[(row + 8) * APAD + c] = make_uint2(f2tf(p2), f2tf(p3));
            }
        }
#pragma unroll
        for (int i = 0; i < 4; i++) {
            ls[i] += __shfl_xor_sync(0xffffffffu, ls[i], 1);
            ls[i] += __shfl_xor_sync(0xffffffffu, ls[i], 2);
            lrun[i] = lrun[i] * corr[i] + ls[i];
        }
#pragma unroll
        for (int mf = 0; mf < 2; mf++)
#pragma unroll
            for (int nf = 0; nf < 8; nf++) {
                oacc[mf][nf][0] *= corr[2 * mf];     oacc[mf][nf][1] *= corr[2 * mf];
                oacc[mf][nf][2] *= corr[2 * mf + 1]; oacc[mf][nf][3] *= corr[2 * mf + 1];
            }
        __syncwarp();

        // ---- O += P V ----
#pragma unroll
        for (int ks = 0; ks < 8; ks++) {
            uint32_t afr[2][4];
            LDSM_X4(afr[0], pa0 + ks * 32);
            LDSM_X4(afr[1], pa1 + ks * 32);
            int kb = ks * 8 + t4;
#pragma unroll
            for (int nf = 0; nf < 8; nf++) {
                int n = nf * 8 + g;
                uint32_t b0 = Vs[kb * VPAD + n];
                uint32_t b1 = Vs[(kb + 4) * VPAD + n];
#pragma unroll
                for (int mf = 0; mf < 2; mf++)
                    MMA_TF32(oacc[mf][nf], afr[mf][0], afr[mf][1], afr[mf][2], afr[mf][3], b0, b1);
            }
        }
        __syncthreads();
    }
#undef A_ISSUE

    // epilogue: write ctx tf32-rounded
    float inv[4];
#pragma unroll
    for (int i = 0; i < 4; i++) inv[i] = __fdividef(1.f, lrun[i]);
#pragma unroll
    for (int mf = 0; mf < 2; mf++) {
        size_t row = (size_t)b * NQ + qt * QTILE + wm + mf * 16 + g;
        float* o1 = ctx + row * INNER + h * DH;
        float* o2 = o1 + (size_t)8 * INNER;
#pragma unroll
        for (int nf = 0; nf < 8; nf++) {
            int c = nf * 8 + t4 * 2;
            *(float2*)(o1 + c) = make_float2(f2tf_f(oacc[mf][nf][0] * inv[2 * mf]),
                                             f2tf_f(oacc[mf][nf][1] * inv[2 * mf]));
            *(float2*)(o2 + c) = make_float2(f2tf_f(oacc[mf][nf][2] * inv[2 * mf + 1]),
                                             f2tf_f(oacc[mf][nf][3] * inv[2 * mf + 1]));
        }
    }
}

// ---------------- launcher ----------------
extern "C" void kernel_launch(void* const* d_in, const int* in_sizes, int n_in,
                              void* d_out, int out_size) {
    const float* x     = (const float*)d_in[0];
    const float* key_t = (const float*)d_in[1];
    const float* value = (const float*)d_in[2];
    const int*   mask  = (const int*)d_in[3];
    const float* Wq    = (const float*)d_in[4];
    const float* Wk    = (const float*)d_in[5];
    const float* Wv    = (const float*)d_in[6];
    const float* Wo    = (const float*)d_in[7];
    const float* gamma = (const float*)d_in[8];
    const float* beta  = (const float*)d_in[9];
    float* out = (float*)d_out;

    float *xn, *q, *k, *v, *ctx, *wqt, *wkt, *wvt, *wot, *kin, *vin;
    unsigned long long* mb;
    cudaGetSymbolAddress((void**)&xn,  g_xn);
    cudaGetSymbolAddress((void**)&q,   g_q);
    cudaGetSymbolAddress((void**)&k,   g_k);
    cudaGetSymbolAddress((void**)&v,   g_v);
    cudaGetSymbolAddress((void**)&ctx, g_ctx);
    cudaGetSymbolAddress((void**)&wqt, g_wqt);
    cudaGetSymbolAddress((void**)&wkt, g_wkt);
    cudaGetSymbolAddress((void**)&wvt, g_wvt);
    cudaGetSymbolAddress((void**)&wot, g_wot);
    cudaGetSymbolAddress((void**)&kin, g_kin);
    cudaGetSymbolAddress((void**)&vin, g_vin);
    cudaGetSymbolAddress((void**)&mb,  g_mb);

    cudaFuncSetAttribute(attn_mma, cudaFuncAttributeMaxDynamicSharedMemorySize, ATTN_SMEM);
    cudaFuncSetAttribute(gemm_mma, cudaFuncAttributeMaxDynamicSharedMemorySize, GT_SMEM);

    dim3 tb(32, 8), tg(32, 32);
    transpose_kernel<<<tg, tb>>>(Wq, wqt);
    transpose_kernel<<<tg, tb>>>(Wk, wkt);
    transpose_kernel<<<tg, tb>>>(Wv, wvt);
    transpose_kernel<<<tg, tb>>>(Wo, wot);

    round_kernel<<<BATCH * NKV * KDIM / 4 / 256, 256>>>(key_t, kin);
    round_kernel<<<BATCH * NKV * KDIM / 4 / 256, 256>>>(value, vin);
    maskbit_kernel<<<BATCH * 32 * NQ / 256, 256>>>(mask, mb);

    ln_kernel<<<BATCH * NQ, 256>>>(x, gamma, beta, xn);

    gemm_mma<<<dim3(8, 32), 256, GT_SMEM>>>(xn,  wqt, q, 1);
    gemm_mma<<<dim3(8, 64), 256, GT_SMEM>>>(kin, wkt, k, 1);
    gemm_mma<<<dim3(8, 64), 256, GT_SMEM>>>(vin, wvt, v, 1);

    attn_mma<<<dim3(NQ / QTILE, HEADS, BATCH), 256, ATTN_SMEM>>>(q, k, v, mb, ctx);

    gemm_mma<<<dim3(8, 32), 256, GT_SMEM>>>(ctx, wot, out, 0);
}

// round 11
// speedup vs baseline: 3.6375x; 1.0287x over previous
#include <cuda_runtime.h>
#include <cuda_bf16.h>
#include <math.h>
#include <cstdint>

#define BATCH  4
#define NQ     1024
#define NKV    2048
#define DMODEL 1024
#define HEADS  16
#define DH     64
#define INNER  1024
#define KDIM   1024

// ---------------- scratch (no allocation allowed) ----------------
__device__ float g_xn [BATCH * NQ  * DMODEL];
__device__ float g_q  [BATCH * NQ  * INNER];
__device__ float g_k  [BATCH * NKV * INNER];
__device__ float g_v  [BATCH * NKV * INNER];
__device__ float g_ctx[BATCH * NQ  * INNER];
__device__ float g_wqt[KDIM * INNER];
__device__ float g_wkt[KDIM * INNER];
__device__ float g_wvt[KDIM * INNER];
__device__ float g_wot[KDIM * INNER];
__device__ float g_kin[BATCH * NKV * KDIM];
__device__ float g_vin[BATCH * NKV * KDIM];
__device__ unsigned long long g_mb[BATCH * 32 * NQ];   // [b][kvblock][q] bitmask

__device__ __forceinline__ uint32_t f2tf(float f) {
    uint32_t r;
    asm("cvt.rna.tf32.f32 %0, %1;" : "=r"(r) : "f"(f));
    return r;
}
__device__ __forceinline__ float f2tf_f(float f) { return __uint_as_float(f2tf(f)); }

__device__ __forceinline__ uint32_t smem_to_u32(const void* p) {
    uint32_t a;
    asm("{ .reg .u64 t; cvta.to.shared.u64 t, %1; cvt.u32.u64 %0, t; }" : "=r"(a) : "l"(p));
    return a;
}
__device__ __forceinline__ void cp_async16(uint32_t saddr, const void* g) {
    asm volatile("cp.async.cg.shared.global [%0], [%1], 16;" :: "r"(saddr), "l"(g));
}
#define CP_COMMIT() asm volatile("cp.async.commit_group;")
#define CP_WAIT(n)  asm volatile("cp.async.wait_group %0;" :: "n"(n) : "memory")

#define MMA_TF32(acc, a0, a1, a2, a3, b0, b1) \
    asm volatile( \
        "mma.sync.aligned.m16n8k8.row.col.f32.tf32.tf32.f32 " \
        "{%0,%1,%2,%3}, {%4,%5,%6,%7}, {%8,%9}, {%0,%1,%2,%3};" \
        : "+f"((acc)[0]), "+f"((acc)[1]), "+f"((acc)[2]), "+f"((acc)[3]) \
        : "r"(a0), "r"(a1), "r"(a2), "r"(a3), "r"(b0), "r"(b1))

#define LDSM_X4(r, addr) \
    asm volatile("ldmatrix.sync.aligned.m8n8.x4.shared.b16 {%0,%1,%2,%3}, [%4];" \
        : "=r"((r)[0]), "=r"((r)[1]), "=r"((r)[2]), "=r"((r)[3]) : "r"(addr))

// ---------------- fused elementwise round to tf32 (key_t + value) -------------
__global__ void round_all_kernel(const float* __restrict__ s0, float* __restrict__ d0,
                                 const float* __restrict__ s1, float* __restrict__ d1,
                                 int half_blocks) {
    int bx = blockIdx.x;
    const float* src = (bx < half_blocks) ? s0 : s1;
    float* dst       = (bx < half_blocks) ? d0 : d1;
    int i = (bx < half_blocks ? bx : bx - half_blocks) * 256 + threadIdx.x;
    float4 v = ((const float4*)src)[i];
    ((float4*)dst)[i] = make_float4(f2tf_f(v.x), f2tf_f(v.y), f2tf_f(v.z), f2tf_f(v.w));
}

// ---------------- mask int32 -> 1 bit, layout [b][kvblock t][q] ----------------
__global__ void maskbit_kernel(const int* __restrict__ src, unsigned long long* __restrict__ dst) {
    int idx = blockIdx.x * 256 + threadIdx.x;   // 131072 total
    int b = idx >> 15;
    int t = (idx >> 10) & 31;
    int q = idx & 1023;
    const int4* p = (const int4*)(src + (((size_t)b * NQ + q) * NKV + t * 64));
    unsigned long long bits = 0ull;
#pragma unroll
    for (int j = 0; j < 16; j++) {
        int4 v = p[j];
        bits |= (unsigned long long)(v.x != 0) << (4 * j);
        bits |= (unsigned long long)(v.y != 0) << (4 * j + 1);
        bits |= (unsigned long long)(v.z != 0) << (4 * j + 2);
        bits |= (unsigned long long)(v.w != 0) << (4 * j + 3);
    }
    dst[idx] = bits;
}

// ---------------- fused weight transpose x4 (rounded) --------------------------
__global__ void transpose_all_kernel(const float* __restrict__ w0, float* __restrict__ d0,
                                     const float* __restrict__ w1, float* __restrict__ d1,
                                     const float* __restrict__ w2, float* __restrict__ d2,
                                     const float* __restrict__ w3, float* __restrict__ d3) {
    __shared__ float t[32][33];
    const float* src = (blockIdx.z == 0) ? w0 : (blockIdx.z == 1) ? w1 : (blockIdx.z == 2) ? w2 : w3;
    float* dst       = (blockIdx.z == 0) ? d0 : (blockIdx.z == 1) ? d1 : (blockIdx.z == 2) ? d2 : d3;
    int bx = blockIdx.x * 32, by = blockIdx.y * 32;
    int x = threadIdx.x, y = threadIdx.y;   // 32 x 8
#pragma unroll
    for (int i = 0; i < 32; i += 8)
        t[y + i][x] = src[(size_t)(by + y + i) * KDIM + bx + x];
    __syncthreads();
#pragma unroll
    for (int i = 0; i < 32; i += 8)
        dst[(size_t)(bx + y + i) * KDIM + by + x] = f2tf_f(t[x][y + i]);
}

// ---------------- LayerNorm (tf32-rounded output) ----------------
__global__ void ln_kernel(const float* __restrict__ x,
                          const float* __restrict__ gamma,
                          const float* __restrict__ beta,
                          float* __restrict__ y) {
    __shared__ float red[16];
    int row = blockIdx.x;
    int tid = threadIdx.x;
    const float4* xr = (const float4*)(x + (size_t)row * DMODEL);
    float4 a = xr[tid];
    float s = a.x + a.y + a.z + a.w;
    float q = a.x * a.x + a.y * a.y + a.z * a.z + a.w * a.w;
#pragma unroll
    for (int off = 16; off; off >>= 1) {
        s += __shfl_xor_sync(0xffffffffu, s, off);
        q += __shfl_xor_sync(0xffffffffu, q, off);
    }
    if ((tid & 31) == 0) { red[tid >> 5] = s; red[8 + (tid >> 5)] = q; }
    __syncthreads();
    if (tid < 32) {
        float ss = (tid < 8) ? red[tid] : 0.f;
        float qq = (tid < 8) ? red[8 + tid] : 0.f;
#pragma unroll
        for (int off = 4; off; off >>= 1) {
            ss += __shfl_xor_sync(0xffffffffu, ss, off);
            qq += __shfl_xor_sync(0xffffffffu, qq, off);
        }
        if (tid == 0) { red[0] = ss; red[1] = qq; }
    }
    __syncthreads();
    float mu  = red[0] * (1.f / DMODEL);
    float var = red[1] * (1.f / DMODEL) - mu * mu;
    float inv = rsqrtf(var + 1e-5f);
    float4 g = ((const float4*)gamma)[tid];
    float4 b = ((const float4*)beta)[tid];
    float4 o;
    o.x = f2tf_f((a.x - mu) * inv * g.x + b.x);
    o.y = f2tf_f((a.y - mu) * inv * g.y + b.y);
    o.z = f2tf_f((a.z - mu) * inv * g.z + b.z);
    o.w = f2tf_f((a.w - mu) * inv * g.w + b.w);
    ((float4*)(y + (size_t)row * DMODEL))[tid] = o;
}

// ---------------- tf32 mma GEMM (cp.async, single-sync pipeline) --------------
#define GPAD 36
#define GBUF (128 * GPAD)
#define GT_SMEM (4 * GBUF * 4)

__global__ void __launch_bounds__(256, 2)
gemm_mma(const float* __restrict__ A, const float* __restrict__ Bt,
         float* __restrict__ C, int round_out) {
    extern __shared__ uint32_t smw[];
    uint32_t sb = smem_to_u32(smw);
    int tid = threadIdx.x, lane = tid & 31, wid = tid >> 5;
    int wm = (wid & 3) * 32, wn = (wid >> 2) * 64;
    int mrow = lane & 7, msel = lane >> 3;

    uint32_t aoffw = (uint32_t)((wm + (msel & 1) * 8 + mrow) * GPAD + (msel >> 1) * 4);
    uint32_t boffw = (uint32_t)((wn + (msel >> 1) * 8 + mrow) * GPAD + (msel & 1) * 4);

    const float* Ab = A  + (size_t)(blockIdx.y * 128) * KDIM;
    const float* Bb = Bt + (size_t)(blockIdx.x * 128) * KDIM;

    float acc[2][8][4] = {};

#define G_ISSUE(it, bf) do { \
    uint32_t abase = sb + (bf) * (GBUF * 4); \
    uint32_t bbase = sb + (2 + (bf)) * (GBUF * 4); \
    _Pragma("unroll") \
    for (int i = 0; i < 4; i++) { \
        int idx = tid + i * 256; int rr = idx >> 3, qq = idx & 7; \
        cp_async16(abase + (rr * GPAD + qq * 4) * 4, Ab + (size_t)rr * KDIM + (it) * 32 + qq * 4); \
        cp_async16(bbase + (rr * GPAD + qq * 4) * 4, Bb + (size_t)rr * KDIM + (it) * 32 + qq * 4); \
    } \
    CP_COMMIT(); \
} while (0)

    G_ISSUE(0, 0);

    for (int it = 0; it < 32; it++) {
        int buf = it & 1;
        CP_WAIT(0);
        __syncthreads();              // all warps done reading buf^1; data for buf visible
        if (it < 31) G_ISSUE(it + 1, buf ^ 1);   // overlaps with compute below

        uint32_t aaddr = sb + buf * (GBUF * 4) + aoffw * 4;
        uint32_t baddr = sb + (2 + buf) * (GBUF * 4) + boffw * 4;
#pragma unroll
        for (int ks = 0; ks < 4; ks++) {
            uint32_t afr[2][4];
            LDSM_X4(afr[0], aaddr + ks * 32);
            LDSM_X4(afr[1], aaddr + 16 * GPAD * 4 + ks * 32);
#pragma unroll
            for (int p = 0; p < 4; p++) {
                uint32_t bfr[4];
                LDSM_X4(bfr, baddr + p * (16 * GPAD * 4) + ks * 32);
#pragma unroll
                for (int sub = 0; sub < 2; sub++) {
                    int nf = 2 * p + sub;
                    uint32_t b0 = bfr[sub * 2], b1 = bfr[sub * 2 + 1];
#pragma unroll
                    for (int mf = 0; mf < 2; mf++)
                        MMA_TF32(acc[mf][nf], afr[mf][0], afr[mf][1], afr[mf][2], afr[mf][3], b0, b1);
                }
            }
        }
    }
#undef G_ISSUE

    float* Cb = C + (size_t)(blockIdx.y * 128) * 1024 + blockIdx.x * 128;
#pragma unroll
    for (int mf = 0; mf < 2; mf++) {
        int row = wm + mf * 16 + (lane >> 2);
#pragma unroll
        for (int nf = 0; nf < 8; nf++) {
            int col = wn + nf * 8 + (lane & 3) * 2;
            float2 w0 = make_float2(acc[mf][nf][0], acc[mf][nf][1]);
            float2 w1 = make_float2(acc[mf][nf][2], acc[mf][nf][3]);
            if (round_out) {
                w0.x = f2tf_f(w0.x); w0.y = f2tf_f(w0.y);
                w1.x = f2tf_f(w1.x); w1.y = f2tf_f(w1.y);
            }
            *(float2*)(Cb + (size_t)row * 1024 + col) = w0;
            *(float2*)(Cb + (size_t)(row + 8) * 1024 + col) = w1;
        }
    }
}

// ---------------- tf32 mma flash attention (single-sync pipeline) -------------
#define APAD 68
#define VPAD 72
#define QTILE 256
#define AQ_W  (QTILE * APAD)
#define AK_W  (64 * APAD)
#define AV_W  (64 * VPAD)
#define PS_W  (AQ_W + 2 * AK_W + 2 * AV_W)
#define MB_BYTE ((PS_W + AQ_W) * 4)
#define ATTN_SMEM (MB_BYTE + 2 * 2048)

__global__ void __launch_bounds__(256, 1)
attn_mma(const float* __restrict__ Q,
         const float* __restrict__ K,
         const float* __restrict__ V,
         const unsigned long long* __restrict__ mbits,
         float* __restrict__ ctx) {
    extern __shared__ uint32_t sw[];
    uint32_t sb = smem_to_u32(sw);

    int tid = threadIdx.x, lane = tid & 31, wid = tid >> 5;
    int b = blockIdx.z, h = blockIdx.y, qt = blockIdx.x;
    const int g = lane >> 2, t4 = lane & 3;
    const int wm = wid * 32;
    const int mrow = lane & 7, msel = lane >> 3;

    const uint32_t qa0 = sb + (uint32_t)((wm + (msel & 1) * 8 + mrow) * APAD + (msel >> 1) * 4) * 4;
    const uint32_t qa1 = qa0 + 16 * APAD * 4;
    const uint32_t kboffB = (uint32_t)(((msel >> 1) * 8 + mrow) * APAD + (msel & 1) * 4) * 4;
    const uint32_t pa0 = sb + PS_W * 4 +
        (uint32_t)((wm + (msel & 1) * 8 + mrow) * APAD + (msel >> 1) * 4) * 4;
    const uint32_t pa1 = pa0 + 16 * APAD * 4;

    const float* Qb = Q + ((size_t)b * NQ + qt * QTILE) * INNER + h * DH;
    const float* Kb = K + (size_t)b * NKV * INNER + h * DH;
    const float* Vb = V + (size_t)b * NKV * INNER + h * DH;
    const char* Mb8 = (const char*)(mbits + (size_t)b * 32 * NQ) + (size_t)qt * QTILE * 8;

#pragma unroll
    for (int i = 0; i < 16; i++) {
        int idx = tid + i * 256;
        int r = idx >> 4, c4 = (idx & 15) * 4;
        cp_async16(sb + (r * APAD + c4) * 4, Qb + (size_t)r * INNER + c4);
    }
    CP_COMMIT();

#define A_ISSUE(t, bf) do { \
    uint32_t kb_ = sb + (AQ_W + (bf) * AK_W) * 4; \
    uint32_t vb_ = sb + (AQ_W + 2 * AK_W + (bf) * AV_W) * 4; \
    uint32_t mb_ = sb + MB_BYTE + (bf) * 2048; \
    _Pragma("unroll") \
    for (int i = 0; i < 4; i++) { \
        int idx = tid + i * 256; int r = idx >> 4, c4 = (idx & 15) * 4; \
        cp_async16(kb_ + (r * APAD + c4) * 4, Kb + (size_t)((t) * 64 + r) * INNER + c4); \
        cp_async16(vb_ + (r * VPAD + c4) * 4, Vb + (size_t)((t) * 64 + r) * INNER + c4); \
    } \
    if (tid < 128) cp_async16(mb_ + tid * 16, Mb8 + (size_t)(t) * NQ * 8 + tid * 16); \
    CP_COMMIT(); \
} while (0)

    A_ISSUE(0, 0);

    float oacc[2][8][4] = {};
    float mrun[4], lrun[4];
#pragma unroll
    for (int i = 0; i < 4; i++) { mrun[i] = -3.402823466e38f; lrun[i] = 0.f; }
    const float scl = 0.125f;

    uint32_t* Ps = sw + PS_W;

    for (int t = 0; t < NKV / 64; t++) {
        int buf = t & 1;
        CP_WAIT(0);
        __syncthreads();              // all warps done with buf^1; data for buf visible
        if (t < 31) A_ISSUE(t + 1, buf ^ 1);   // overlaps with compute below

        const uint32_t* Vs = sw + AQ_W + 2 * AK_W + buf * AV_W;
        const uint32_t kbase = sb + (AQ_W + buf * AK_W) * 4 + kboffB;
        const unsigned long long* Msk =
            (const unsigned long long*)((const char*)sw + MB_BYTE + buf * 2048);

        // ---- S = Q K^T (warp: 32 x 64) ----
        float sacc[2][8][4] = {};
#pragma unroll
        for (int ks = 0; ks < 8; ks++) {
            uint32_t afr[2][4];
            LDSM_X4(afr[0], qa0 + ks * 32);
            LDSM_X4(afr[1], qa1 + ks * 32);
#pragma unroll
            for (int p = 0; p < 4; p++) {
                uint32_t bfr[4];
                LDSM_X4(bfr, kbase + p * (16 * APAD * 4) + ks * 32);
#pragma unroll
                for (int sub = 0; sub < 2; sub++) {
                    int nf = 2 * p + sub;
                    uint32_t b0 = bfr[sub * 2], b1 = bfr[sub * 2 + 1];
#pragma unroll
                    for (int mf = 0; mf < 2; mf++)
                        MMA_TF32(sacc[mf][nf], afr[mf][0], afr[mf][1], afr[mf][2], afr[mf][3], b0, b1);
                }
            }
        }

        // ---- mask + scale + online softmax ----
        unsigned long long mbm[4];
        mbm[0] = Msk[wm + g];
        mbm[1] = Msk[wm + g + 8];
        mbm[2] = Msk[wm + g + 16];
        mbm[3] = Msk[wm + g + 24];
        int sh0 = t4 * 2;

        float tm[4];
#pragma unroll
        for (int i = 0; i < 4; i++) tm[i] = -3.402823466e38f;
#pragma unroll
        for (int mf = 0; mf < 2; mf++) {
            unsigned long long mlo = mbm[2 * mf], mhi = mbm[2 * mf + 1];
#pragma unroll
            for (int nf = 0; nf < 8; nf++) {
                int shn = nf * 8 + sh0;
                float s0 = sacc[mf][nf][0] * scl, s1 = sacc[mf][nf][1] * scl;
                float s2 = sacc[mf][nf][2] * scl, s3 = sacc[mf][nf][3] * scl;
                if ((mlo >> shn) & 1)       s0 = -3.402823466e38f;
                if ((mlo >> (shn + 1)) & 1) s1 = -3.402823466e38f;
                if ((mhi >> shn) & 1)       s2 = -3.402823466e38f;
                if ((mhi >> (shn + 1)) & 1) s3 = -3.402823466e38f;
                sacc[mf][nf][0] = s0; sacc[mf][nf][1] = s1;
                sacc[mf][nf][2] = s2; sacc[mf][nf][3] = s3;
                tm[2 * mf]     = fmaxf(tm[2 * mf], fmaxf(s0, s1));
                tm[2 * mf + 1] = fmaxf(tm[2 * mf + 1], fmaxf(s2, s3));
            }
        }
        float corr[4], mn[4];
#pragma unroll
        for (int i = 0; i < 4; i++) {
            tm[i] = fmaxf(tm[i], __shfl_xor_sync(0xffffffffu, tm[i], 1));
            tm[i] = fmaxf(tm[i], __shfl_xor_sync(0xffffffffu, tm[i], 2));
            mn[i] = fmaxf(mrun[i], tm[i]);
            corr[i] = __expf(mrun[i] - mn[i]);
            mrun[i] = mn[i];
        }
        float ls[4] = {0.f, 0.f, 0.f, 0.f};
#pragma unroll
        for (int mf = 0; mf < 2; mf++) {
#pragma unroll
            for (int nf = 0; nf < 8; nf++) {
                int c = nf * 8 + sh0;
                float p0 = __expf(sacc[mf][nf][0] - mn[2 * mf]);
                float p1 = __expf(sacc[mf][nf][1] - mn[2 * mf]);
                float p2 = __expf(sacc[mf][nf][2] - mn[2 * mf + 1]);
                float p3 = __expf(sacc[mf][nf][3] - mn[2 * mf + 1]);
                ls[2 * mf]     += p0 + p1;
                ls[2 * mf + 1] += p2 + p3;
                int row = wm + mf * 16 + g;
                *(uint2*)&Ps[row * APAD + c]       = make_uint2(f2tf(p0), f2tf(p1));
                *(uint2*)&Ps[(row + 8) * APAD + c] = make_uint2(f2tf(p2), f2tf(p3));
            }
        }
#pragma unroll
        for (int i = 0; i < 4; i++) {
            ls[i] += __shfl_xor_sync(0xffffffffu, ls[i], 1);
            ls[i] += __shfl_xor_sync(0xffffffffu, ls[i], 2);
            lrun[i] = lrun[i] * corr[i] + ls[i];
        }
#pragma unroll
        for (int mf = 0; mf < 2; mf++)
#pragma unroll
            for (int nf = 0; nf < 8; nf++) {
                oacc[mf][nf][0] *= corr[2 * mf];     oacc[mf][nf][1] *= corr[2 * mf];
                oacc[mf][nf][2] *= corr[2 * mf + 1]; oacc[mf][nf][3] *= corr[2 * mf + 1];
            }
        __syncwarp();

        // ---- O += P V ----
#pragma unroll
        for (int ks = 0; ks < 8; ks++) {
            uint32_t afr[2][4];
            LDSM_X4(afr[0], pa0 + ks * 32);
            LDSM_X4(afr[1], pa1 + ks * 32);
            int kb = ks * 8 + t4;
#pragma unroll
            for (int nf = 0; nf < 8; nf++) {
                int n = nf * 8 + g;
                uint32_t b0 = Vs[kb * VPAD + n];
                uint32_t b1 = Vs[(kb + 4) * VPAD + n];
#pragma unroll
                for (int mf = 0; mf < 2; mf++)
                    MMA_TF32(oacc[mf][nf], afr[mf][0], afr[mf][1], afr[mf][2], afr[mf][3], b0, b1);
            }
        }
    }
#undef A_ISSUE

    // epilogue: write ctx tf32-rounded
    float inv[4];
#pragma unroll
    for (int i = 0; i < 4; i++) inv[i] = __fdividef(1.f, lrun[i]);
#pragma unroll
    for (int mf = 0; mf < 2; mf++) {
        size_t row = (size_t)b * NQ + qt * QTILE + wm + mf * 16 + g;
        float* o1 = ctx + row * INNER + h * DH;
        float* o2 = o1 + (size_t)8 * INNER;
#pragma unroll
        for (int nf = 0; nf < 8; nf++) {
            int c = nf * 8 + t4 * 2;
            *(float2*)(o1 + c) = make_float2(f2tf_f(oacc[mf][nf][0] * inv[2 * mf]),
                                             f2tf_f(oacc[mf][nf][1] * inv[2 * mf]));
            *(float2*)(o2 + c) = make_float2(f2tf_f(oacc[mf][nf][2] * inv[2 * mf + 1]),
                                             f2tf_f(oacc[mf][nf][3] * inv[2 * mf + 1]));
        }
    }
}

// ---------------- launcher ----------------
extern "C" void kernel_launch(void* const* d_in, const int* in_sizes, int n_in,
                              void* d_out, int out_size) {
    const float* x     = (const float*)d_in[0];
    const float* key_t = (const float*)d_in[1];
    const float* value = (const float*)d_in[2];
    const int*   mask  = (const int*)d_in[3];
    const float* Wq    = (const float*)d_in[4];
    const float* Wk    = (const float*)d_in[5];
    const float* Wv    = (const float*)d_in[6];
    const float* Wo    = (const float*)d_in[7];
    const float* gamma = (const float*)d_in[8];
    const float* beta  = (const float*)d_in[9];
    float* out = (float*)d_out;

    float *xn, *q, *k, *v, *ctx, *wqt, *wkt, *wvt, *wot, *kin, *vin;
    unsigned long long* mb;
    cudaGetSymbolAddress((void**)&xn,  g_xn);
    cudaGetSymbolAddress((void**)&q,   g_q);
    cudaGetSymbolAddress((void**)&k,   g_k);
    cudaGetSymbolAddress((void**)&v,   g_v);
    cudaGetSymbolAddress((void**)&ctx, g_ctx);
    cudaGetSymbolAddress((void**)&wqt, g_wqt);
    cudaGetSymbolAddress((void**)&wkt, g_wkt);
    cudaGetSymbolAddress((void**)&wvt, g_wvt);
    cudaGetSymbolAddress((void**)&wot, g_wot);
    cudaGetSymbolAddress((void**)&kin, g_kin);
    cudaGetSymbolAddress((void**)&vin, g_vin);
    cudaGetSymbolAddress((void**)&mb,  g_mb);

    cudaFuncSetAttribute(attn_mma, cudaFuncAttributeMaxDynamicSharedMemorySize, ATTN_SMEM);
    cudaFuncSetAttribute(gemm_mma, cudaFuncAttributeMaxDynamicSharedMemorySize, GT_SMEM);

    // prep (4 launches): transpose_all, round_all, maskbit, ln
    transpose_all_kernel<<<dim3(32, 32, 4), dim3(32, 8)>>>(Wq, wqt, Wk, wkt, Wv, wvt, Wo, wot);
    {
        int half = BATCH * NKV * KDIM / 4 / 256;
        round_all_kernel<<<2 * half, 256>>>(key_t, kin, value, vin, half);
    }
    maskbit_kernel<<<BATCH * 32 * NQ / 256, 256>>>(mask, mb);
    ln_kernel<<<BATCH * NQ, 256>>>(x, gamma, beta, xn);

    // heavy phase (ncu -s 5 -c 1 lands on the 6th launch = gemm_mma for K)
    gemm_mma<<<dim3(8, 32), 256, GT_SMEM>>>(xn,  wqt, q, 1);
    gemm_mma<<<dim3(8, 64), 256, GT_SMEM>>>(kin, wkt, k, 1);
    gemm_mma<<<dim3(8, 64), 256, GT_SMEM>>>(vin, wvt, v, 1);

    attn_mma<<<dim3(NQ / QTILE, HEADS, BATCH), 256, ATTN_SMEM>>>(q, k, v, mb, ctx);

    gemm_mma<<<dim3(8, 32), 256, GT_SMEM>>>(ctx, wot, out, 0);
}

// round 12
// speedup vs baseline: 6.2835x; 1.7274x over previous
#include <cuda_runtime.h>
#include <cuda_fp16.h>
#include <math.h>
#include <cstdint>

#define BATCH  4
#define NQ     1024
#define NKV    2048
#define DMODEL 1024
#define HEADS  16
#define DH     64
#define INNER  1024
#define KDIM   1024

// ---------------- scratch (no allocation allowed) ----------------
__device__ __half g_xn [BATCH * NQ  * DMODEL];
__device__ __half g_q  [BATCH * NQ  * INNER];
__device__ __half g_k  [BATCH * NKV * INNER];
__device__ __half g_v  [BATCH * NKV * INNER];
__device__ __half g_ctx[BATCH * NQ  * INNER];
__device__ __half g_wqt[KDIM * INNER];
__device__ __half g_wkt[KDIM * INNER];
__device__ __half g_wvt[KDIM * INNER];
__device__ __half g_wot[KDIM * INNER];
__device__ __half g_kin[BATCH * NKV * KDIM];
__device__ __half g_vin[BATCH * NKV * KDIM];
__device__ unsigned long long g_mb[BATCH * 32 * NQ];   // [b][kvblock][q] bitmask

__device__ __forceinline__ uint32_t smem_to_u32(const void* p) {
    uint32_t a;
    asm("{ .reg .u64 t; cvta.to.shared.u64 t, %1; cvt.u32.u64 %0, t; }" : "=r"(a) : "l"(p));
    return a;
}
__device__ __forceinline__ void cp_async16(uint32_t saddr, const void* g) {
    asm volatile("cp.async.cg.shared.global [%0], [%1], 16;" :: "r"(saddr), "l"(g));
}
#define CP_COMMIT() asm volatile("cp.async.commit_group;")
#define CP_WAIT(n)  asm volatile("cp.async.wait_group %0;" :: "n"(n) : "memory")

#define MMA_F16(acc, a0, a1, a2, a3, b0, b1) \
    asm volatile( \
        "mma.sync.aligned.m16n8k16.row.col.f32.f16.f16.f32 " \
        "{%0,%1,%2,%3}, {%4,%5,%6,%7}, {%8,%9}, {%0,%1,%2,%3};" \
        : "+f"((acc)[0]), "+f"((acc)[1]), "+f"((acc)[2]), "+f"((acc)[3]) \
        : "r"(a0), "r"(a1), "r"(a2), "r"(a3), "r"(b0), "r"(b1))

#define LDSM_X4(r, addr) \
    asm volatile("ldmatrix.sync.aligned.m8n8.x4.shared.b16 {%0,%1,%2,%3}, [%4];" \
        : "=r"((r)[0]), "=r"((r)[1]), "=r"((r)[2]), "=r"((r)[3]) : "r"(addr))

#define LDSM_X4_T(r, addr) \
    asm volatile("ldmatrix.sync.aligned.m8n8.x4.trans.shared.b16 {%0,%1,%2,%3}, [%4];" \
        : "=r"((r)[0]), "=r"((r)[1]), "=r"((r)[2]), "=r"((r)[3]) : "r"(addr))

// ---------------- elementwise convert to fp16 (key_t + value) -----------------
__global__ void round_all_kernel(const float* __restrict__ s0, __half* __restrict__ d0,
                                 const float* __restrict__ s1, __half* __restrict__ d1,
                                 int half_blocks) {
    int bx = blockIdx.x;
    const float* src = (bx < half_blocks) ? s0 : s1;
    __half* dst      = (bx < half_blocks) ? d0 : d1;
    int i = (bx < half_blocks ? bx : bx - half_blocks) * 256 + threadIdx.x;
    float4 v = ((const float4*)src)[i];
    ((__half2*)dst)[2 * i]     = __floats2half2_rn(v.x, v.y);
    ((__half2*)dst)[2 * i + 1] = __floats2half2_rn(v.z, v.w);
}

// ---------------- mask int32 -> 1 bit, layout [b][kvblock t][q] ----------------
__global__ void maskbit_kernel(const int* __restrict__ src, unsigned long long* __restrict__ dst) {
    int idx = blockIdx.x * 256 + threadIdx.x;   // 131072 total
    int b = idx >> 15;
    int t = (idx >> 10) & 31;
    int q = idx & 1023;
    const int4* p = (const int4*)(src + (((size_t)b * NQ + q) * NKV + t * 64));
    unsigned long long bits = 0ull;
#pragma unroll
    for (int j = 0; j < 16; j++) {
        int4 v = p[j];
        bits |= (unsigned long long)(v.x != 0) << (4 * j);
        bits |= (unsigned long long)(v.y != 0) << (4 * j + 1);
        bits |= (unsigned long long)(v.z != 0) << (4 * j + 2);
        bits |= (unsigned long long)(v.w != 0) << (4 * j + 3);
    }
    dst[idx] = bits;
}

// ---------------- fused weight transpose x4 (to fp16) --------------------------
__global__ void transpose_all_kernel(const float* __restrict__ w0, __half* __restrict__ d0,
                                     const float* __restrict__ w1, __half* __restrict__ d1,
                                     const float* __restrict__ w2, __half* __restrict__ d2,
                                     const float* __restrict__ w3, __half* __restrict__ d3) {
    __shared__ float t[32][33];
    const float* src = (blockIdx.z == 0) ? w0 : (blockIdx.z == 1) ? w1 : (blockIdx.z == 2) ? w2 : w3;
    __half* dst      = (blockIdx.z == 0) ? d0 : (blockIdx.z == 1) ? d1 : (blockIdx.z == 2) ? d2 : d3;
    int bx = blockIdx.x * 32, by = blockIdx.y * 32;
    int x = threadIdx.x, y = threadIdx.y;   // 32 x 8
#pragma unroll
    for (int i = 0; i < 32; i += 8)
        t[y + i][x] = src[(size_t)(by + y + i) * KDIM + bx + x];
    __syncthreads();
#pragma unroll
    for (int i = 0; i < 32; i += 8)
        dst[(size_t)(bx + y + i) * KDIM + by + x] = __float2half_rn(t[x][y + i]);
}

// ---------------- LayerNorm (fp16 output) ----------------
__global__ void ln_kernel(const float* __restrict__ x,
                          const float* __restrict__ gamma,
                          const float* __restrict__ beta,
                          __half* __restrict__ y) {
    __shared__ float red[16];
    int row = blockIdx.x;
    int tid = threadIdx.x;
    const float4* xr = (const float4*)(x + (size_t)row * DMODEL);
    float4 a = xr[tid];
    float s = a.x + a.y + a.z + a.w;
    float q = a.x * a.x + a.y * a.y + a.z * a.z + a.w * a.w;
#pragma unroll
    for (int off = 16; off; off >>= 1) {
        s += __shfl_xor_sync(0xffffffffu, s, off);
        q += __shfl_xor_sync(0xffffffffu, q, off);
    }
    if ((tid & 31) == 0) { red[tid >> 5] = s; red[8 + (tid >> 5)] = q; }
    __syncthreads();
    if (tid < 32) {
        float ss = (tid < 8) ? red[tid] : 0.f;
        float qq = (tid < 8) ? red[8 + tid] : 0.f;
#pragma unroll
        for (int off = 4; off; off >>= 1) {
            ss += __shfl_xor_sync(0xffffffffu, ss, off);
            qq += __shfl_xor_sync(0xffffffffu, qq, off);
        }
        if (tid == 0) { red[0] = ss; red[1] = qq; }
    }
    __syncthreads();
    float mu  = red[0] * (1.f / DMODEL);
    float var = red[1] * (1.f / DMODEL) - mu * mu;
    float inv = rsqrtf(var + 1e-5f);
    float4 g = ((const float4*)gamma)[tid];
    float4 b = ((const float4*)beta)[tid];
    __half2* yr = (__half2*)(y + (size_t)row * DMODEL);
    yr[2 * tid]     = __floats2half2_rn((a.x - mu) * inv * g.x + b.x, (a.y - mu) * inv * g.y + b.y);
    yr[2 * tid + 1] = __floats2half2_rn((a.z - mu) * inv * g.z + b.z, (a.w - mu) * inv * g.w + b.w);
}

// ---------------- fp16 mma GEMM (cp.async, single-sync pipeline) --------------
// rows: 64 halves data + 8 pad = 144 B (same bank geometry as tf32 version)
#define GROW 144
#define GBUF_B (128 * GROW)                  // 18432 B per buffer
#define GT_SMEM (4 * GBUF_B)                 // 73728 B

__global__ void __launch_bounds__(256, 2)
gemm_mma(const __half* __restrict__ A, const __half* __restrict__ Bt,
         void* __restrict__ Cout, int half_out) {
    extern __shared__ uint32_t smw[];
    uint32_t sb = smem_to_u32(smw);
    int tid = threadIdx.x, lane = tid & 31, wid = tid >> 5;
    int wm = (wid & 3) * 32, wn = (wid >> 2) * 64;
    int mrow = lane & 7, msel = lane >> 3;

    uint32_t aoffB = (uint32_t)((wm + (msel & 1) * 8 + mrow) * GROW + (msel >> 1) * 16);
    uint32_t boffB = (uint32_t)((wn + (msel >> 1) * 8 + mrow) * GROW + (msel & 1) * 16);

    const __half* Ab = A  + (size_t)(blockIdx.y * 128) * KDIM;
    const __half* Bb = Bt + (size_t)(blockIdx.x * 128) * KDIM;

    float acc[2][8][4] = {};

#define G_ISSUE(it, bf) do { \
    uint32_t abase = sb + (bf) * GBUF_B; \
    uint32_t bbase = sb + (2 + (bf)) * GBUF_B; \
    _Pragma("unroll") \
    for (int i = 0; i < 4; i++) { \
        int idx = tid + i * 256; int rr = idx >> 3, qq = idx & 7; \
        cp_async16(abase + rr * GROW + qq * 16, Ab + (size_t)rr * KDIM + (it) * 64 + qq * 8); \
        cp_async16(bbase + rr * GROW + qq * 16, Bb + (size_t)rr * KDIM + (it) * 64 + qq * 8); \
    } \
    CP_COMMIT(); \
} while (0)

    G_ISSUE(0, 0);

    for (int it = 0; it < 16; it++) {
        int buf = it & 1;
        CP_WAIT(0);
        __syncthreads();
        if (it < 15) G_ISSUE(it + 1, buf ^ 1);

        uint32_t aaddr = sb + buf * GBUF_B + aoffB;
        uint32_t baddr = sb + (2 + buf) * GBUF_B + boffB;
#pragma unroll
        for (int ks = 0; ks < 4; ks++) {          // 4 x k16 = 64 k per chunk
            uint32_t afr[2][4];
            LDSM_X4(afr[0], aaddr + ks * 32);
            LDSM_X4(afr[1], aaddr + 16 * GROW + ks * 32);
#pragma unroll
            for (int p = 0; p < 4; p++) {
                uint32_t bfr[4];
                LDSM_X4(bfr, baddr + p * (16 * GROW) + ks * 32);
#pragma unroll
                for (int sub = 0; sub < 2; sub++) {
                    int nf = 2 * p + sub;
                    uint32_t b0 = bfr[sub * 2], b1 = bfr[sub * 2 + 1];
#pragma unroll
                    for (int mf = 0; mf < 2; mf++)
                        MMA_F16(acc[mf][nf], afr[mf][0], afr[mf][1], afr[mf][2], afr[mf][3], b0, b1);
                }
            }
        }
    }
#undef G_ISSUE

    if (half_out) {
        __half* Cb = (__half*)Cout + (size_t)(blockIdx.y * 128) * 1024 + blockIdx.x * 128;
#pragma unroll
        for (int mf = 0; mf < 2; mf++) {
            int row = wm + mf * 16 + (lane >> 2);
#pragma unroll
            for (int nf = 0; nf < 8; nf++) {
                int col = wn + nf * 8 + (lane & 3) * 2;
                *(__half2*)(Cb + (size_t)row * 1024 + col) =
                    __floats2half2_rn(acc[mf][nf][0], acc[mf][nf][1]);
                *(__half2*)(Cb + (size_t)(row + 8) * 1024 + col) =
                    __floats2half2_rn(acc[mf][nf][2], acc[mf][nf][3]);
            }
        }
    } else {
        float* Cb = (float*)Cout + (size_t)(blockIdx.y * 128) * 1024 + blockIdx.x * 128;
#pragma unroll
        for (int mf = 0; mf < 2; mf++) {
            int row = wm + mf * 16 + (lane >> 2);
#pragma unroll
            for (int nf = 0; nf < 8; nf++) {
                int col = wn + nf * 8 + (lane & 3) * 2;
                *(float2*)(Cb + (size_t)row * 1024 + col) = make_float2(acc[mf][nf][0], acc[mf][nf][1]);
                *(float2*)(Cb + (size_t)(row + 8) * 1024 + col) = make_float2(acc[mf][nf][2], acc[mf][nf][3]);
            }
        }
    }
}

// ---------------- fp16 mma flash attention: 256 q x 64 kv, 32-row warps -------
// rows: 64 halves data + 8 pad = 144 B
#define QTILE 256
#define AROW 144
#define OFF_Q 0
#define SZ_Q  (QTILE * AROW)                 // 36864
#define OFF_K (SZ_Q)                         // + bf*9216
#define SZ_KV (64 * AROW)                    // 9216
#define OFF_V (SZ_Q + 2 * SZ_KV)
#define OFF_P (SZ_Q + 4 * SZ_KV)             // 73728
#define SZ_P  (QTILE * AROW)
#define OFF_M (OFF_P + SZ_P)                 // 110592
#define ATTN_SMEM (OFF_M + 2 * 2048)         // 114688

__global__ void __launch_bounds__(256, 1)
attn_mma(const __half* __restrict__ Q,
         const __half* __restrict__ K,
         const __half* __restrict__ V,
         const unsigned long long* __restrict__ mbits,
         __half* __restrict__ ctx) {
    extern __shared__ uint32_t sw[];
    uint32_t sb = smem_to_u32(sw);

    int tid = threadIdx.x, lane = tid & 31, wid = tid >> 5;
    int b = blockIdx.z, h = blockIdx.y, qt = blockIdx.x;
    const int g = lane >> 2, t4 = lane & 3;
    const int wm = wid * 32;
    const int mrow = lane & 7, msel = lane >> 3;

    // fragment base addresses (A-pattern for Q/P, B-pattern for K, trans for V)
    const uint32_t qa0 = sb + OFF_Q + (uint32_t)((wm + (msel & 1) * 8 + mrow) * AROW + (msel >> 1) * 16);
    const uint32_t qa1 = qa0 + 16 * AROW;
    const uint32_t kfragoff = (uint32_t)(((msel >> 1) * 8 + mrow) * AROW + (msel & 1) * 16);
    const uint32_t pa0 = sb + OFF_P + (uint32_t)((wm + (msel & 1) * 8 + mrow) * AROW + (msel >> 1) * 16);
    const uint32_t pa1 = pa0 + 16 * AROW;
    const uint32_t vfragoff = (uint32_t)(((msel & 1) * 8 + mrow) * AROW + (msel >> 1) * 16);

    const __half* Qb = Q + ((size_t)b * NQ + qt * QTILE) * INNER + h * DH;
    const __half* Kb = K + (size_t)b * NKV * INNER + h * DH;
    const __half* Vb = V + (size_t)b * NKV * INNER + h * DH;
    const char* Mb8 = (const char*)(mbits + (size_t)b * 32 * NQ) + (size_t)qt * QTILE * 8;

    // issue Q tile: 256 rows x 64 halves (128B = 8 segs/row)
#pragma unroll
    for (int i = 0; i < 8; i++) {
        int idx = tid + i * 256;
        int r = idx >> 3, qq = idx & 7;
        cp_async16(sb + OFF_Q + r * AROW + qq * 16, Qb + (size_t)r * INNER + qq * 8);
    }
    CP_COMMIT();

#define A_ISSUE(t, bf) do { \
    uint32_t kb_ = sb + OFF_K + (bf) * SZ_KV; \
    uint32_t vb_ = sb + OFF_V + (bf) * SZ_KV; \
    uint32_t mb_ = sb + OFF_M + (bf) * 2048; \
    _Pragma("unroll") \
    for (int i = 0; i < 2; i++) { \
        int idx = tid + i * 256; int r = idx >> 3, qq = idx & 7; \
        cp_async16(kb_ + r * AROW + qq * 16, Kb + (size_t)((t) * 64 + r) * INNER + qq * 8); \
        cp_async16(vb_ + r * AROW + qq * 16, Vb + (size_t)((t) * 64 + r) * INNER + qq * 8); \
    } \
    if (tid < 128) cp_async16(mb_ + tid * 16, Mb8 + (size_t)(t) * NQ * 8 + tid * 16); \
    CP_COMMIT(); \
} while (0)

    A_ISSUE(0, 0);

    float oacc[2][8][4] = {};
    float mrun[4], lrun[4];
#pragma unroll
    for (int i = 0; i < 4; i++) { mrun[i] = -3.402823466e38f; lrun[i] = 0.f; }
    const float scl = 0.125f;

    __half* Ps = (__half*)((char*)sw + OFF_P);

    for (int t = 0; t < NKV / 64; t++) {
        int buf = t & 1;
        CP_WAIT(0);
        __syncthreads();
        if (t < 31) A_ISSUE(t + 1, buf ^ 1);

        const uint32_t kbase = sb + OFF_K + buf * SZ_KV + kfragoff;
        const uint32_t vbase = sb + OFF_V + buf * SZ_KV + vfragoff;
        const unsigned long long* Msk =
            (const unsigned long long*)((const char*)sw + OFF_M + buf * 2048);

        // ---- S = Q K^T (warp: 32 x 64, 4 x k16) ----
        float sacc[2][8][4] = {};
#pragma unroll
        for (int ks = 0; ks < 4; ks++) {
            uint32_t afr[2][4];
            LDSM_X4(afr[0], qa0 + ks * 32);
            LDSM_X4(afr[1], qa1 + ks * 32);
#pragma unroll
            for (int p = 0; p < 4; p++) {
                uint32_t bfr[4];
                LDSM_X4(bfr, kbase + p * (16 * AROW) + ks * 32);
#pragma unroll
                for (int sub = 0; sub < 2; sub++) {
                    int nf = 2 * p + sub;
                    uint32_t b0 = bfr[sub * 2], b1 = bfr[sub * 2 + 1];
#pragma unroll
                    for (int mf = 0; mf < 2; mf++)
                        MMA_F16(sacc[mf][nf], afr[mf][0], afr[mf][1], afr[mf][2], afr[mf][3], b0, b1);
                }
            }
        }

        // ---- mask + scale + online softmax ----
        unsigned long long mbm[4];
        mbm[0] = Msk[wm + g];
        mbm[1] = Msk[wm + g + 8];
        mbm[2] = Msk[wm + g + 16];
        mbm[3] = Msk[wm + g + 24];
        int sh0 = t4 * 2;

        float tm[4];
#pragma unroll
        for (int i = 0; i < 4; i++) tm[i] = -3.402823466e38f;
#pragma unroll
        for (int mf = 0; mf < 2; mf++) {
            unsigned long long mlo = mbm[2 * mf], mhi = mbm[2 * mf + 1];
#pragma unroll
            for (int nf = 0; nf < 8; nf++) {
                int shn = nf * 8 + sh0;
                float s0 = sacc[mf][nf][0] * scl, s1 = sacc[mf][nf][1] * scl;
                float s2 = sacc[mf][nf][2] * scl, s3 = sacc[mf][nf][3] * scl;
                if ((mlo >> shn) & 1)       s0 = -3.402823466e38f;
                if ((mlo >> (shn + 1)) & 1) s1 = -3.402823466e38f;
                if ((mhi >> shn) & 1)       s2 = -3.402823466e38f;
                if ((mhi >> (shn + 1)) & 1) s3 = -3.402823466e38f;
                sacc[mf][nf][0] = s0; sacc[mf][nf][1] = s1;
                sacc[mf][nf][2] = s2; sacc[mf][nf][3] = s3;
                tm[2 * mf]     = fmaxf(tm[2 * mf], fmaxf(s0, s1));
                tm[2 * mf + 1] = fmaxf(tm[2 * mf + 1], fmaxf(s2, s3));
            }
        }
        float corr[4], mn[4];
#pragma unroll
        for (int i = 0; i < 4; i++) {
            tm[i] = fmaxf(tm[i], __shfl_xor_sync(0xffffffffu, tm[i], 1));
            tm[i] = fmaxf(tm[i], __shfl_xor_sync(0xffffffffu, tm[i], 2));
            mn[i] = fmaxf(mrun[i], tm[i]);
            corr[i] = __expf(mrun[i] - mn[i]);
            mrun[i] = mn[i];
        }
        float ls[4] = {0.f, 0.f, 0.f, 0.f};
#pragma unroll
        for (int mf = 0; mf < 2; mf++) {
#pragma unroll
            for (int nf = 0; nf < 8; nf++) {
                int c = nf * 8 + sh0;
                float p0 = __expf(sacc[mf][nf][0] - mn[2 * mf]);
                float p1 = __expf(sacc[mf][nf][1] - mn[2 * mf]);
                float p2 = __expf(sacc[mf][nf][2] - mn[2 * mf + 1]);
                float p3 = __expf(sacc[mf][nf][3] - mn[2 * mf + 1]);
                ls[2 * mf]     += p0 + p1;
                ls[2 * mf + 1] += p2 + p3;
                int row = wm + mf * 16 + g;
                *(__half2*)&Ps[row * 72 + c]       = __floats2half2_rn(p0, p1);
                *(__half2*)&Ps[(row + 8) * 72 + c] = __floats2half2_rn(p2, p3);
            }
        }
#pragma unroll
        for (int i = 0; i < 4; i++) {
            ls[i] += __shfl_xor_sync(0xffffffffu, ls[i], 1);
            ls[i] += __shfl_xor_sync(0xffffffffu, ls[i], 2);
            lrun[i] = lrun[i] * corr[i] + ls[i];
        }
#pragma unroll
        for (int mf = 0; mf < 2; mf++)
#pragma unroll
            for (int nf = 0; nf < 8; nf++) {
                oacc[mf][nf][0] *= corr[2 * mf];     oacc[mf][nf][1] *= corr[2 * mf];
                oacc[mf][nf][2] *= corr[2 * mf + 1]; oacc[mf][nf][3] *= corr[2 * mf + 1];
            }
        __syncwarp();

        // ---- O += P V  (A from Ps via ldmatrix; B from Vs via ldmatrix.trans) ----
#pragma unroll
        for (int ks = 0; ks < 4; ks++) {            // 4 x k16 over 64 kv
            uint32_t afr[2][4];
            LDSM_X4(afr[0], pa0 + ks * 32);
            LDSM_X4(afr[1], pa1 + ks * 32);
#pragma unroll
            for (int p = 0; p < 4; p++) {
                uint32_t bfr[4];
                LDSM_X4_T(bfr, vbase + ks * (16 * AROW) + p * 32);
#pragma unroll
                for (int sub = 0; sub < 2; sub++) {
                    int nf = 2 * p + sub;
                    uint32_t b0 = bfr[sub * 2], b1 = bfr[sub * 2 + 1];
#pragma unroll
                    for (int mf = 0; mf < 2; mf++)
                        MMA_F16(oacc[mf][nf], afr[mf][0], afr[mf][1], afr[mf][2], afr[mf][3], b0, b1);
                }
            }
        }
    }
#undef A_ISSUE

    // epilogue: write ctx fp16
    float inv[4];
#pragma unroll
    for (int i = 0; i < 4; i++) inv[i] = __fdividef(1.f, lrun[i]);
#pragma unroll
    for (int mf = 0; mf < 2; mf++) {
        size_t row = (size_t)b * NQ + qt * QTILE + wm + mf * 16 + g;
        __half* o1 = ctx + row * INNER + h * DH;
        __half* o2 = o1 + (size_t)8 * INNER;
#pragma unroll
        for (int nf = 0; nf < 8; nf++) {
            int c = nf * 8 + t4 * 2;
            *(__half2*)(o1 + c) = __floats2half2_rn(oacc[mf][nf][0] * inv[2 * mf],
                                                    oacc[mf][nf][1] * inv[2 * mf]);
            *(__half2*)(o2 + c) = __floats2half2_rn(oacc[mf][nf][2] * inv[2 * mf + 1],
                                                    oacc[mf][nf][3] * inv[2 * mf + 1]);
        }
    }
}

// ---------------- launcher ----------------
extern "C" void kernel_launch(void* const* d_in, const int* in_sizes, int n_in,
                              void* d_out, int out_size) {
    const float* x     = (const float*)d_in[0];
    const float* key_t = (const float*)d_in[1];
    const float* value = (const float*)d_in[2];
    const int*   mask  = (const int*)d_in[3];
    const float* Wq    = (const float*)d_in[4];
    const float* Wk    = (const float*)d_in[5];
    const float* Wv    = (const float*)d_in[6];
    const float* Wo    = (const float*)d_in[7];
    const float* gamma = (const float*)d_in[8];
    const float* beta  = (const float*)d_in[9];
    float* out = (float*)d_out;

    __half *xn, *q, *k, *v, *ctx, *wqt, *wkt, *wvt, *wot, *kin, *vin;
    unsigned long long* mb;
    cudaGetSymbolAddress((void**)&xn,  g_xn);
    cudaGetSymbolAddress((void**)&q,   g_q);
    cudaGetSymbolAddress((void**)&k,   g_k);
    cudaGetSymbolAddress((void**)&v,   g_v);
    cudaGetSymbolAddress((void**)&ctx, g_ctx);
    cudaGetSymbolAddress((void**)&wqt, g_wqt);
    cudaGetSymbolAddress((void**)&wkt, g_wkt);
    cudaGetSymbolAddress((void**)&wvt, g_wvt);
    cudaGetSymbolAddress((void**)&wot, g_wot);
    cudaGetSymbolAddress((void**)&kin, g_kin);
    cudaGetSymbolAddress((void**)&vin, g_vin);
    cudaGetSymbolAddress((void**)&mb,  g_mb);

    cudaFuncSetAttribute(attn_mma, cudaFuncAttributeMaxDynamicSharedMemorySize, ATTN_SMEM);
    cudaFuncSetAttribute(gemm_mma, cudaFuncAttributeMaxDynamicSharedMemorySize, GT_SMEM);

    transpose_all_kernel<<<dim3(32, 32, 4), dim3(32, 8)>>>(Wq, wqt, Wk, wkt, Wv, wvt, Wo, wot);
    {
        int half = BATCH * NKV * KDIM / 4 / 256;
        round_all_kernel<<<2 * half, 256>>>(key_t, kin, value, vin, half);
    }
    maskbit_kernel<<<BATCH * 32 * NQ / 256, 256>>>(mask, mb);
    ln_kernel<<<BATCH * NQ, 256>>>(x, gamma, beta, xn);

    gemm_mma<<<dim3(8, 32), 256, GT_SMEM>>>(xn,  wqt, q, 1);
    gemm_mma<<<dim3(8, 64), 256, GT_SMEM>>>(kin, wkt, k, 1);
    gemm_mma<<<dim3(8, 64), 256, GT_SMEM>>>(vin, wvt, v, 1);

    attn_mma<<<dim3(NQ / QTILE, HEADS, BATCH), 256, ATTN_SMEM>>>(q, k, v, mb, ctx);

    gemm_mma<<<dim3(8, 32), 256, GT_SMEM>>>(ctx, wot, out, 0);
}

// round 13
// speedup vs baseline: 6.8083x; 1.0835x over previous
#include <cuda_runtime.h>
#include <cuda_fp16.h>
#include <math.h>
#include <cstdint>

#define BATCH  4
#define NQ     1024
#define NKV    2048
#define DMODEL 1024
#define HEADS  16
#define DH     64
#define INNER  1024
#define KDIM   1024

// ---------------- scratch (no allocation allowed) ----------------
__device__ __half g_xn [BATCH * NQ  * DMODEL];
__device__ __half g_q  [BATCH * NQ  * INNER];
__device__ __half g_k  [BATCH * NKV * INNER];
__device__ __half g_v  [BATCH * NKV * INNER];
__device__ __half g_ctx[BATCH * NQ  * INNER];
__device__ __half g_wqt[KDIM * INNER];
__device__ __half g_wkt[KDIM * INNER];
__device__ __half g_wvt[KDIM * INNER];
__device__ __half g_wot[KDIM * INNER];
__device__ __half g_kin[BATCH * NKV * KDIM];
__device__ __half g_vin[BATCH * NKV * KDIM];
__device__ unsigned long long g_mb[BATCH * 32 * NQ];   // [b][kvblock][q] bitmask

__device__ __forceinline__ uint32_t smem_to_u32(const void* p) {
    uint32_t a;
    asm("{ .reg .u64 t; cvta.to.shared.u64 t, %1; cvt.u32.u64 %0, t; }" : "=r"(a) : "l"(p));
    return a;
}
__device__ __forceinline__ void cp_async16(uint32_t saddr, const void* g) {
    asm volatile("cp.async.cg.shared.global [%0], [%1], 16;" :: "r"(saddr), "l"(g));
}
#define CP_COMMIT() asm volatile("cp.async.commit_group;")
#define CP_WAIT(n)  asm volatile("cp.async.wait_group %0;" :: "n"(n) : "memory")

#define MMA_F16(acc, a0, a1, a2, a3, b0, b1) \
    asm volatile( \
        "mma.sync.aligned.m16n8k16.row.col.f32.f16.f16.f32 " \
        "{%0,%1,%2,%3}, {%4,%5,%6,%7}, {%8,%9}, {%0,%1,%2,%3};" \
        : "+f"((acc)[0]), "+f"((acc)[1]), "+f"((acc)[2]), "+f"((acc)[3]) \
        : "r"(a0), "r"(a1), "r"(a2), "r"(a3), "r"(b0), "r"(b1))

#define LDSM_X4(r, addr) \
    asm volatile("ldmatrix.sync.aligned.m8n8.x4.shared.b16 {%0,%1,%2,%3}, [%4];" \
        : "=r"((r)[0]), "=r"((r)[1]), "=r"((r)[2]), "=r"((r)[3]) : "r"(addr))

#define LDSM_X4_T(r, addr) \
    asm volatile("ldmatrix.sync.aligned.m8n8.x4.trans.shared.b16 {%0,%1,%2,%3}, [%4];" \
        : "=r"((r)[0]), "=r"((r)[1]), "=r"((r)[2]), "=r"((r)[3]) : "r"(addr))

// ---------------- fused prep: transposes + rounds + maskbits + LN -------------
// blocks: [0,4096) transpose  [4096,20480) round  [20480,20992) maskbit  [20992,25088) ln
__global__ void prep_fused(const float* __restrict__ x,
                           const float* __restrict__ key_t, const float* __restrict__ value,
                           const int* __restrict__ mask,
                           const float* __restrict__ Wq, const float* __restrict__ Wk,
                           const float* __restrict__ Wv, const float* __restrict__ Wo,
                           const float* __restrict__ gamma, const float* __restrict__ beta,
                           __half* __restrict__ xn,
                           __half* __restrict__ kin, __half* __restrict__ vin,
                           unsigned long long* __restrict__ mb,
                           __half* __restrict__ wqt, __half* __restrict__ wkt,
                           __half* __restrict__ wvt, __half* __restrict__ wot) {
    __shared__ float smbuf[32][33];
    int bid = blockIdx.x, tid = threadIdx.x;

    if (bid < 4096) {                          // ---- weight transpose (to fp16)
        int w = bid >> 10, t = bid & 1023;
        const float* src = (w == 0) ? Wq : (w == 1) ? Wk : (w == 2) ? Wv : Wo;
        __half* dst      = (w == 0) ? wqt : (w == 1) ? wkt : (w == 2) ? wvt : wot;
        int bx = (t & 31) * 32, by = (t >> 5) * 32;
        int xI = tid & 31, yI = tid >> 5;      // 32 x 8
#pragma unroll
        for (int i = 0; i < 32; i += 8)
            smbuf[yI + i][xI] = src[(size_t)(by + yI + i) * KDIM + bx + xI];
        __syncthreads();
#pragma unroll
        for (int i = 0; i < 32; i += 8)
            dst[(size_t)(bx + yI + i) * KDIM + by + xI] = __float2half_rn(smbuf[xI][yI + i]);
    } else if (bid < 20480) {                  // ---- fp32 -> fp16 round
        int i0 = bid - 4096;
        const float* src = (i0 < 8192) ? key_t : value;
        __half* dst      = (i0 < 8192) ? kin : vin;
        int i = (i0 & 8191) * 256 + tid;
        float4 v = ((const float4*)src)[i];
        ((__half2*)dst)[2 * i]     = __floats2half2_rn(v.x, v.y);
        ((__half2*)dst)[2 * i + 1] = __floats2half2_rn(v.z, v.w);
    } else if (bid < 20992) {                  // ---- mask -> bitmask
        int idx = (bid - 20480) * 256 + tid;
        int b = idx >> 15, t = (idx >> 10) & 31, q = idx & 1023;
        const int4* p = (const int4*)(mask + (((size_t)b * NQ + q) * NKV + t * 64));
        unsigned long long bits = 0ull;
#pragma unroll
        for (int j = 0; j < 16; j++) {
            int4 v = p[j];
            bits |= (unsigned long long)(v.x != 0) << (4 * j);
            bits |= (unsigned long long)(v.y != 0) << (4 * j + 1);
            bits |= (unsigned long long)(v.z != 0) << (4 * j + 2);
            bits |= (unsigned long long)(v.w != 0) << (4 * j + 3);
        }
        mb[idx] = bits;
    } else {                                   // ---- LayerNorm (fp16 out)
        float* red = &smbuf[0][0];
        int row = bid - 20992;
        const float4* xr = (const float4*)(x + (size_t)row * DMODEL);
        float4 a = xr[tid];
        float s = a.x + a.y + a.z + a.w;
        float q = a.x * a.x + a.y * a.y + a.z * a.z + a.w * a.w;
#pragma unroll
        for (int off = 16; off; off >>= 1) {
            s += __shfl_xor_sync(0xffffffffu, s, off);
            q += __shfl_xor_sync(0xffffffffu, q, off);
        }
        if ((tid & 31) == 0) { red[tid >> 5] = s; red[8 + (tid >> 5)] = q; }
        __syncthreads();
        if (tid < 32) {
            float ss = (tid < 8) ? red[tid] : 0.f;
            float qq = (tid < 8) ? red[8 + tid] : 0.f;
#pragma unroll
            for (int off = 4; off; off >>= 1) {
                ss += __shfl_xor_sync(0xffffffffu, ss, off);
                qq += __shfl_xor_sync(0xffffffffu, qq, off);
            }
            if (tid == 0) { red[0] = ss; red[1] = qq; }
        }
        __syncthreads();
        float mu  = red[0] * (1.f / DMODEL);
        float var = red[1] * (1.f / DMODEL) - mu * mu;
        float inv = rsqrtf(var + 1e-5f);
        float4 g = ((const float4*)gamma)[tid];
        float4 b = ((const float4*)beta)[tid];
        __half2* yr = (__half2*)(xn + (size_t)row * DMODEL);
        yr[2 * tid]     = __floats2half2_rn((a.x - mu) * inv * g.x + b.x, (a.y - mu) * inv * g.y + b.y);
        yr[2 * tid + 1] = __floats2half2_rn((a.z - mu) * inv * g.z + b.z, (a.w - mu) * inv * g.w + b.w);
    }
}

// ---------------- fp16 mma GEMM core (cp.async, single-sync pipeline) ---------
#define GROW 144
#define GBUF_B (128 * GROW)
#define GT_SMEM (4 * GBUF_B)

__device__ __forceinline__ void gemm_core(const __half* __restrict__ Ab,
                                          const __half* __restrict__ Bb,
                                          void* __restrict__ Cout, size_t crowbase,
                                          int half_out, uint32_t sb, uint32_t* smw) {
    int tid = threadIdx.x, lane = tid & 31, wid = tid >> 5;
    int wm = (wid & 3) * 32, wn = (wid >> 2) * 64;
    int mrow = lane & 7, msel = lane >> 3;

    uint32_t aoffB = (uint32_t)((wm + (msel & 1) * 8 + mrow) * GROW + (msel >> 1) * 16);
    uint32_t boffB = (uint32_t)((wn + (msel >> 1) * 8 + mrow) * GROW + (msel & 1) * 16);

    float acc[2][8][4] = {};

#define G_ISSUE(it, bf) do { \
    uint32_t abase = sb + (bf) * GBUF_B; \
    uint32_t bbase = sb + (2 + (bf)) * GBUF_B; \
    _Pragma("unroll") \
    for (int i = 0; i < 4; i++) { \
        int idx = tid + i * 256; int rr = idx >> 3, qq = idx & 7; \
        cp_async16(abase + rr * GROW + qq * 16, Ab + (size_t)rr * KDIM + (it) * 64 + qq * 8); \
        cp_async16(bbase + rr * GROW + qq * 16, Bb + (size_t)rr * KDIM + (it) * 64 + qq * 8); \
    } \
    CP_COMMIT(); \
} while (0)

    G_ISSUE(0, 0);

    for (int it = 0; it < 16; it++) {
        int buf = it & 1;
        CP_WAIT(0);
        __syncthreads();
        if (it < 15) G_ISSUE(it + 1, buf ^ 1);

        uint32_t aaddr = sb + buf * GBUF_B + aoffB;
        uint32_t baddr = sb + (2 + buf) * GBUF_B + boffB;
#pragma unroll
        for (int ks = 0; ks < 4; ks++) {
            uint32_t afr[2][4];
            LDSM_X4(afr[0], aaddr + ks * 32);
            LDSM_X4(afr[1], aaddr + 16 * GROW + ks * 32);
#pragma unroll
            for (int p = 0; p < 4; p++) {
                uint32_t bfr[4];
                LDSM_X4(bfr, baddr + p * (16 * GROW) + ks * 32);
#pragma unroll
                for (int sub = 0; sub < 2; sub++) {
                    int nf = 2 * p + sub;
                    uint32_t b0 = bfr[sub * 2], b1 = bfr[sub * 2 + 1];
#pragma unroll
                    for (int mf = 0; mf < 2; mf++)
                        MMA_F16(acc[mf][nf], afr[mf][0], afr[mf][1], afr[mf][2], afr[mf][3], b0, b1);
                }
            }
        }
    }
#undef G_ISSUE

    if (half_out) {
        __half* Cb = (__half*)Cout + crowbase;
#pragma unroll
        for (int mf = 0; mf < 2; mf++) {
            int row = wm + mf * 16 + (lane >> 2);
#pragma unroll
            for (int nf = 0; nf < 8; nf++) {
                int col = wn + nf * 8 + (lane & 3) * 2;
                *(__half2*)(Cb + (size_t)row * 1024 + col) =
                    __floats2half2_rn(acc[mf][nf][0], acc[mf][nf][1]);
                *(__half2*)(Cb + (size_t)(row + 8) * 1024 + col) =
                    __floats2half2_rn(acc[mf][nf][2], acc[mf][nf][3]);
            }
        }
    } else {
        float* Cb = (float*)Cout + crowbase;
#pragma unroll
        for (int mf = 0; mf < 2; mf++) {
            int row = wm + mf * 16 + (lane >> 2);
#pragma unroll
            for (int nf = 0; nf < 8; nf++) {
                int col = wn + nf * 8 + (lane & 3) * 2;
                *(float2*)(Cb + (size_t)row * 1024 + col) = make_float2(acc[mf][nf][0], acc[mf][nf][1]);
                *(float2*)(Cb + (size_t)(row + 8) * 1024 + col) = make_float2(acc[mf][nf][2], acc[mf][nf][3]);
            }
        }
    }
}

// merged QKV GEMM: grid y 0..159 (32 q tiles, 64 k tiles, 64 v tiles)
__global__ void __launch_bounds__(256, 2)
gemm_qkv(const __half* __restrict__ xn, const __half* __restrict__ kin, const __half* __restrict__ vin,
         const __half* __restrict__ wqt, const __half* __restrict__ wkt, const __half* __restrict__ wvt,
         __half* __restrict__ q, __half* __restrict__ k, __half* __restrict__ v) {
    extern __shared__ uint32_t smw[];
    uint32_t sb = smem_to_u32(smw);
    int y = blockIdx.y;
    const __half *A, *B;
    __half* C;
    int ytile;
    if (y < 32)      { A = xn;  B = wqt; C = q; ytile = y; }
    else if (y < 96) { A = kin; B = wkt; C = k; ytile = y - 32; }
    else             { A = vin; B = wvt; C = v; ytile = y - 96; }
    gemm_core(A + (size_t)(ytile * 128) * KDIM,
              B + (size_t)(blockIdx.x * 128) * KDIM,
              C, (size_t)(ytile * 128) * 1024 + blockIdx.x * 128, 1, sb, smw);
}

// final out GEMM (fp32 out)
__global__ void __launch_bounds__(256, 2)
gemm_out(const __half* __restrict__ ctx, const __half* __restrict__ wot, float* __restrict__ out) {
    extern __shared__ uint32_t smw[];
    uint32_t sb = smem_to_u32(smw);
    gemm_core(ctx + (size_t)(blockIdx.y * 128) * KDIM,
              wot + (size_t)(blockIdx.x * 128) * KDIM,
              out, (size_t)(blockIdx.y * 128) * 1024 + blockIdx.x * 128, 0, sb, smw);
}

// ---------------- fp16 mma flash attention: 256 q x 64 kv, 32-row warps -------
#define QTILE 256
#define AROW 144
#define OFF_Q 0
#define SZ_Q  (QTILE * AROW)
#define OFF_K (SZ_Q)
#define SZ_KV (64 * AROW)
#define OFF_V (SZ_Q + 2 * SZ_KV)
#define OFF_P (SZ_Q + 4 * SZ_KV)
#define SZ_P  (QTILE * AROW)
#define OFF_M (OFF_P + SZ_P)
#define ATTN_SMEM (OFF_M + 2 * 2048)

__global__ void __launch_bounds__(256, 1)
attn_mma(const __half* __restrict__ Q,
         const __half* __restrict__ K,
         const __half* __restrict__ V,
         const unsigned long long* __restrict__ mbits,
         __half* __restrict__ ctx) {
    extern __shared__ uint32_t sw[];
    uint32_t sb = smem_to_u32(sw);

    int tid = threadIdx.x, lane = tid & 31, wid = tid >> 5;
    int b = blockIdx.z, h = blockIdx.y, qt = blockIdx.x;
    const int g = lane >> 2, t4 = lane & 3;
    const int wm = wid * 32;
    const int mrow = lane & 7, msel = lane >> 3;

    const uint32_t qa0 = sb + OFF_Q + (uint32_t)((wm + (msel & 1) * 8 + mrow) * AROW + (msel >> 1) * 16);
    const uint32_t qa1 = qa0 + 16 * AROW;
    const uint32_t kfragoff = (uint32_t)(((msel >> 1) * 8 + mrow) * AROW + (msel & 1) * 16);
    const uint32_t pa0 = sb + OFF_P + (uint32_t)((wm + (msel & 1) * 8 + mrow) * AROW + (msel >> 1) * 16);
    const uint32_t pa1 = pa0 + 16 * AROW;
    const uint32_t vfragoff = (uint32_t)(((msel & 1) * 8 + mrow) * AROW + (msel >> 1) * 16);

    const __half* Qb = Q + ((size_t)b * NQ + qt * QTILE) * INNER + h * DH;
    const __half* Kb = K + (size_t)b * NKV * INNER + h * DH;
    const __half* Vb = V + (size_t)b * NKV * INNER + h * DH;
    const char* Mb8 = (const char*)(mbits + (size_t)b * 32 * NQ) + (size_t)qt * QTILE * 8;

#pragma unroll
    for (int i = 0; i < 8; i++) {
        int idx = tid + i * 256;
        int r = idx >> 3, qq = idx & 7;
        cp_async16(sb + OFF_Q + r * AROW + qq * 16, Qb + (size_t)r * INNER + qq * 8);
    }
    CP_COMMIT();

#define A_ISSUE(t, bf) do { \
    uint32_t kb_ = sb + OFF_K + (bf) * SZ_KV; \
    uint32_t vb_ = sb + OFF_V + (bf) * SZ_KV; \
    uint32_t mb_ = sb + OFF_M + (bf) * 2048; \
    _Pragma("unroll") \
    for (int i = 0; i < 2; i++) { \
        int idx = tid + i * 256; int r = idx >> 3, qq = idx & 7; \
        cp_async16(kb_ + r * AROW + qq * 16, Kb + (size_t)((t) * 64 + r) * INNER + qq * 8); \
        cp_async16(vb_ + r * AROW + qq * 16, Vb + (size_t)((t) * 64 + r) * INNER + qq * 8); \
    } \
    if (tid < 128) cp_async16(mb_ + tid * 16, Mb8 + (size_t)(t) * NQ * 8 + tid * 16); \
    CP_COMMIT(); \
} while (0)

    A_ISSUE(0, 0);

    float oacc[2][8][4] = {};
    float mrun[4], lrun[4];
#pragma unroll
    for (int i = 0; i < 4; i++) { mrun[i] = -3.402823466e38f; lrun[i] = 0.f; }
    const float scl = 0.125f;

    __half* Ps = (__half*)((char*)sw + OFF_P);

    for (int t = 0; t < NKV / 64; t++) {
        int buf = t & 1;
        CP_WAIT(0);
        __syncthreads();
        if (t < 31) A_ISSUE(t + 1, buf ^ 1);

        const uint32_t kbase = sb + OFF_K + buf * SZ_KV + kfragoff;
        const uint32_t vbase = sb + OFF_V + buf * SZ_KV + vfragoff;
        const unsigned long long* Msk =
            (const unsigned long long*)((const char*)sw + OFF_M + buf * 2048);

        float sacc[2][8][4] = {};
#pragma unroll
        for (int ks = 0; ks < 4; ks++) {
            uint32_t afr[2][4];
            LDSM_X4(afr[0], qa0 + ks * 32);
            LDSM_X4(afr[1], qa1 + ks * 32);
#pragma unroll
            for (int p = 0; p < 4; p++) {
                uint32_t bfr[4];
                LDSM_X4(bfr, kbase + p * (16 * AROW) + ks * 32);
#pragma unroll
                for (int sub = 0; sub < 2; sub++) {
                    int nf = 2 * p + sub;
                    uint32_t b0 = bfr[sub * 2], b1 = bfr[sub * 2 + 1];
#pragma unroll
                    for (int mf = 0; mf < 2; mf++)
                        MMA_F16(sacc[mf][nf], afr[mf][0], afr[mf][1], afr[mf][2], afr[mf][3], b0, b1);
                }
            }
        }

        unsigned long long mbm[4];
        mbm[0] = Msk[wm + g];
        mbm[1] = Msk[wm + g + 8];
        mbm[2] = Msk[wm + g + 16];
        mbm[3] = Msk[wm + g + 24];
        int sh0 = t4 * 2;

        float tm[4];
#pragma unroll
        for (int i = 0; i < 4; i++) tm[i] = -3.402823466e38f;
#pragma unroll
        for (int mf = 0; mf < 2; mf++) {
            unsigned long long mlo = mbm[2 * mf], mhi = mbm[2 * mf + 1];
#pragma unroll
            for (int nf = 0; nf < 8; nf++) {
                int shn = nf * 8 + sh0;
                float s0 = sacc[mf][nf][0] * scl, s1 = sacc[mf][nf][1] * scl;
                float s2 = sacc[mf][nf][2] * scl, s3 = sacc[mf][nf][3] * scl;
                if ((mlo >> shn) & 1)       s0 = -3.402823466e38f;
                if ((mlo >> (shn + 1)) & 1) s1 = -3.402823466e38f;
                if ((mhi >> shn) & 1)       s2 = -3.402823466e38f;
                if ((mhi >> (shn + 1)) & 1) s3 = -3.402823466e38f;
                sacc[mf][nf][0] = s0; sacc[mf][nf][1] = s1;
                sacc[mf][nf][2] = s2; sacc[mf][nf][3] = s3;
                tm[2 * mf]     = fmaxf(tm[2 * mf], fmaxf(s0, s1));
                tm[2 * mf + 1] = fmaxf(tm[2 * mf + 1], fmaxf(s2, s3));
            }
        }
        float corr[4], mn[4];
#pragma unroll
        for (int i = 0; i < 4; i++) {
            tm[i] = fmaxf(tm[i], __shfl_xor_sync(0xffffffffu, tm[i], 1));
            tm[i] = fmaxf(tm[i], __shfl_xor_sync(0xffffffffu, tm[i], 2));
            mn[i] = fmaxf(mrun[i], tm[i]);
            corr[i] = __expf(mrun[i] - mn[i]);
            mrun[i] = mn[i];
        }
        float ls[4] = {0.f, 0.f, 0.f, 0.f};
#pragma unroll
        for (int mf = 0; mf < 2; mf++) {
#pragma unroll
            for (int nf = 0; nf < 8; nf++) {
                int c = nf * 8 + sh0;
                float p0 = __expf(sacc[mf][nf][0] - mn[2 * mf]);
                float p1 = __expf(sacc[mf][nf][1] - mn[2 * mf]);
                float p2 = __expf(sacc[mf][nf][2] - mn[2 * mf + 1]);
                float p3 = __expf(sacc[mf][nf][3] - mn[2 * mf + 1]);
                ls[2 * mf]     += p0 + p1;
                ls[2 * mf + 1] += p2 + p3;
                int row = wm + mf * 16 + g;
                *(__half2*)&Ps[row * 72 + c]       = __floats2half2_rn(p0, p1);
                *(__half2*)&Ps[(row + 8) * 72 + c] = __floats2half2_rn(p2, p3);
            }
        }
#pragma unroll
        for (int i = 0; i < 4; i++) {
            ls[i] += __shfl_xor_sync(0xffffffffu, ls[i], 1);
            ls[i] += __shfl_xor_sync(0xffffffffu, ls[i], 2);
            lrun[i] = lrun[i] * corr[i] + ls[i];
        }
#pragma unroll
        for (int mf = 0; mf < 2; mf++)
#pragma unroll
            for (int nf = 0; nf < 8; nf++) {
                oacc[mf][nf][0] *= corr[2 * mf];     oacc[mf][nf][1] *= corr[2 * mf];
                oacc[mf][nf][2] *= corr[2 * mf + 1]; oacc[mf][nf][3] *= corr[2 * mf + 1];
            }
        __syncwarp();

#pragma unroll
        for (int ks = 0; ks < 4; ks++) {
            uint32_t afr[2][4];
            LDSM_X4(afr[0], pa0 + ks * 32);
            LDSM_X4(afr[1], pa1 + ks * 32);
#pragma unroll
            for (int p = 0; p < 4; p++) {
                uint32_t bfr[4];
                LDSM_X4_T(bfr, vbase + ks * (16 * AROW) + p * 32);
#pragma unroll
                for (int sub = 0; sub < 2; sub++) {
                    int nf = 2 * p + sub;
                    uint32_t b0 = bfr[sub * 2], b1 = bfr[sub * 2 + 1];
#pragma unroll
                    for (int mf = 0; mf < 2; mf++)
                        MMA_F16(oacc[mf][nf], afr[mf][0], afr[mf][1], afr[mf][2], afr[mf][3], b0, b1);
                }
            }
        }
    }
#undef A_ISSUE

    float inv[4];
#pragma unroll
    for (int i = 0; i < 4; i++) inv[i] = __fdividef(1.f, lrun[i]);
#pragma unroll
    for (int mf = 0; mf < 2; mf++) {
        size_t row = (size_t)b * NQ + qt * QTILE + wm + mf * 16 + g;
        __half* o1 = ctx + row * INNER + h * DH;
        __half* o2 = o1 + (size_t)8 * INNER;
#pragma unroll
        for (int nf = 0; nf < 8; nf++) {
            int c = nf * 8 + t4 * 2;
            *(__half2*)(o1 + c) = __floats2half2_rn(oacc[mf][nf][0] * inv[2 * mf],
                                                    oacc[mf][nf][1] * inv[2 * mf]);
            *(__half2*)(o2 + c) = __floats2half2_rn(oacc[mf][nf][2] * inv[2 * mf + 1],
                                                    oacc[mf][nf][3] * inv[2 * mf + 1]);
        }
    }
}

// ---------------- launcher ----------------
extern "C" void kernel_launch(void* const* d_in, const int* in_sizes, int n_in,
                              void* d_out, int out_size) {
    const float* x     = (const float*)d_in[0];
    const float* key_t = (const float*)d_in[1];
    const float* value = (const float*)d_in[2];
    const int*   mask  = (const int*)d_in[3];
    const float* Wq    = (const float*)d_in[4];
    const float* Wk    = (const float*)d_in[5];
    const float* Wv    = (const float*)d_in[6];
    const float* Wo    = (const float*)d_in[7];
    const float* gamma = (const float*)d_in[8];
    const float* beta  = (const float*)d_in[9];
    float* out = (float*)d_out;

    __half *xn, *q, *k, *v, *ctx, *wqt, *wkt, *wvt, *wot, *kin, *vin;
    unsigned long long* mb;
    cudaGetSymbolAddress((void**)&xn,  g_xn);
    cudaGetSymbolAddress((void**)&q,   g_q);
    cudaGetSymbolAddress((void**)&k,   g_k);
    cudaGetSymbolAddress((void**)&v,   g_v);
    cudaGetSymbolAddress((void**)&ctx, g_ctx);
    cudaGetSymbolAddress((void**)&wqt, g_wqt);
    cudaGetSymbolAddress((void**)&wkt, g_wkt);
    cudaGetSymbolAddress((void**)&wvt, g_wvt);
    cudaGetSymbolAddress((void**)&wot, g_wot);
    cudaGetSymbolAddress((void**)&kin, g_kin);
    cudaGetSymbolAddress((void**)&vin, g_vin);
    cudaGetSymbolAddress((void**)&mb,  g_mb);

    cudaFuncSetAttribute(attn_mma, cudaFuncAttributeMaxDynamicSharedMemorySize, ATTN_SMEM);
    cudaFuncSetAttribute(gemm_qkv, cudaFuncAttributeMaxDynamicSharedMemorySize, GT_SMEM);
    cudaFuncSetAttribute(gemm_out, cudaFuncAttributeMaxDynamicSharedMemorySize, GT_SMEM);

    prep_fused<<<25088, 256>>>(x, key_t, value, mask, Wq, Wk, Wv, Wo, gamma, beta,
                               xn, kin, vin, mb, wqt, wkt, wvt, wot);

    gemm_qkv<<<dim3(8, 160), 256, GT_SMEM>>>(xn, kin, vin, wqt, wkt, wvt, q, k, v);

    attn_mma<<<dim3(NQ / QTILE, HEADS, BATCH), 256, ATTN_SMEM>>>(q, k, v, mb, ctx);

    gemm_out<<<dim3(8, 32), 256, GT_SMEM>>>(ctx, wot, out);
}